// round 8
// baseline (speedup 1.0000x reference)
#include <cuda_runtime.h>
#include <math.h>
#include <stdint.h>

#define SS   2048
#define DD   1024
#define NL   4
#define NH   16
#define HDIM 64
#define NV   50257
#define DMLP 4096

// ---------------- scratch ----------------
__device__ float g_x[SS * DD];
__device__ float g_h[SS * DD];
__device__ float g_q[SS * DD];
__device__ float g_k[SS * DD];
__device__ float g_v[SS * DD];
__device__ float g_mlp[SS * DMLP];
// tf32-rounded weight copies
__device__ float g_wqr[(size_t)NL * DD * DD];
__device__ float g_wkr[(size_t)NL * DD * DD];
__device__ float g_wvr[(size_t)NL * DD * DD];
__device__ float g_wor[(size_t)NL * DD * DD];
__device__ float g_w1r[(size_t)NL * DD * DMLP];
__device__ float g_w2r[(size_t)NL * DMLP * DD];
__device__ float g_embr[(size_t)NV * DD];

// ---------------- tf32 helpers ----------------
__device__ __forceinline__ unsigned f2tf(float f) {
    unsigned u;
    asm("cvt.rna.tf32.f32 %0, %1;" : "=r"(u) : "f"(f));
    return u;
}
__device__ __forceinline__ float tf32f(float f) {
    return __uint_as_float(f2tf(f));
}

// ---------------- tf32 rounding pre-pass ----------------
__global__ void round_kernel(const float4* __restrict__ in,
                             float4* __restrict__ out, long long n4) {
    long long i = blockIdx.x * (long long)blockDim.x + threadIdx.x;
    long long stride = (long long)gridDim.x * blockDim.x;
    for (; i < n4; i += stride) {
        float4 t = in[i];
        t.x = tf32f(t.x); t.y = tf32f(t.y);
        t.z = tf32f(t.z); t.w = tf32f(t.w);
        out[i] = t;
    }
}

// ---------------- embedding gather (x stays full fp32) ----------------
__global__ void embed_kernel(const int* __restrict__ ids,
                             const float* __restrict__ emb,
                             float* __restrict__ x) {
    int t = blockIdx.x;
    int id = ids[t];
    if (id < 0) id = 0;
    if (id >= NV) id = NV - 1;
    const float* src = emb + (size_t)id * DD;
    float* dst = x + (size_t)t * DD;
    for (int d = threadIdx.x; d < DD; d += blockDim.x) dst[d] = src[d];
}

// ---------------- layernorm (output tf32-rounded: always feeds a GEMM) ----
__global__ void layernorm_kernel(const float* __restrict__ x,
                                 const float* __restrict__ g,
                                 const float* __restrict__ b,
                                 float* __restrict__ out) {
    __shared__ float red[256];
    int row = blockIdx.x;
    const float* xr = x + (size_t)row * DD;
    float s = 0.f;
    for (int d = threadIdx.x; d < DD; d += 256) s += xr[d];
    red[threadIdx.x] = s;
    __syncthreads();
    for (int o = 128; o > 0; o >>= 1) {
        if (threadIdx.x < o) red[threadIdx.x] += red[threadIdx.x + o];
        __syncthreads();
    }
    float mean = red[0] * (1.f / DD);
    __syncthreads();
    float v = 0.f;
    for (int d = threadIdx.x; d < DD; d += 256) {
        float t = xr[d] - mean;
        v += t * t;
    }
    red[threadIdx.x] = v;
    __syncthreads();
    for (int o = 128; o > 0; o >>= 1) {
        if (threadIdx.x < o) red[threadIdx.x] += red[threadIdx.x + o];
        __syncthreads();
    }
    float inv = rsqrtf(red[0] * (1.f / DD) + 1e-5f);
    float* orow = out + (size_t)row * DD;
    for (int d = threadIdx.x; d < DD; d += 256)
        orow[d] = tf32f((xr[d] - mean) * inv * g[d] + b[d]);
}

// ---------------- RoPE (stores tf32-rounded) ----------------
__global__ void rope_kernel(float* __restrict__ q, float* __restrict__ k) {
    int idx = blockIdx.x * blockDim.x + threadIdx.x;
    int i = idx & 31;
    int rest = idx >> 5;
    int h = rest & (NH - 1);
    int t = rest >> 4;
    if (t >= SS) return;
    float inv_freq = powf(10000.f, -(float)i / 32.f);
    float ang = (float)t * inv_freq;
    float c = cosf(ang), s = sinf(ang);
    size_t base = (size_t)t * DD + h * HDIM;
    float x1 = q[base + i], x2 = q[base + i + 32];
    q[base + i]      = tf32f(x1 * c - x2 * s);
    q[base + i + 32] = tf32f(x2 * c + x1 * s);
    float y1 = k[base + i], y2 = k[base + i + 32];
    k[base + i]      = tf32f(y1 * c - y2 * s);
    k[base + i + 32] = tf32f(y2 * c + y1 * s);
}

// ---------------- common PTX helpers ----------------
__device__ __forceinline__ void cp16(unsigned dst, const void* src, int bytes) {
    asm volatile("cp.async.cg.shared.global [%0], [%1], 16, %2;"
                 :: "r"(dst), "l"(src), "r"(bytes));
}
__device__ __forceinline__ void cp_commit() {
    asm volatile("cp.async.commit_group;");
}
template <int N>
__device__ __forceinline__ void cp_wait() {
    asm volatile("cp.async.wait_group %0;" :: "n"(N));
}
__device__ __forceinline__ void mma_tf32(float c[4], unsigned a0, unsigned a1,
                                         unsigned a2, unsigned a3,
                                         unsigned b0, unsigned b1) {
    asm volatile(
        "mma.sync.aligned.m16n8k8.row.col.f32.tf32.tf32.f32 "
        "{%0,%1,%2,%3}, {%4,%5,%6,%7}, {%8,%9}, {%0,%1,%2,%3};"
        : "+f"(c[0]), "+f"(c[1]), "+f"(c[2]), "+f"(c[3])
        : "r"(a0), "r"(a1), "r"(a2), "r"(a3), "r"(b0), "r"(b1));
}

// ================= TF32 mma.sync GEMM — cvt-free mainloop =================
// All operands must be tf32-pre-rounded in global memory.
#define BMT 128
#define BKT 16
#define APITCH 20

struct Ptr3 {
    const float* b0; const float* b1; const float* b2;
    float* c0; float* c1; float* c2;
};

template <int BN, bool TB>
__global__ void __launch_bounds__(256, 2)
tgemm_kernel(const float* __restrict__ A, int lda, long long strideA,
             Ptr3 p, int ldb, long long strideB,
             int ldc, long long strideC,
             int M, int N, int K, float alpha,
             const float* __restrict__ bias,
             const float* __restrict__ res,
             int do_gelu, int multiB, int do_round) {
    const int BPN = (BN == 128) ? 136 : 72;
    const int BPT = 20;
    const int NBI = (BN * BKT) / 1024;
    const int MT  = (BN == 128) ? 4 : 2;

    __shared__ __align__(16) float As[2][BMT * APITCH];
    __shared__ __align__(16) float Bs[2][TB ? (BN * BPT) : (BKT * BPN)];

    int z = blockIdx.z;
    const float* B;
    float* C;
    if (multiB) {
        B = (z == 0) ? p.b0 : (z == 1) ? p.b1 : p.b2;
        C = (z == 0) ? p.c0 : (z == 1) ? p.c1 : p.c2;
    } else {
        B = p.b0 + (size_t)z * strideB;
        C = p.c0 + (size_t)z * strideC;
        if (res) res += (size_t)z * strideC;
    }
    A += (size_t)z * strideA;

    int row0 = blockIdx.x * BMT;
    int col0 = blockIdx.y * BN;
    int nk = K / BKT;

    int tid = threadIdx.x;
    int lane = tid & 31, warp = tid >> 5;
    int l4 = lane & 3, l28 = lane >> 2;
    int mbase, nbase;
    if (BN == 128) { mbase = (warp >> 2) * 64; nbase = (warp & 3) * 32; }
    else           { mbase = (warp >> 1) * 32; nbase = (warp & 1) * 32; }

    unsigned sA[2], sB[2];
    sA[0] = (unsigned)__cvta_generic_to_shared(&As[0][0]);
    sA[1] = (unsigned)__cvta_generic_to_shared(&As[1][0]);
    sB[0] = (unsigned)__cvta_generic_to_shared(&Bs[0][0]);
    sB[1] = (unsigned)__cvta_generic_to_shared(&Bs[1][0]);

    float acc[MT][4][4];
#pragma unroll
    for (int mt = 0; mt < MT; mt++)
#pragma unroll
        for (int nt = 0; nt < 4; nt++)
#pragma unroll
            for (int c = 0; c < 4; c++) acc[mt][nt][c] = 0.f;

    auto prefetch = [&](int s, int k0) {
#pragma unroll
        for (int i = 0; i < 2; i++) {
            int lin = i * 256 + tid;
            int m = lin >> 2, f4 = lin & 3;
            cp16(sA[s] + (m * APITCH + f4 * 4) * 4,
                 A + (size_t)(row0 + m) * lda + k0 + f4 * 4, 16);
        }
#pragma unroll
        for (int i = 0; i < NBI; i++) {
            int lin = i * 256 + tid;
            if (TB) {
                int n = lin >> 2, f4 = lin & 3;
                int gn = col0 + n;
                cp16(sB[s] + (n * BPT + f4 * 4) * 4,
                     B + (size_t)gn * ldb + k0 + f4 * 4, (gn < N) ? 16 : 0);
            } else {
                int kk = lin / (BN / 4), f4 = lin % (BN / 4);
                cp16(sB[s] + (kk * BPN + f4 * 4) * 4,
                     B + (size_t)(k0 + kk) * ldb + col0 + f4 * 4, 16);
            }
        }
        cp_commit();
    };

    prefetch(0, 0);

    for (int ks = 0; ks < nk; ks++) {
        int cur = ks & 1, nxt = cur ^ 1;
        bool more = (ks + 1) < nk;
        if (more) prefetch(nxt, (ks + 1) * BKT);

        if (more) cp_wait<1>(); else cp_wait<0>();
        __syncthreads();

#pragma unroll
        for (int kk8 = 0; kk8 < 2; kk8++) {
            int kb = kk8 * 8;
            unsigned af[MT][4];
#pragma unroll
            for (int mt = 0; mt < MT; mt++) {
                int mrow = mbase + mt * 16 + l28;
                af[mt][0] = __float_as_uint(As[cur][mrow * APITCH + kb + l4]);
                af[mt][1] = __float_as_uint(As[cur][(mrow + 8) * APITCH + kb + l4]);
                af[mt][2] = __float_as_uint(As[cur][mrow * APITCH + kb + l4 + 4]);
                af[mt][3] = __float_as_uint(As[cur][(mrow + 8) * APITCH + kb + l4 + 4]);
            }
            unsigned bf[4][2];
#pragma unroll
            for (int nt = 0; nt < 4; nt++) {
                int ncol = nbase + nt * 8 + l28;
                if (TB) {
                    bf[nt][0] = __float_as_uint(Bs[cur][ncol * BPT + kb + l4]);
                    bf[nt][1] = __float_as_uint(Bs[cur][ncol * BPT + kb + l4 + 4]);
                } else {
                    bf[nt][0] = __float_as_uint(Bs[cur][(kb + l4) * BPN + ncol]);
                    bf[nt][1] = __float_as_uint(Bs[cur][(kb + l4 + 4) * BPN + ncol]);
                }
            }
#pragma unroll
            for (int mt = 0; mt < MT; mt++)
#pragma unroll
                for (int nt = 0; nt < 4; nt++)
                    mma_tf32(acc[mt][nt], af[mt][0], af[mt][1], af[mt][2], af[mt][3],
                             bf[nt][0], bf[nt][1]);
        }
        __syncthreads();
    }

#pragma unroll
    for (int mt = 0; mt < MT; mt++) {
#pragma unroll
        for (int nt = 0; nt < 4; nt++) {
#pragma unroll
            for (int c = 0; c < 4; c++) {
                int gr = row0 + mbase + mt * 16 + l28 + ((c >= 2) ? 8 : 0);
                int gc = col0 + nbase + nt * 8 + l4 * 2 + (c & 1);
                if (gc >= N) continue;
                float v = alpha * acc[mt][nt][c];
                if (bias) v += bias[gc];
                if (res) v += res[(size_t)gr * ldc + gc];
                if (do_gelu) v = 0.5f * v * (1.f + erff(v * 0.70710678118654752f));
                if (do_round) v = tf32f(v);
                C[(size_t)gr * ldc + gc] = v;
            }
        }
    }
}

static inline Ptr3 one(const float* b, float* c) {
    Ptr3 p; p.b0 = b; p.b1 = nullptr; p.b2 = nullptr;
    p.c0 = c; p.c1 = nullptr; p.c2 = nullptr; return p;
}

// ================= fused causal flash attention (pre-rounded q/k/v) =========
#define FKP 68
#define FVP 72
#define FA_SMEM ((2 * 128 * FKP + 2 * 128 * FVP) * 4)

__global__ void __launch_bounds__(256, 1)
flash_kernel(const float* __restrict__ q, const float* __restrict__ k,
             const float* __restrict__ v, float* __restrict__ o) {
    extern __shared__ __align__(16) float fsm[];
    float* Ksm[2] = { fsm, fsm + 128 * FKP };
    float* Vsm[2] = { fsm + 2 * 128 * FKP, fsm + 2 * 128 * FKP + 128 * FVP };
    unsigned uK[2], uV[2];
    uK[0] = (unsigned)__cvta_generic_to_shared(Ksm[0]);
    uK[1] = (unsigned)__cvta_generic_to_shared(Ksm[1]);
    uV[0] = (unsigned)__cvta_generic_to_shared(Vsm[0]);
    uV[1] = (unsigned)__cvta_generic_to_shared(Vsm[1]);

    int rb = 15 - blockIdx.x;
    int hb = blockIdx.y * HDIM;
    int row0 = rb * 128;

    int tid = threadIdx.x, lane = tid & 31, w = tid >> 5;
    int l4 = lane & 3, l28 = lane >> 2;
    int rl0 = w * 16 + l28;
    int rl1 = rl0 + 8;
    int grow0 = row0 + rl0, grow1 = row0 + rl1;

    // q pre-rounded; 0.125 scale is exact (exponent shift) -> raw bits valid tf32
    unsigned qa[8][4];
#pragma unroll
    for (int c = 0; c < 8; c++) {
        qa[c][0] = __float_as_uint(0.125f * q[(size_t)grow0 * DD + hb + 8 * c + l4]);
        qa[c][1] = __float_as_uint(0.125f * q[(size_t)grow1 * DD + hb + 8 * c + l4]);
        qa[c][2] = __float_as_uint(0.125f * q[(size_t)grow0 * DD + hb + 8 * c + l4 + 4]);
        qa[c][3] = __float_as_uint(0.125f * q[(size_t)grow1 * DD + hb + 8 * c + l4 + 4]);
    }

    float oacc[8][4];
#pragma unroll
    for (int n2 = 0; n2 < 8; n2++)
#pragma unroll
        for (int c = 0; c < 4; c++) oacc[n2][c] = 0.f;
    float mA = -1e30f, mB = -1e30f, lA = 0.f, lB = 0.f;

    auto prefetch = [&](int j, int s) {
#pragma unroll
        for (int i = 0; i < 8; i++) {
            int lin = i * 256 + tid;
            int r = lin >> 4, f4 = lin & 15;
            const float* gk = k + (size_t)(j * 128 + r) * DD + hb + f4 * 4;
            const float* gv = v + (size_t)(j * 128 + r) * DD + hb + f4 * 4;
            cp16(uK[s] + (r * FKP + f4 * 4) * 4, gk, 16);
            cp16(uV[s] + (r * FVP + f4 * 4) * 4, gv, 16);
        }
        cp_commit();
    };

    int src0 = (lane & ~3) | (l4 >> 1);
    int src1 = src0 + 2;
    bool par = (l4 & 1) != 0;

    prefetch(0, 0);

    for (int j = 0; j <= rb; j++) {
        int s = j & 1;
        bool more = j < rb;
        if (more) prefetch(j + 1, s ^ 1);
        if (more) cp_wait<1>(); else cp_wait<0>();
        __syncthreads();

        float sacc[16][4];
#pragma unroll
        for (int t = 0; t < 16; t++)
#pragma unroll
            for (int c = 0; c < 4; c++) sacc[t][c] = 0.f;
#pragma unroll
        for (int c = 0; c < 8; c++) {
#pragma unroll
            for (int t = 0; t < 16; t++) {
                unsigned b0 = __float_as_uint(Ksm[s][(t * 8 + l28) * FKP + 8 * c + l4]);
                unsigned b1 = __float_as_uint(Ksm[s][(t * 8 + l28) * FKP + 8 * c + l4 + 4]);
                mma_tf32(sacc[t], qa[c][0], qa[c][1], qa[c][2], qa[c][3], b0, b1);
            }
        }

        if (j == rb) {
#pragma unroll
            for (int t = 0; t < 16; t++) {
                int cb = 8 * t + 2 * l4;
                if (cb     > rl0) sacc[t][0] = -1e30f;
                if (cb + 1 > rl0) sacc[t][1] = -1e30f;
                if (cb     > rl1) sacc[t][2] = -1e30f;
                if (cb + 1 > rl1) sacc[t][3] = -1e30f;
            }
        }

        float tmA = -1e30f, tmB = -1e30f;
#pragma unroll
        for (int t = 0; t < 16; t++) {
            tmA = fmaxf(tmA, fmaxf(sacc[t][0], sacc[t][1]));
            tmB = fmaxf(tmB, fmaxf(sacc[t][2], sacc[t][3]));
        }
        tmA = fmaxf(tmA, __shfl_xor_sync(0xffffffffu, tmA, 1));
        tmA = fmaxf(tmA, __shfl_xor_sync(0xffffffffu, tmA, 2));
        tmB = fmaxf(tmB, __shfl_xor_sync(0xffffffffu, tmB, 1));
        tmB = fmaxf(tmB, __shfl_xor_sync(0xffffffffu, tmB, 2));

        float mnA = fmaxf(mA, tmA), mnB = fmaxf(mB, tmB);
        float cA = __expf(mA - mnA), cB = __expf(mB - mnB);
        mA = mnA; mB = mnB;

        float tsA = 0.f, tsB = 0.f;
#pragma unroll
        for (int t = 0; t < 16; t++) {
            sacc[t][0] = __expf(sacc[t][0] - mA);
            sacc[t][1] = __expf(sacc[t][1] - mA);
            sacc[t][2] = __expf(sacc[t][2] - mB);
            sacc[t][3] = __expf(sacc[t][3] - mB);
            tsA += sacc[t][0] + sacc[t][1];
            tsB += sacc[t][2] + sacc[t][3];
        }
        tsA += __shfl_xor_sync(0xffffffffu, tsA, 1);
        tsA += __shfl_xor_sync(0xffffffffu, tsA, 2);
        tsB += __shfl_xor_sync(0xffffffffu, tsB, 1);
        tsB += __shfl_xor_sync(0xffffffffu, tsB, 2);
        lA = lA * cA + tsA;
        lB = lB * cB + tsB;

#pragma unroll
        for (int n2 = 0; n2 < 8; n2++) {
            oacc[n2][0] *= cA; oacc[n2][1] *= cA;
            oacc[n2][2] *= cB; oacc[n2][3] *= cB;
        }

#pragma unroll
        for (int kc = 0; kc < 16; kc++) {
            float v00 = __shfl_sync(0xffffffffu, sacc[kc][0], src0);
            float v01 = __shfl_sync(0xffffffffu, sacc[kc][1], src0);
            float v10 = __shfl_sync(0xffffffffu, sacc[kc][2], src0);
            float v11 = __shfl_sync(0xffffffffu, sacc[kc][3], src0);
            float w00 = __shfl_sync(0xffffffffu, sacc[kc][0], src1);
            float w01 = __shfl_sync(0xffffffffu, sacc[kc][1], src1);
            float w10 = __shfl_sync(0xffffffffu, sacc[kc][2], src1);
            float w11 = __shfl_sync(0xffffffffu, sacc[kc][3], src1);
            unsigned a0 = f2tf(par ? v01 : v00);
            unsigned a1 = f2tf(par ? v11 : v10);
            unsigned a2 = f2tf(par ? w01 : w00);
            unsigned a3 = f2tf(par ? w11 : w10);
#pragma unroll
            for (int n2 = 0; n2 < 8; n2++) {
                unsigned b0 = __float_as_uint(Vsm[s][(kc * 8 + l4) * FVP + n2 * 8 + l28]);
                unsigned b1 = __float_as_uint(Vsm[s][(kc * 8 + l4 + 4) * FVP + n2 * 8 + l28]);
                mma_tf32(oacc[n2], a0, a1, a2, a3, b0, b1);
            }
        }
        __syncthreads();
    }

    // output feeds Wo GEMM -> store tf32-rounded
    float iA = 1.f / lA, iB = 1.f / lB;
#pragma unroll
    for (int n2 = 0; n2 < 8; n2++) {
        *(float2*)&o[(size_t)grow0 * DD + hb + n2 * 8 + 2 * l4] =
            make_float2(tf32f(oacc[n2][0] * iA), tf32f(oacc[n2][1] * iA));
        *(float2*)&o[(size_t)grow1 * DD + hb + n2 * 8 + 2 * l4] =
            make_float2(tf32f(oacc[n2][2] * iB), tf32f(oacc[n2][3] * iB));
    }
}

// ---------------- host orchestration ----------------
extern "C" void kernel_launch(void* const* d_in, const int* in_sizes, int n_in,
                              void* d_out, int out_size) {
    const int*   ids  = (const int*)d_in[0];
    const float* emb  = (const float*)d_in[1];
    const float* Wq   = (const float*)d_in[2];
    const float* Wk   = (const float*)d_in[3];
    const float* Wv   = (const float*)d_in[4];
    const float* Wo   = (const float*)d_in[5];
    const float* ln1g = (const float*)d_in[6];
    const float* ln1b = (const float*)d_in[7];
    const float* ln2g = (const float*)d_in[8];
    const float* ln2b = (const float*)d_in[9];
    const float* W1   = (const float*)d_in[10];
    const float* b1   = (const float*)d_in[11];
    const float* W2   = (const float*)d_in[12];
    const float* b2   = (const float*)d_in[13];
    const float* lnfg = (const float*)d_in[14];
    const float* lnfb = (const float*)d_in[15];
    float* out = (float*)d_out;

    float *x, *h, *q, *k, *v, *mlp;
    float *wqr, *wkr, *wvr, *wor, *w1r, *w2r, *embr;
    cudaGetSymbolAddress((void**)&x,    g_x);
    cudaGetSymbolAddress((void**)&h,    g_h);
    cudaGetSymbolAddress((void**)&q,    g_q);
    cudaGetSymbolAddress((void**)&k,    g_k);
    cudaGetSymbolAddress((void**)&v,    g_v);
    cudaGetSymbolAddress((void**)&mlp,  g_mlp);
    cudaGetSymbolAddress((void**)&wqr,  g_wqr);
    cudaGetSymbolAddress((void**)&wkr,  g_wkr);
    cudaGetSymbolAddress((void**)&wvr,  g_wvr);
    cudaGetSymbolAddress((void**)&wor,  g_wor);
    cudaGetSymbolAddress((void**)&w1r,  g_w1r);
    cudaGetSymbolAddress((void**)&w2r,  g_w2r);
    cudaGetSymbolAddress((void**)&embr, g_embr);

    cudaFuncSetAttribute(flash_kernel,
                         cudaFuncAttributeMaxDynamicSharedMemorySize, FA_SMEM);

    // tf32 pre-rounding of all GEMM B-operands
    round_kernel<<<4096, 256>>>((const float4*)Wq,  (float4*)wqr,  (long long)NL * DD * DD / 4);
    round_kernel<<<4096, 256>>>((const float4*)Wk,  (float4*)wkr,  (long long)NL * DD * DD / 4);
    round_kernel<<<4096, 256>>>((const float4*)Wv,  (float4*)wvr,  (long long)NL * DD * DD / 4);
    round_kernel<<<4096, 256>>>((const float4*)Wo,  (float4*)wor,  (long long)NL * DD * DD / 4);
    round_kernel<<<4096, 256>>>((const float4*)W1,  (float4*)w1r,  (long long)NL * DD * DMLP / 4);
    round_kernel<<<4096, 256>>>((const float4*)W2,  (float4*)w2r,  (long long)NL * DMLP * DD / 4);
    round_kernel<<<4096, 256>>>((const float4*)emb, (float4*)embr, (long long)NV * DD / 4);

    embed_kernel<<<SS, 256>>>(ids, emb, x);

    for (int l = 0; l < NL; l++) {
        const size_t wofs = (size_t)l * DD * DD;
        layernorm_kernel<<<SS, 256>>>(x, ln1g + l * DD, ln1b + l * DD, h);

        // fused QKV (outputs rounded; q,k re-rounded by rope)
        {
            Ptr3 p;
            p.b0 = wqr + wofs; p.b1 = wkr + wofs; p.b2 = wvr + wofs;
            p.c0 = q; p.c1 = k; p.c2 = v;
            tgemm_kernel<128, false><<<dim3(SS / 128, DD / 128, 3), 256>>>(
                h, DD, 0, p, DD, 0, DD, 0,
                SS, DD, DD, 1.f, nullptr, nullptr, 0, 1, 1);
        }

        rope_kernel<<<(SS * NH * 32 + 255) / 256, 256>>>(q, k);

        flash_kernel<<<dim3(SS / 128, NH), 256, FA_SMEM>>>(q, k, v, h);

        // x = x + attn @ Wo (full fp32 out)
        tgemm_kernel<64, false><<<dim3(SS / 128, DD / 64, 1), 256>>>(
            h, DD, 0, one(wor + wofs, x), DD, 0, DD, 0,
            SS, DD, DD, 1.f, nullptr, x, 0, 0, 0);

        layernorm_kernel<<<SS, 256>>>(x, ln2g + l * DD, ln2b + l * DD, h);

        // mlp = gelu(h @ W1 + b1), rounded (feeds W2 GEMM)
        tgemm_kernel<128, false><<<dim3(SS / 128, DMLP / 128, 1), 256>>>(
            h, DD, 0, one(w1r + (size_t)l * DD * DMLP, mlp), DMLP, 0, DMLP, 0,
            SS, DMLP, DD, 1.f, b1 + (size_t)l * DMLP, nullptr, 1, 0, 1);

        // x = x + mlp @ W2 + b2 (full fp32 out)
        tgemm_kernel<64, false><<<dim3(SS / 128, DD / 64, 1), 256>>>(
            mlp, DMLP, 0, one(w2r + (size_t)l * DMLP * DD, x), DD, 0, DD, 0,
            SS, DD, DMLP, 1.f, b2 + (size_t)l * DD, x, 0, 0, 0);
    }

    layernorm_kernel<<<SS, 256>>>(x, lnfg, lnfb, h);

    // logits = h @ emb_r^T
    tgemm_kernel<128, true><<<dim3(SS / 128, (NV + 127) / 128, 1), 256>>>(
        h, DD, 0, one(embr, out), DD, 0, NV, 0,
        SS, NV, DD, 1.f, nullptr, nullptr, 0, 0, 0);
}

// round 9
// speedup vs baseline: 1.0114x; 1.0114x over previous
#include <cuda_runtime.h>
#include <math.h>
#include <stdint.h>

#define SS   2048
#define DD   1024
#define NL   4
#define NH   16
#define HDIM 64
#define NV   50257
#define DMLP 4096

// ---------------- scratch ----------------
__device__ float g_x[SS * DD];
__device__ float g_h[SS * DD];
__device__ float g_q[SS * DD];
__device__ float g_k[SS * DD];
__device__ float g_v[SS * DD];
__device__ float g_mlp[SS * DMLP];

// ---------------- tf32 helpers ----------------
__device__ __forceinline__ unsigned f2tf(float f) {
    unsigned u;
    asm("cvt.rna.tf32.f32 %0, %1;" : "=r"(u) : "f"(f));
    return u;
}
__device__ __forceinline__ float tf32f(float f) {
    return __uint_as_float(f2tf(f));
}

// ---------------- embedding gather (x stays full fp32) ----------------
__global__ void embed_kernel(const int* __restrict__ ids,
                             const float* __restrict__ emb,
                             float* __restrict__ x) {
    int t = blockIdx.x;
    int id = ids[t];
    if (id < 0) id = 0;
    if (id >= NV) id = NV - 1;
    const float* src = emb + (size_t)id * DD;
    float* dst = x + (size_t)t * DD;
    for (int d = threadIdx.x; d < DD; d += blockDim.x) dst[d] = src[d];
}

// ---------------- layernorm (output tf32-rounded: always feeds a GEMM A) ----
__global__ void layernorm_kernel(const float* __restrict__ x,
                                 const float* __restrict__ g,
                                 const float* __restrict__ b,
                                 float* __restrict__ out) {
    __shared__ float red[256];
    int row = blockIdx.x;
    const float* xr = x + (size_t)row * DD;
    float s = 0.f;
    for (int d = threadIdx.x; d < DD; d += 256) s += xr[d];
    red[threadIdx.x] = s;
    __syncthreads();
    for (int o = 128; o > 0; o >>= 1) {
        if (threadIdx.x < o) red[threadIdx.x] += red[threadIdx.x + o];
        __syncthreads();
    }
    float mean = red[0] * (1.f / DD);
    __syncthreads();
    float v = 0.f;
    for (int d = threadIdx.x; d < DD; d += 256) {
        float t = xr[d] - mean;
        v += t * t;
    }
    red[threadIdx.x] = v;
    __syncthreads();
    for (int o = 128; o > 0; o >>= 1) {
        if (threadIdx.x < o) red[threadIdx.x] += red[threadIdx.x + o];
        __syncthreads();
    }
    float inv = rsqrtf(red[0] * (1.f / DD) + 1e-5f);
    float* orow = out + (size_t)row * DD;
    for (int d = threadIdx.x; d < DD; d += 256)
        orow[d] = tf32f((xr[d] - mean) * inv * g[d] + b[d]);
}

// ---------------- RoPE (stores tf32-rounded) ----------------
__global__ void rope_kernel(float* __restrict__ q, float* __restrict__ k) {
    int idx = blockIdx.x * blockDim.x + threadIdx.x;
    int i = idx & 31;
    int rest = idx >> 5;
    int h = rest & (NH - 1);
    int t = rest >> 4;
    if (t >= SS) return;
    float inv_freq = powf(10000.f, -(float)i / 32.f);
    float ang = (float)t * inv_freq;
    float c = cosf(ang), s = sinf(ang);
    size_t base = (size_t)t * DD + h * HDIM;
    float x1 = q[base + i], x2 = q[base + i + 32];
    q[base + i]      = tf32f(x1 * c - x2 * s);
    q[base + i + 32] = tf32f(x2 * c + x1 * s);
    float y1 = k[base + i], y2 = k[base + i + 32];
    k[base + i]      = tf32f(y1 * c - y2 * s);
    k[base + i + 32] = tf32f(y2 * c + y1 * s);
}

// ---------------- common PTX helpers ----------------
__device__ __forceinline__ void cp16(unsigned dst, const void* src, int bytes) {
    asm volatile("cp.async.cg.shared.global [%0], [%1], 16, %2;"
                 :: "r"(dst), "l"(src), "r"(bytes));
}
__device__ __forceinline__ void cp_commit() {
    asm volatile("cp.async.commit_group;");
}
template <int N>
__device__ __forceinline__ void cp_wait() {
    asm volatile("cp.async.wait_group %0;" :: "n"(N));
}
__device__ __forceinline__ void mma_tf32(float c[4], unsigned a0, unsigned a1,
                                         unsigned a2, unsigned a3,
                                         unsigned b0, unsigned b1) {
    asm volatile(
        "mma.sync.aligned.m16n8k8.row.col.f32.tf32.tf32.f32 "
        "{%0,%1,%2,%3}, {%4,%5,%6,%7}, {%8,%9}, {%0,%1,%2,%3};"
        : "+f"(c[0]), "+f"(c[1]), "+f"(c[2]), "+f"(c[3])
        : "r"(a0), "r"(a1), "r"(a2), "r"(a3), "r"(b0), "r"(b1));
}

// ================= TF32 mma.sync GEMM =================
// A operands must be tf32-pre-rounded (our producers guarantee it);
// B operands (weights/emb) converted at fragment load.
// Single __syncthreads per k-tile: prefetch is issued AFTER the barrier, so a
// leading warp blocks at the next barrier before it can overwrite a stage a
// lagging warp still reads.
#define BMT 128
#define BKT 16
#define APITCH 20

struct Ptr3 {
    const float* b0; const float* b1; const float* b2;
    float* c0; float* c1; float* c2;
};

template <int BN, bool TB>
__global__ void __launch_bounds__(256, 2)
tgemm_kernel(const float* __restrict__ A, int lda, long long strideA,
             Ptr3 p, int ldb, long long strideB,
             int ldc, long long strideC,
             int M, int N, int K, float alpha,
             const float* __restrict__ bias,
             const float* __restrict__ res,
             int do_gelu, int multiB, int do_round) {
    const int BPN = (BN == 128) ? 136 : 72;
    const int BPT = 20;
    const int NBI = (BN * BKT) / 1024;
    const int MT  = (BN == 128) ? 4 : 2;

    __shared__ __align__(16) float As[2][BMT * APITCH];
    __shared__ __align__(16) float Bs[2][TB ? (BN * BPT) : (BKT * BPN)];

    int z = blockIdx.z;
    const float* B;
    float* C;
    if (multiB) {
        B = (z == 0) ? p.b0 : (z == 1) ? p.b1 : p.b2;
        C = (z == 0) ? p.c0 : (z == 1) ? p.c1 : p.c2;
    } else {
        B = p.b0 + (size_t)z * strideB;
        C = p.c0 + (size_t)z * strideC;
        if (res) res += (size_t)z * strideC;
    }
    A += (size_t)z * strideA;

    int row0 = blockIdx.x * BMT;
    int col0 = blockIdx.y * BN;
    int nk = K / BKT;

    int tid = threadIdx.x;
    int lane = tid & 31, warp = tid >> 5;
    int l4 = lane & 3, l28 = lane >> 2;
    int mbase, nbase;
    if (BN == 128) { mbase = (warp >> 2) * 64; nbase = (warp & 3) * 32; }
    else           { mbase = (warp >> 1) * 32; nbase = (warp & 1) * 32; }

    unsigned sA[2], sB[2];
    sA[0] = (unsigned)__cvta_generic_to_shared(&As[0][0]);
    sA[1] = (unsigned)__cvta_generic_to_shared(&As[1][0]);
    sB[0] = (unsigned)__cvta_generic_to_shared(&Bs[0][0]);
    sB[1] = (unsigned)__cvta_generic_to_shared(&Bs[1][0]);

    float acc[MT][4][4];
#pragma unroll
    for (int mt = 0; mt < MT; mt++)
#pragma unroll
        for (int nt = 0; nt < 4; nt++)
#pragma unroll
            for (int c = 0; c < 4; c++) acc[mt][nt][c] = 0.f;

    auto prefetch = [&](int s, int k0) {
#pragma unroll
        for (int i = 0; i < 2; i++) {
            int lin = i * 256 + tid;
            int m = lin >> 2, f4 = lin & 3;
            cp16(sA[s] + (m * APITCH + f4 * 4) * 4,
                 A + (size_t)(row0 + m) * lda + k0 + f4 * 4, 16);
        }
#pragma unroll
        for (int i = 0; i < NBI; i++) {
            int lin = i * 256 + tid;
            if (TB) {
                int n = lin >> 2, f4 = lin & 3;
                int gn = col0 + n;
                cp16(sB[s] + (n * BPT + f4 * 4) * 4,
                     B + (size_t)gn * ldb + k0 + f4 * 4, (gn < N) ? 16 : 0);
            } else {
                int kk = lin / (BN / 4), f4 = lin % (BN / 4);
                cp16(sB[s] + (kk * BPN + f4 * 4) * 4,
                     B + (size_t)(k0 + kk) * ldb + col0 + f4 * 4, 16);
            }
        }
        cp_commit();
    };

    prefetch(0, 0);

    for (int ks = 0; ks < nk; ks++) {
        int cur = ks & 1, nxt = cur ^ 1;
        bool more = (ks + 1) < nk;

        cp_wait<0>();
        __syncthreads();
        if (more) prefetch(nxt, (ks + 1) * BKT);   // lands during compute below

#pragma unroll
        for (int kk8 = 0; kk8 < 2; kk8++) {
            int kb = kk8 * 8;
            unsigned af[MT][4];
#pragma unroll
            for (int mt = 0; mt < MT; mt++) {
                int mrow = mbase + mt * 16 + l28;
                af[mt][0] = __float_as_uint(As[cur][mrow * APITCH + kb + l4]);
                af[mt][1] = __float_as_uint(As[cur][(mrow + 8) * APITCH + kb + l4]);
                af[mt][2] = __float_as_uint(As[cur][mrow * APITCH + kb + l4 + 4]);
                af[mt][3] = __float_as_uint(As[cur][(mrow + 8) * APITCH + kb + l4 + 4]);
            }
            unsigned bf[4][2];
#pragma unroll
            for (int nt = 0; nt < 4; nt++) {
                int ncol = nbase + nt * 8 + l28;
                if (TB) {
                    bf[nt][0] = f2tf(Bs[cur][ncol * BPT + kb + l4]);
                    bf[nt][1] = f2tf(Bs[cur][ncol * BPT + kb + l4 + 4]);
                } else {
                    bf[nt][0] = f2tf(Bs[cur][(kb + l4) * BPN + ncol]);
                    bf[nt][1] = f2tf(Bs[cur][(kb + l4 + 4) * BPN + ncol]);
                }
            }
#pragma unroll
            for (int mt = 0; mt < MT; mt++)
#pragma unroll
                for (int nt = 0; nt < 4; nt++)
                    mma_tf32(acc[mt][nt], af[mt][0], af[mt][1], af[mt][2], af[mt][3],
                             bf[nt][0], bf[nt][1]);
        }
    }

#pragma unroll
    for (int mt = 0; mt < MT; mt++) {
#pragma unroll
        for (int nt = 0; nt < 4; nt++) {
#pragma unroll
            for (int c = 0; c < 4; c++) {
                int gr = row0 + mbase + mt * 16 + l28 + ((c >= 2) ? 8 : 0);
                int gc = col0 + nbase + nt * 8 + l4 * 2 + (c & 1);
                if (gc >= N) continue;
                float v = alpha * acc[mt][nt][c];
                if (bias) v += bias[gc];
                if (res) v += res[(size_t)gr * ldc + gc];
                if (do_gelu) v = 0.5f * v * (1.f + erff(v * 0.70710678118654752f));
                if (do_round) v = tf32f(v);
                C[(size_t)gr * ldc + gc] = v;
            }
        }
    }
}

static inline Ptr3 one(const float* b, float* c) {
    Ptr3 p; p.b0 = b; p.b1 = nullptr; p.b2 = nullptr;
    p.c0 = c; p.c1 = nullptr; p.c2 = nullptr; return p;
}

// ================= fused causal flash attention (pre-rounded q/k/v) =========
#define FKP 68
#define FVP 72
#define FA_SMEM ((2 * 128 * FKP + 2 * 128 * FVP) * 4)

__global__ void __launch_bounds__(256, 1)
flash_kernel(const float* __restrict__ q, const float* __restrict__ k,
             const float* __restrict__ v, float* __restrict__ o) {
    extern __shared__ __align__(16) float fsm[];
    float* Ksm[2] = { fsm, fsm + 128 * FKP };
    float* Vsm[2] = { fsm + 2 * 128 * FKP, fsm + 2 * 128 * FKP + 128 * FVP };
    unsigned uK[2], uV[2];
    uK[0] = (unsigned)__cvta_generic_to_shared(Ksm[0]);
    uK[1] = (unsigned)__cvta_generic_to_shared(Ksm[1]);
    uV[0] = (unsigned)__cvta_generic_to_shared(Vsm[0]);
    uV[1] = (unsigned)__cvta_generic_to_shared(Vsm[1]);

    int rb = 15 - blockIdx.x;
    int hb = blockIdx.y * HDIM;
    int row0 = rb * 128;

    int tid = threadIdx.x, lane = tid & 31, w = tid >> 5;
    int l4 = lane & 3, l28 = lane >> 2;
    int rl0 = w * 16 + l28;
    int rl1 = rl0 + 8;
    int grow0 = row0 + rl0, grow1 = row0 + rl1;

    // q pre-rounded; 0.125 scale exact (exponent shift) -> raw bits valid tf32
    unsigned qa[8][4];
#pragma unroll
    for (int c = 0; c < 8; c++) {
        qa[c][0] = __float_as_uint(0.125f * q[(size_t)grow0 * DD + hb + 8 * c + l4]);
        qa[c][1] = __float_as_uint(0.125f * q[(size_t)grow1 * DD + hb + 8 * c + l4]);
        qa[c][2] = __float_as_uint(0.125f * q[(size_t)grow0 * DD + hb + 8 * c + l4 + 4]);
        qa[c][3] = __float_as_uint(0.125f * q[(size_t)grow1 * DD + hb + 8 * c + l4 + 4]);
    }

    float oacc[8][4];
#pragma unroll
    for (int n2 = 0; n2 < 8; n2++)
#pragma unroll
        for (int c = 0; c < 4; c++) oacc[n2][c] = 0.f;
    float mA = -1e30f, mB = -1e30f, lA = 0.f, lB = 0.f;

    auto prefetch = [&](int j, int s) {
#pragma unroll
        for (int i = 0; i < 8; i++) {
            int lin = i * 256 + tid;
            int r = lin >> 4, f4 = lin & 15;
            const float* gk = k + (size_t)(j * 128 + r) * DD + hb + f4 * 4;
            const float* gv = v + (size_t)(j * 128 + r) * DD + hb + f4 * 4;
            cp16(uK[s] + (r * FKP + f4 * 4) * 4, gk, 16);
            cp16(uV[s] + (r * FVP + f4 * 4) * 4, gv, 16);
        }
        cp_commit();
    };

    int src0 = (lane & ~3) | (l4 >> 1);
    int src1 = src0 + 2;
    bool par = (l4 & 1) != 0;

    prefetch(0, 0);

    for (int j = 0; j <= rb; j++) {
        int s = j & 1;
        bool more = j < rb;

        cp_wait<0>();
        __syncthreads();
        if (more) prefetch(j + 1, s ^ 1);

        float sacc[16][4];
#pragma unroll
        for (int t = 0; t < 16; t++)
#pragma unroll
            for (int c = 0; c < 4; c++) sacc[t][c] = 0.f;
#pragma unroll
        for (int c = 0; c < 8; c++) {
#pragma unroll
            for (int t = 0; t < 16; t++) {
                unsigned b0 = __float_as_uint(Ksm[s][(t * 8 + l28) * FKP + 8 * c + l4]);
                unsigned b1 = __float_as_uint(Ksm[s][(t * 8 + l28) * FKP + 8 * c + l4 + 4]);
                mma_tf32(sacc[t], qa[c][0], qa[c][1], qa[c][2], qa[c][3], b0, b1);
            }
        }

        if (j == rb) {
#pragma unroll
            for (int t = 0; t < 16; t++) {
                int cb = 8 * t + 2 * l4;
                if (cb     > rl0) sacc[t][0] = -1e30f;
                if (cb + 1 > rl0) sacc[t][1] = -1e30f;
                if (cb     > rl1) sacc[t][2] = -1e30f;
                if (cb + 1 > rl1) sacc[t][3] = -1e30f;
            }
        }

        float tmA = -1e30f, tmB = -1e30f;
#pragma unroll
        for (int t = 0; t < 16; t++) {
            tmA = fmaxf(tmA, fmaxf(sacc[t][0], sacc[t][1]));
            tmB = fmaxf(tmB, fmaxf(sacc[t][2], sacc[t][3]));
        }
        tmA = fmaxf(tmA, __shfl_xor_sync(0xffffffffu, tmA, 1));
        tmA = fmaxf(tmA, __shfl_xor_sync(0xffffffffu, tmA, 2));
        tmB = fmaxf(tmB, __shfl_xor_sync(0xffffffffu, tmB, 1));
        tmB = fmaxf(tmB, __shfl_xor_sync(0xffffffffu, tmB, 2));

        float mnA = fmaxf(mA, tmA), mnB = fmaxf(mB, tmB);
        float cA = __expf(mA - mnA), cB = __expf(mB - mnB);
        mA = mnA; mB = mnB;

        float tsA = 0.f, tsB = 0.f;
#pragma unroll
        for (int t = 0; t < 16; t++) {
            sacc[t][0] = __expf(sacc[t][0] - mA);
            sacc[t][1] = __expf(sacc[t][1] - mA);
            sacc[t][2] = __expf(sacc[t][2] - mB);
            sacc[t][3] = __expf(sacc[t][3] - mB);
            tsA += sacc[t][0] + sacc[t][1];
            tsB += sacc[t][2] + sacc[t][3];
        }
        tsA += __shfl_xor_sync(0xffffffffu, tsA, 1);
        tsA += __shfl_xor_sync(0xffffffffu, tsA, 2);
        tsB += __shfl_xor_sync(0xffffffffu, tsB, 1);
        tsB += __shfl_xor_sync(0xffffffffu, tsB, 2);
        lA = lA * cA + tsA;
        lB = lB * cB + tsB;

#pragma unroll
        for (int n2 = 0; n2 < 8; n2++) {
            oacc[n2][0] *= cA; oacc[n2][1] *= cA;
            oacc[n2][2] *= cB; oacc[n2][3] *= cB;
        }

#pragma unroll
        for (int kc = 0; kc < 16; kc++) {
            float v00 = __shfl_sync(0xffffffffu, sacc[kc][0], src0);
            float v01 = __shfl_sync(0xffffffffu, sacc[kc][1], src0);
            float v10 = __shfl_sync(0xffffffffu, sacc[kc][2], src0);
            float v11 = __shfl_sync(0xffffffffu, sacc[kc][3], src0);
            float w00 = __shfl_sync(0xffffffffu, sacc[kc][0], src1);
            float w01 = __shfl_sync(0xffffffffu, sacc[kc][1], src1);
            float w10 = __shfl_sync(0xffffffffu, sacc[kc][2], src1);
            float w11 = __shfl_sync(0xffffffffu, sacc[kc][3], src1);
            unsigned a0 = f2tf(par ? v01 : v00);
            unsigned a1 = f2tf(par ? v11 : v10);
            unsigned a2 = f2tf(par ? w01 : w00);
            unsigned a3 = f2tf(par ? w11 : w10);
#pragma unroll
            for (int n2 = 0; n2 < 8; n2++) {
                unsigned b0 = __float_as_uint(Vsm[s][(kc * 8 + l4) * FVP + n2 * 8 + l28]);
                unsigned b1 = __float_as_uint(Vsm[s][(kc * 8 + l4 + 4) * FVP + n2 * 8 + l28]);
                mma_tf32(oacc[n2], a0, a1, a2, a3, b0, b1);
            }
        }
    }

    // output feeds Wo GEMM A-side -> store tf32-rounded
    float iA = 1.f / lA, iB = 1.f / lB;
#pragma unroll
    for (int n2 = 0; n2 < 8; n2++) {
        *(float2*)&o[(size_t)grow0 * DD + hb + n2 * 8 + 2 * l4] =
            make_float2(tf32f(oacc[n2][0] * iA), tf32f(oacc[n2][1] * iA));
        *(float2*)&o[(size_t)grow1 * DD + hb + n2 * 8 + 2 * l4] =
            make_float2(tf32f(oacc[n2][2] * iB), tf32f(oacc[n2][3] * iB));
    }
}

// ---------------- host orchestration ----------------
extern "C" void kernel_launch(void* const* d_in, const int* in_sizes, int n_in,
                              void* d_out, int out_size) {
    const int*   ids  = (const int*)d_in[0];
    const float* emb  = (const float*)d_in[1];
    const float* Wq   = (const float*)d_in[2];
    const float* Wk   = (const float*)d_in[3];
    const float* Wv   = (const float*)d_in[4];
    const float* Wo   = (const float*)d_in[5];
    const float* ln1g = (const float*)d_in[6];
    const float* ln1b = (const float*)d_in[7];
    const float* ln2g = (const float*)d_in[8];
    const float* ln2b = (const float*)d_in[9];
    const float* W1   = (const float*)d_in[10];
    const float* b1   = (const float*)d_in[11];
    const float* W2   = (const float*)d_in[12];
    const float* b2   = (const float*)d_in[13];
    const float* lnfg = (const float*)d_in[14];
    const float* lnfb = (const float*)d_in[15];
    float* out = (float*)d_out;

    float *x, *h, *q, *k, *v, *mlp;
    cudaGetSymbolAddress((void**)&x,   g_x);
    cudaGetSymbolAddress((void**)&h,   g_h);
    cudaGetSymbolAddress((void**)&q,   g_q);
    cudaGetSymbolAddress((void**)&k,   g_k);
    cudaGetSymbolAddress((void**)&v,   g_v);
    cudaGetSymbolAddress((void**)&mlp, g_mlp);

    cudaFuncSetAttribute(flash_kernel,
                         cudaFuncAttributeMaxDynamicSharedMemorySize, FA_SMEM);

    embed_kernel<<<SS, 256>>>(ids, emb, x);

    for (int l = 0; l < NL; l++) {
        const size_t wofs = (size_t)l * DD * DD;
        layernorm_kernel<<<SS, 256>>>(x, ln1g + l * DD, ln1b + l * DD, h);

        // fused QKV (outputs tf32-rounded; q,k re-rounded by rope)
        {
            Ptr3 p;
            p.b0 = Wq + wofs; p.b1 = Wk + wofs; p.b2 = Wv + wofs;
            p.c0 = q; p.c1 = k; p.c2 = v;
            tgemm_kernel<128, false><<<dim3(SS / 128, DD / 128, 3), 256>>>(
                h, DD, 0, p, DD, 0, DD, 0,
                SS, DD, DD, 1.f, nullptr, nullptr, 0, 1, 1);
        }

        rope_kernel<<<(SS * NH * 32 + 255) / 256, 256>>>(q, k);

        flash_kernel<<<dim3(SS / 128, NH), 256, FA_SMEM>>>(q, k, v, h);

        // x = x + attn @ Wo (full fp32 out; next LN rounds)
        tgemm_kernel<64, false><<<dim3(SS / 128, DD / 64, 1), 256>>>(
            h, DD, 0, one(Wo + wofs, x), DD, 0, DD, 0,
            SS, DD, DD, 1.f, nullptr, x, 0, 0, 0);

        layernorm_kernel<<<SS, 256>>>(x, ln2g + l * DD, ln2b + l * DD, h);

        // mlp = gelu(h @ W1 + b1), rounded (feeds W2 GEMM A-side)
        tgemm_kernel<128, false><<<dim3(SS / 128, DMLP / 128, 1), 256>>>(
            h, DD, 0, one(W1 + (size_t)l * DD * DMLP, mlp), DMLP, 0, DMLP, 0,
            SS, DMLP, DD, 1.f, b1 + (size_t)l * DMLP, nullptr, 1, 0, 1);

        // x = x + mlp @ W2 + b2 (full fp32 out)
        tgemm_kernel<64, false><<<dim3(SS / 128, DD / 64, 1), 256>>>(
            mlp, DMLP, 0, one(W2 + (size_t)l * DMLP * DD, x), DD, 0, DD, 0,
            SS, DD, DMLP, 1.f, b2 + (size_t)l * DD, x, 0, 0, 0);
    }

    layernorm_kernel<<<SS, 256>>>(x, lnfg, lnfb, h);

    // logits = h @ emb^T (emb converted at B-frag load)
    tgemm_kernel<128, true><<<dim3(SS / 128, (NV + 127) / 128, 1), 256>>>(
        h, DD, 0, one(emb, out), DD, 0, NV, 0,
        SS, NV, DD, 1.f, nullptr, nullptr, 0, 0, 0);
}

// round 10
// speedup vs baseline: 1.2163x; 1.2026x over previous
#include <cuda_runtime.h>
#include <math.h>
#include <stdint.h>

#define SS   2048
#define DD   1024
#define NL   4
#define NH   16
#define HDIM 64
#define NV   50257
#define DMLP 4096

// ---------------- scratch ----------------
__device__ float g_x[SS * DD];
__device__ float g_h[SS * DD];
__device__ float g_q[SS * DD];
__device__ float g_k[SS * DD];
__device__ float g_v[SS * DD];
__device__ float g_mlp[SS * DMLP];

// ---------------- tf32 helpers ----------------
__device__ __forceinline__ unsigned f2tf(float f) {
    unsigned u;
    asm("cvt.rna.tf32.f32 %0, %1;" : "=r"(u) : "f"(f));
    return u;
}
__device__ __forceinline__ float tf32f(float f) {
    return __uint_as_float(f2tf(f));
}
// pack two fp32 -> fp16x2 (lo = a, hi = b)
__device__ __forceinline__ unsigned packh(float a, float b) {
    unsigned d;
    asm("cvt.rn.f16x2.f32 %0, %1, %2;" : "=r"(d) : "f"(b), "f"(a));
    return d;
}
__device__ __forceinline__ unsigned packh2(float2 f) { return packh(f.x, f.y); }

// ---------------- embedding gather ----------------
__global__ void embed_kernel(const int* __restrict__ ids,
                             const float* __restrict__ emb,
                             float* __restrict__ x) {
    int t = blockIdx.x;
    int id = ids[t];
    if (id < 0) id = 0;
    if (id >= NV) id = NV - 1;
    const float* src = emb + (size_t)id * DD;
    float* dst = x + (size_t)t * DD;
    for (int d = threadIdx.x; d < DD; d += blockDim.x) dst[d] = src[d];
}

// ---------------- layernorm (tf32-rounded out: feeds GEMM A / flash) -------
__global__ void layernorm_kernel(const float* __restrict__ x,
                                 const float* __restrict__ g,
                                 const float* __restrict__ b,
                                 float* __restrict__ out) {
    __shared__ float red[256];
    int row = blockIdx.x;
    const float* xr = x + (size_t)row * DD;
    float s = 0.f;
    for (int d = threadIdx.x; d < DD; d += 256) s += xr[d];
    red[threadIdx.x] = s;
    __syncthreads();
    for (int o = 128; o > 0; o >>= 1) {
        if (threadIdx.x < o) red[threadIdx.x] += red[threadIdx.x + o];
        __syncthreads();
    }
    float mean = red[0] * (1.f / DD);
    __syncthreads();
    float v = 0.f;
    for (int d = threadIdx.x; d < DD; d += 256) {
        float t = xr[d] - mean;
        v += t * t;
    }
    red[threadIdx.x] = v;
    __syncthreads();
    for (int o = 128; o > 0; o >>= 1) {
        if (threadIdx.x < o) red[threadIdx.x] += red[threadIdx.x + o];
        __syncthreads();
    }
    float inv = rsqrtf(red[0] * (1.f / DD) + 1e-5f);
    float* orow = out + (size_t)row * DD;
    for (int d = threadIdx.x; d < DD; d += 256)
        orow[d] = tf32f((xr[d] - mean) * inv * g[d] + b[d]);
}

// ---------------- RoPE (stores tf32-rounded) ----------------
__global__ void rope_kernel(float* __restrict__ q, float* __restrict__ k) {
    int idx = blockIdx.x * blockDim.x + threadIdx.x;
    int i = idx & 31;
    int rest = idx >> 5;
    int h = rest & (NH - 1);
    int t = rest >> 4;
    if (t >= SS) return;
    float inv_freq = powf(10000.f, -(float)i / 32.f);
    float ang = (float)t * inv_freq;
    float c = cosf(ang), s = sinf(ang);
    size_t base = (size_t)t * DD + h * HDIM;
    float x1 = q[base + i], x2 = q[base + i + 32];
    q[base + i]      = tf32f(x1 * c - x2 * s);
    q[base + i + 32] = tf32f(x2 * c + x1 * s);
    float y1 = k[base + i], y2 = k[base + i + 32];
    k[base + i]      = tf32f(y1 * c - y2 * s);
    k[base + i + 32] = tf32f(y2 * c + y1 * s);
}

// ---------------- common PTX helpers ----------------
__device__ __forceinline__ void cp16(unsigned dst, const void* src, int bytes) {
    asm volatile("cp.async.cg.shared.global [%0], [%1], 16, %2;"
                 :: "r"(dst), "l"(src), "r"(bytes));
}
__device__ __forceinline__ void cp_commit() {
    asm volatile("cp.async.commit_group;");
}
template <int N>
__device__ __forceinline__ void cp_wait() {
    asm volatile("cp.async.wait_group %0;" :: "n"(N));
}
__device__ __forceinline__ void mma_tf32(float c[4], unsigned a0, unsigned a1,
                                         unsigned a2, unsigned a3,
                                         unsigned b0, unsigned b1) {
    asm volatile(
        "mma.sync.aligned.m16n8k8.row.col.f32.tf32.tf32.f32 "
        "{%0,%1,%2,%3}, {%4,%5,%6,%7}, {%8,%9}, {%0,%1,%2,%3};"
        : "+f"(c[0]), "+f"(c[1]), "+f"(c[2]), "+f"(c[3])
        : "r"(a0), "r"(a1), "r"(a2), "r"(a3), "r"(b0), "r"(b1));
}
__device__ __forceinline__ void mma_f16(float c[4], unsigned a0, unsigned a1,
                                        unsigned a2, unsigned a3,
                                        unsigned b0, unsigned b1) {
    asm volatile(
        "mma.sync.aligned.m16n8k16.row.col.f32.f16.f16.f32 "
        "{%0,%1,%2,%3}, {%4,%5,%6,%7}, {%8,%9}, {%0,%1,%2,%3};"
        : "+f"(c[0]), "+f"(c[1]), "+f"(c[2]), "+f"(c[3])
        : "r"(a0), "r"(a1), "r"(a2), "r"(a3), "r"(b0), "r"(b1));
}

// ================= FP16 m16n8k16 mma.sync GEMM =================
// A is tf32-pre-rounded by producers -> fp32->fp16 cvt is exact in range.
// B (raw weights/emb) gets one RN rounding to 10-bit mantissa (== tf32 error).
// R7-proven pipeline: prefetch(next) -> cp_wait<1> -> sync -> compute -> sync.
#define BMT 128
#define BKT 16
#define APITCH 24      // %32==24: float2 frag loads conflict-free per phase

struct Ptr3 {
    const float* b0; const float* b1; const float* b2;
    float* c0; float* c1; float* c2;
};

template <int BN, bool TB>
__global__ void __launch_bounds__(256, 2)
tgemm_kernel(const float* __restrict__ A, int lda, long long strideA,
             Ptr3 p, int ldb, long long strideB,
             int ldc, long long strideC,
             int M, int N, int K, float alpha,
             const float* __restrict__ bias,
             const float* __restrict__ res,
             int do_gelu, int multiB, int do_round) {
    const int BPN = (BN == 128) ? 132 : 68;  // [k][n] pitch, %32==4
    const int BPT = 24;                       // [n][k] pitch (float2 loads)
    const int NBI = (BN * BKT) / 1024;
    const int MT  = (BN == 128) ? 4 : 2;

    __shared__ __align__(16) float As[2][BMT * APITCH];
    __shared__ __align__(16) float Bs[2][TB ? (BN * BPT) : (BKT * BPN)];

    int z = blockIdx.z;
    const float* B;
    float* C;
    if (multiB) {
        B = (z == 0) ? p.b0 : (z == 1) ? p.b1 : p.b2;
        C = (z == 0) ? p.c0 : (z == 1) ? p.c1 : p.c2;
    } else {
        B = p.b0 + (size_t)z * strideB;
        C = p.c0 + (size_t)z * strideC;
        if (res) res += (size_t)z * strideC;
    }
    A += (size_t)z * strideA;

    int row0 = blockIdx.x * BMT;
    int col0 = blockIdx.y * BN;
    int nk = K / BKT;

    int tid = threadIdx.x;
    int lane = tid & 31, warp = tid >> 5;
    int l4 = lane & 3, l28 = lane >> 2;
    int mbase, nbase;
    if (BN == 128) { mbase = (warp >> 2) * 64; nbase = (warp & 3) * 32; }
    else           { mbase = (warp >> 1) * 32; nbase = (warp & 1) * 32; }

    unsigned sA[2], sB[2];
    sA[0] = (unsigned)__cvta_generic_to_shared(&As[0][0]);
    sA[1] = (unsigned)__cvta_generic_to_shared(&As[1][0]);
    sB[0] = (unsigned)__cvta_generic_to_shared(&Bs[0][0]);
    sB[1] = (unsigned)__cvta_generic_to_shared(&Bs[1][0]);

    float acc[MT][4][4];
#pragma unroll
    for (int mt = 0; mt < MT; mt++)
#pragma unroll
        for (int nt = 0; nt < 4; nt++)
#pragma unroll
            for (int c = 0; c < 4; c++) acc[mt][nt][c] = 0.f;

    auto prefetch = [&](int s, int k0) {
#pragma unroll
        for (int i = 0; i < 2; i++) {
            int lin = i * 256 + tid;
            int m = lin >> 2, f4 = lin & 3;
            cp16(sA[s] + (m * APITCH + f4 * 4) * 4,
                 A + (size_t)(row0 + m) * lda + k0 + f4 * 4, 16);
        }
#pragma unroll
        for (int i = 0; i < NBI; i++) {
            int lin = i * 256 + tid;
            if (TB) {
                int n = lin >> 2, f4 = lin & 3;
                int gn = col0 + n;
                cp16(sB[s] + (n * BPT + f4 * 4) * 4,
                     B + (size_t)gn * ldb + k0 + f4 * 4, (gn < N) ? 16 : 0);
            } else {
                int kk = lin / (BN / 4), f4 = lin % (BN / 4);
                cp16(sB[s] + (kk * BPN + f4 * 4) * 4,
                     B + (size_t)(k0 + kk) * ldb + col0 + f4 * 4, 16);
            }
        }
        cp_commit();
    };

    prefetch(0, 0);

    for (int ks = 0; ks < nk; ks++) {
        int cur = ks & 1, nxt = cur ^ 1;
        bool more = (ks + 1) < nk;
        if (more) prefetch(nxt, (ks + 1) * BKT);

        if (more) cp_wait<1>(); else cp_wait<0>();
        __syncthreads();

        // one k16 step per stage
        unsigned af[MT][4];
#pragma unroll
        for (int mt = 0; mt < MT; mt++) {
            int mrow = mbase + mt * 16 + l28;
            af[mt][0] = packh2(*(float2*)&As[cur][mrow * APITCH + 2 * l4]);
            af[mt][1] = packh2(*(float2*)&As[cur][(mrow + 8) * APITCH + 2 * l4]);
            af[mt][2] = packh2(*(float2*)&As[cur][mrow * APITCH + 2 * l4 + 8]);
            af[mt][3] = packh2(*(float2*)&As[cur][(mrow + 8) * APITCH + 2 * l4 + 8]);
        }
        unsigned bf[4][2];
#pragma unroll
        for (int nt = 0; nt < 4; nt++) {
            int ncol = nbase + nt * 8 + l28;
            if (TB) {
                bf[nt][0] = packh2(*(float2*)&Bs[cur][ncol * BPT + 2 * l4]);
                bf[nt][1] = packh2(*(float2*)&Bs[cur][ncol * BPT + 2 * l4 + 8]);
            } else {
                bf[nt][0] = packh(Bs[cur][(2 * l4) * BPN + ncol],
                                  Bs[cur][(2 * l4 + 1) * BPN + ncol]);
                bf[nt][1] = packh(Bs[cur][(2 * l4 + 8) * BPN + ncol],
                                  Bs[cur][(2 * l4 + 9) * BPN + ncol]);
            }
        }
#pragma unroll
        for (int mt = 0; mt < MT; mt++)
#pragma unroll
            for (int nt = 0; nt < 4; nt++)
                mma_f16(acc[mt][nt], af[mt][0], af[mt][1], af[mt][2], af[mt][3],
                        bf[nt][0], bf[nt][1]);

        __syncthreads();
    }

#pragma unroll
    for (int mt = 0; mt < MT; mt++) {
#pragma unroll
        for (int nt = 0; nt < 4; nt++) {
#pragma unroll
            for (int c = 0; c < 4; c++) {
                int gr = row0 + mbase + mt * 16 + l28 + ((c >= 2) ? 8 : 0);
                int gc = col0 + nbase + nt * 8 + l4 * 2 + (c & 1);
                if (gc >= N) continue;
                float v = alpha * acc[mt][nt][c];
                if (bias) v += bias[gc];
                if (res) v += res[(size_t)gr * ldc + gc];
                if (do_gelu) v = 0.5f * v * (1.f + erff(v * 0.70710678118654752f));
                if (do_round) v = tf32f(v);
                C[(size_t)gr * ldc + gc] = v;
            }
        }
    }
}

static inline Ptr3 one(const float* b, float* c) {
    Ptr3 p; p.b0 = b; p.b1 = nullptr; p.b2 = nullptr;
    p.c0 = c; p.c1 = nullptr; p.c2 = nullptr; return p;
}

// ================= fused causal flash attention (tf32, R7 pipeline) =========
#define FKP 68
#define FVP 72
#define FA_SMEM ((2 * 128 * FKP + 2 * 128 * FVP) * 4)

__global__ void __launch_bounds__(256, 1)
flash_kernel(const float* __restrict__ q, const float* __restrict__ k,
             const float* __restrict__ v, float* __restrict__ o) {
    extern __shared__ __align__(16) float fsm[];
    float* Ksm[2] = { fsm, fsm + 128 * FKP };
    float* Vsm[2] = { fsm + 2 * 128 * FKP, fsm + 2 * 128 * FKP + 128 * FVP };
    unsigned uK[2], uV[2];
    uK[0] = (unsigned)__cvta_generic_to_shared(Ksm[0]);
    uK[1] = (unsigned)__cvta_generic_to_shared(Ksm[1]);
    uV[0] = (unsigned)__cvta_generic_to_shared(Vsm[0]);
    uV[1] = (unsigned)__cvta_generic_to_shared(Vsm[1]);

    int rb = 15 - blockIdx.x;
    int hb = blockIdx.y * HDIM;
    int row0 = rb * 128;

    int tid = threadIdx.x, lane = tid & 31, w = tid >> 5;
    int l4 = lane & 3, l28 = lane >> 2;
    int rl0 = w * 16 + l28;
    int rl1 = rl0 + 8;
    int grow0 = row0 + rl0, grow1 = row0 + rl1;

    unsigned qa[8][4];
#pragma unroll
    for (int c = 0; c < 8; c++) {
        qa[c][0] = __float_as_uint(0.125f * q[(size_t)grow0 * DD + hb + 8 * c + l4]);
        qa[c][1] = __float_as_uint(0.125f * q[(size_t)grow1 * DD + hb + 8 * c + l4]);
        qa[c][2] = __float_as_uint(0.125f * q[(size_t)grow0 * DD + hb + 8 * c + l4 + 4]);
        qa[c][3] = __float_as_uint(0.125f * q[(size_t)grow1 * DD + hb + 8 * c + l4 + 4]);
    }

    float oacc[8][4];
#pragma unroll
    for (int n2 = 0; n2 < 8; n2++)
#pragma unroll
        for (int c = 0; c < 4; c++) oacc[n2][c] = 0.f;
    float mA = -1e30f, mB = -1e30f, lA = 0.f, lB = 0.f;

    auto prefetch = [&](int j, int s) {
#pragma unroll
        for (int i = 0; i < 8; i++) {
            int lin = i * 256 + tid;
            int r = lin >> 4, f4 = lin & 15;
            const float* gk = k + (size_t)(j * 128 + r) * DD + hb + f4 * 4;
            const float* gv = v + (size_t)(j * 128 + r) * DD + hb + f4 * 4;
            cp16(uK[s] + (r * FKP + f4 * 4) * 4, gk, 16);
            cp16(uV[s] + (r * FVP + f4 * 4) * 4, gv, 16);
        }
        cp_commit();
    };

    int src0 = (lane & ~3) | (l4 >> 1);
    int src1 = src0 + 2;
    bool par = (l4 & 1) != 0;

    prefetch(0, 0);

    for (int j = 0; j <= rb; j++) {
        int s = j & 1;
        bool more = j < rb;
        if (more) prefetch(j + 1, s ^ 1);
        if (more) cp_wait<1>(); else cp_wait<0>();
        __syncthreads();

        float sacc[16][4];
#pragma unroll
        for (int t = 0; t < 16; t++)
#pragma unroll
            for (int c = 0; c < 4; c++) sacc[t][c] = 0.f;
#pragma unroll
        for (int c = 0; c < 8; c++) {
#pragma unroll
            for (int t = 0; t < 16; t++) {
                unsigned b0 = __float_as_uint(Ksm[s][(t * 8 + l28) * FKP + 8 * c + l4]);
                unsigned b1 = __float_as_uint(Ksm[s][(t * 8 + l28) * FKP + 8 * c + l4 + 4]);
                mma_tf32(sacc[t], qa[c][0], qa[c][1], qa[c][2], qa[c][3], b0, b1);
            }
        }

        if (j == rb) {
#pragma unroll
            for (int t = 0; t < 16; t++) {
                int cb = 8 * t + 2 * l4;
                if (cb     > rl0) sacc[t][0] = -1e30f;
                if (cb + 1 > rl0) sacc[t][1] = -1e30f;
                if (cb     > rl1) sacc[t][2] = -1e30f;
                if (cb + 1 > rl1) sacc[t][3] = -1e30f;
            }
        }

        float tmA = -1e30f, tmB = -1e30f;
#pragma unroll
        for (int t = 0; t < 16; t++) {
            tmA = fmaxf(tmA, fmaxf(sacc[t][0], sacc[t][1]));
            tmB = fmaxf(tmB, fmaxf(sacc[t][2], sacc[t][3]));
        }
        tmA = fmaxf(tmA, __shfl_xor_sync(0xffffffffu, tmA, 1));
        tmA = fmaxf(tmA, __shfl_xor_sync(0xffffffffu, tmA, 2));
        tmB = fmaxf(tmB, __shfl_xor_sync(0xffffffffu, tmB, 1));
        tmB = fmaxf(tmB, __shfl_xor_sync(0xffffffffu, tmB, 2));

        float mnA = fmaxf(mA, tmA), mnB = fmaxf(mB, tmB);
        float cA = __expf(mA - mnA), cB = __expf(mB - mnB);
        mA = mnA; mB = mnB;

        float tsA = 0.f, tsB = 0.f;
#pragma unroll
        for (int t = 0; t < 16; t++) {
            sacc[t][0] = __expf(sacc[t][0] - mA);
            sacc[t][1] = __expf(sacc[t][1] - mA);
            sacc[t][2] = __expf(sacc[t][2] - mB);
            sacc[t][3] = __expf(sacc[t][3] - mB);
            tsA += sacc[t][0] + sacc[t][1];
            tsB += sacc[t][2] + sacc[t][3];
        }
        tsA += __shfl_xor_sync(0xffffffffu, tsA, 1);
        tsA += __shfl_xor_sync(0xffffffffu, tsA, 2);
        tsB += __shfl_xor_sync(0xffffffffu, tsB, 1);
        tsB += __shfl_xor_sync(0xffffffffu, tsB, 2);
        lA = lA * cA + tsA;
        lB = lB * cB + tsB;

#pragma unroll
        for (int n2 = 0; n2 < 8; n2++) {
            oacc[n2][0] *= cA; oacc[n2][1] *= cA;
            oacc[n2][2] *= cB; oacc[n2][3] *= cB;
        }

#pragma unroll
        for (int kc = 0; kc < 16; kc++) {
            float v00 = __shfl_sync(0xffffffffu, sacc[kc][0], src0);
            float v01 = __shfl_sync(0xffffffffu, sacc[kc][1], src0);
            float v10 = __shfl_sync(0xffffffffu, sacc[kc][2], src0);
            float v11 = __shfl_sync(0xffffffffu, sacc[kc][3], src0);
            float w00 = __shfl_sync(0xffffffffu, sacc[kc][0], src1);
            float w01 = __shfl_sync(0xffffffffu, sacc[kc][1], src1);
            float w10 = __shfl_sync(0xffffffffu, sacc[kc][2], src1);
            float w11 = __shfl_sync(0xffffffffu, sacc[kc][3], src1);
            unsigned a0 = f2tf(par ? v01 : v00);
            unsigned a1 = f2tf(par ? v11 : v10);
            unsigned a2 = f2tf(par ? w01 : w00);
            unsigned a3 = f2tf(par ? w11 : w10);
#pragma unroll
            for (int n2 = 0; n2 < 8; n2++) {
                unsigned b0 = __float_as_uint(Vsm[s][(kc * 8 + l4) * FVP + n2 * 8 + l28]);
                unsigned b1 = __float_as_uint(Vsm[s][(kc * 8 + l4 + 4) * FVP + n2 * 8 + l28]);
                mma_tf32(oacc[n2], a0, a1, a2, a3, b0, b1);
            }
        }
        __syncthreads();
    }

    float iA = 1.f / lA, iB = 1.f / lB;
#pragma unroll
    for (int n2 = 0; n2 < 8; n2++) {
        *(float2*)&o[(size_t)grow0 * DD + hb + n2 * 8 + 2 * l4] =
            make_float2(tf32f(oacc[n2][0] * iA), tf32f(oacc[n2][1] * iA));
        *(float2*)&o[(size_t)grow1 * DD + hb + n2 * 8 + 2 * l4] =
            make_float2(tf32f(oacc[n2][2] * iB), tf32f(oacc[n2][3] * iB));
    }
}

// ---------------- host orchestration ----------------
extern "C" void kernel_launch(void* const* d_in, const int* in_sizes, int n_in,
                              void* d_out, int out_size) {
    const int*   ids  = (const int*)d_in[0];
    const float* emb  = (const float*)d_in[1];
    const float* Wq   = (const float*)d_in[2];
    const float* Wk   = (const float*)d_in[3];
    const float* Wv   = (const float*)d_in[4];
    const float* Wo   = (const float*)d_in[5];
    const float* ln1g = (const float*)d_in[6];
    const float* ln1b = (const float*)d_in[7];
    const float* ln2g = (const float*)d_in[8];
    const float* ln2b = (const float*)d_in[9];
    const float* W1   = (const float*)d_in[10];
    const float* b1   = (const float*)d_in[11];
    const float* W2   = (const float*)d_in[12];
    const float* b2   = (const float*)d_in[13];
    const float* lnfg = (const float*)d_in[14];
    const float* lnfb = (const float*)d_in[15];
    float* out = (float*)d_out;

    float *x, *h, *q, *k, *v, *mlp;
    cudaGetSymbolAddress((void**)&x,   g_x);
    cudaGetSymbolAddress((void**)&h,   g_h);
    cudaGetSymbolAddress((void**)&q,   g_q);
    cudaGetSymbolAddress((void**)&k,   g_k);
    cudaGetSymbolAddress((void**)&v,   g_v);
    cudaGetSymbolAddress((void**)&mlp, g_mlp);

    cudaFuncSetAttribute(flash_kernel,
                         cudaFuncAttributeMaxDynamicSharedMemorySize, FA_SMEM);

    embed_kernel<<<SS, 256>>>(ids, emb, x);

    for (int l = 0; l < NL; l++) {
        const size_t wofs = (size_t)l * DD * DD;
        layernorm_kernel<<<SS, 256>>>(x, ln1g + l * DD, ln1b + l * DD, h);

        // fused QKV (outputs tf32-rounded; q,k re-rounded by rope)
        {
            Ptr3 p;
            p.b0 = Wq + wofs; p.b1 = Wk + wofs; p.b2 = Wv + wofs;
            p.c0 = q; p.c1 = k; p.c2 = v;
            tgemm_kernel<128, false><<<dim3(SS / 128, DD / 128, 3), 256>>>(
                h, DD, 0, p, DD, 0, DD, 0,
                SS, DD, DD, 1.f, nullptr, nullptr, 0, 1, 1);
        }

        rope_kernel<<<(SS * NH * 32 + 255) / 256, 256>>>(q, k);

        flash_kernel<<<dim3(SS / 128, NH), 256, FA_SMEM>>>(q, k, v, h);

        // x = x + attn @ Wo
        tgemm_kernel<64, false><<<dim3(SS / 128, DD / 64, 1), 256>>>(
            h, DD, 0, one(Wo + wofs, x), DD, 0, DD, 0,
            SS, DD, DD, 1.f, nullptr, x, 0, 0, 0);

        layernorm_kernel<<<SS, 256>>>(x, ln2g + l * DD, ln2b + l * DD, h);

        // mlp = gelu(h @ W1 + b1), rounded (feeds W2 A-side)
        tgemm_kernel<128, false><<<dim3(SS / 128, DMLP / 128, 1), 256>>>(
            h, DD, 0, one(W1 + (size_t)l * DD * DMLP, mlp), DMLP, 0, DMLP, 0,
            SS, DMLP, DD, 1.f, b1 + (size_t)l * DMLP, nullptr, 1, 0, 1);

        // x = x + mlp @ W2 + b2
        tgemm_kernel<64, false><<<dim3(SS / 128, DD / 64, 1), 256>>>(
            mlp, DMLP, 0, one(W2 + (size_t)l * DMLP * DD, x), DD, 0, DD, 0,
            SS, DD, DMLP, 1.f, b2 + (size_t)l * DD, x, 0, 0, 0);
    }

    layernorm_kernel<<<SS, 256>>>(x, lnfg, lnfb, h);

    // logits = h @ emb^T
    tgemm_kernel<128, true><<<dim3(SS / 128, (NV + 127) / 128, 1), 256>>>(
        h, DD, 0, one(emb, out), DD, 0, NV, 0,
        SS, NV, DD, 1.f, nullptr, nullptr, 0, 0, 0);
}

// round 11
// speedup vs baseline: 1.4920x; 1.2267x over previous
#include <cuda_runtime.h>
#include <cuda_fp16.h>
#include <math.h>
#include <stdint.h>

#define SS   2048
#define DD   1024
#define NL   4
#define NH   16
#define HDIM 64
#define NV   50257
#define DMLP 4096

// ---------------- scratch ----------------
__device__ float  g_x[SS * DD];
__device__ __half g_h[SS * DD];        // GEMM A-operand buffer (LN / flash out)
__device__ float  g_q[SS * DD];
__device__ float  g_k[SS * DD];
__device__ float  g_v[SS * DD];
__device__ __half g_mlp[SS * DMLP];    // GEMM A-operand buffer (GELU out)

// ---------------- helpers ----------------
__device__ __forceinline__ unsigned f2tf(float f) {
    unsigned u;
    asm("cvt.rna.tf32.f32 %0, %1;" : "=r"(u) : "f"(f));
    return u;
}
__device__ __forceinline__ float tf32f(float f) {
    return __uint_as_float(f2tf(f));
}
__device__ __forceinline__ unsigned packh(float a, float b) {
    unsigned d;
    asm("cvt.rn.f16x2.f32 %0, %1, %2;" : "=r"(d) : "f"(b), "f"(a));
    return d;
}
__device__ __forceinline__ unsigned packh2(float2 f) { return packh(f.x, f.y); }

// ---------------- embedding gather ----------------
__global__ void embed_kernel(const int* __restrict__ ids,
                             const float* __restrict__ emb,
                             float* __restrict__ x) {
    int t = blockIdx.x;
    int id = ids[t];
    if (id < 0) id = 0;
    if (id >= NV) id = NV - 1;
    const float* src = emb + (size_t)id * DD;
    float* dst = x + (size_t)t * DD;
    for (int d = threadIdx.x; d < DD; d += blockDim.x) dst[d] = src[d];
}

// ---------------- layernorm (half out: feeds GEMM A) ----------------
__global__ void layernorm_kernel(const float* __restrict__ x,
                                 const float* __restrict__ g,
                                 const float* __restrict__ b,
                                 __half* __restrict__ out) {
    __shared__ float red[256];
    int row = blockIdx.x;
    const float* xr = x + (size_t)row * DD;
    float s = 0.f;
    for (int d = threadIdx.x; d < DD; d += 256) s += xr[d];
    red[threadIdx.x] = s;
    __syncthreads();
    for (int o = 128; o > 0; o >>= 1) {
        if (threadIdx.x < o) red[threadIdx.x] += red[threadIdx.x + o];
        __syncthreads();
    }
    float mean = red[0] * (1.f / DD);
    __syncthreads();
    float v = 0.f;
    for (int d = threadIdx.x; d < DD; d += 256) {
        float t = xr[d] - mean;
        v += t * t;
    }
    red[threadIdx.x] = v;
    __syncthreads();
    for (int o = 128; o > 0; o >>= 1) {
        if (threadIdx.x < o) red[threadIdx.x] += red[threadIdx.x + o];
        __syncthreads();
    }
    float inv = rsqrtf(red[0] * (1.f / DD) + 1e-5f);
    __half* orow = out + (size_t)row * DD;
    for (int d = threadIdx.x; d < DD; d += 256)
        orow[d] = __float2half((xr[d] - mean) * inv * g[d] + b[d]);
}

// ---------------- RoPE (stores tf32-rounded fp32: flash uses raw bits) -----
__global__ void rope_kernel(float* __restrict__ q, float* __restrict__ k) {
    int idx = blockIdx.x * blockDim.x + threadIdx.x;
    int i = idx & 31;
    int rest = idx >> 5;
    int h = rest & (NH - 1);
    int t = rest >> 4;
    if (t >= SS) return;
    float inv_freq = powf(10000.f, -(float)i / 32.f);
    float ang = (float)t * inv_freq;
    float c = cosf(ang), s = sinf(ang);
    size_t base = (size_t)t * DD + h * HDIM;
    float x1 = q[base + i], x2 = q[base + i + 32];
    q[base + i]      = tf32f(x1 * c - x2 * s);
    q[base + i + 32] = tf32f(x2 * c + x1 * s);
    float y1 = k[base + i], y2 = k[base + i + 32];
    k[base + i]      = tf32f(y1 * c - y2 * s);
    k[base + i + 32] = tf32f(y2 * c + y1 * s);
}

// ---------------- PTX helpers ----------------
__device__ __forceinline__ void cp16(unsigned dst, const void* src, int bytes) {
    asm volatile("cp.async.cg.shared.global [%0], [%1], 16, %2;"
                 :: "r"(dst), "l"(src), "r"(bytes));
}
__device__ __forceinline__ void cp_commit() {
    asm volatile("cp.async.commit_group;");
}
template <int N>
__device__ __forceinline__ void cp_wait() {
    asm volatile("cp.async.wait_group %0;" :: "n"(N));
}
__device__ __forceinline__ void mma_tf32(float c[4], unsigned a0, unsigned a1,
                                         unsigned a2, unsigned a3,
                                         unsigned b0, unsigned b1) {
    asm volatile(
        "mma.sync.aligned.m16n8k8.row.col.f32.tf32.tf32.f32 "
        "{%0,%1,%2,%3}, {%4,%5,%6,%7}, {%8,%9}, {%0,%1,%2,%3};"
        : "+f"(c[0]), "+f"(c[1]), "+f"(c[2]), "+f"(c[3])
        : "r"(a0), "r"(a1), "r"(a2), "r"(a3), "r"(b0), "r"(b1));
}
__device__ __forceinline__ void mma_f16(float c[4], unsigned a0, unsigned a1,
                                        unsigned a2, unsigned a3,
                                        unsigned b0, unsigned b1) {
    asm volatile(
        "mma.sync.aligned.m16n8k16.row.col.f32.f16.f16.f32 "
        "{%0,%1,%2,%3}, {%4,%5,%6,%7}, {%8,%9}, {%0,%1,%2,%3};"
        : "+f"(c[0]), "+f"(c[1]), "+f"(c[2]), "+f"(c[3])
        : "r"(a0), "r"(a1), "r"(a2), "r"(a3), "r"(b0), "r"(b1));
}

// ================= FP16 GEMM, BK=32, half A-operand, dynamic smem ==========
#define BMT  128
#define BKT2 32
#define APH  40        // A pitch in halves: row stride 80B -> conflict-free

struct Ptr3 {
    const float* b0; const float* b1; const float* b2;
    void* c0; void* c1; void* c2;
};

template <int BN, bool TB>
__global__ void __launch_bounds__(256, 2)
tgemm_kernel(const __half* __restrict__ A, int lda, long long strideA,
             Ptr3 p, int ldb, long long strideB,
             int ldc, long long strideC,
             int M, int N, int K, float alpha,
             const float* __restrict__ bias,
             const float* __restrict__ res,
             int do_gelu, int multiB, int out_mode) {   // out_mode: 0 f32, 1 f32+tf32rnd, 2 f16
    const int BPN = (BN == 128) ? 132 : 68;  // [k][n] float pitch
    const int BPT = 40;                       // [n][k] float pitch (BK=32)
    const int MT  = (BN == 128) ? 4 : 2;
    const int AST = 128 * APH;                // halves per A stage
    const int BST = TB ? (BN * BPT) : (BKT2 * BPN);  // floats per B stage

    extern __shared__ __align__(16) char dsm[];
    __half* Ash = (__half*)dsm;
    float*  Bsf = (float*)(dsm + 2 * AST * 2);

    int z = blockIdx.z;
    const float* B;
    void* C;
    if (multiB) {
        B = (z == 0) ? p.b0 : (z == 1) ? p.b1 : p.b2;
        C = (z == 0) ? p.c0 : (z == 1) ? p.c1 : p.c2;
    } else {
        B = p.b0 + (size_t)z * strideB;
        C = (out_mode == 2) ? (void*)((__half*)p.c0 + (size_t)z * strideC)
                            : (void*)((float*)p.c0 + (size_t)z * strideC);
        if (res) res += (size_t)z * strideC;
    }
    A += (size_t)z * strideA;

    int row0 = blockIdx.x * BMT;
    int col0 = blockIdx.y * BN;
    int nk = K / BKT2;

    int tid = threadIdx.x;
    int lane = tid & 31, warp = tid >> 5;
    int l4 = lane & 3, l28 = lane >> 2;
    int mbase, nbase;
    if (BN == 128) { mbase = (warp >> 2) * 64; nbase = (warp & 3) * 32; }
    else           { mbase = (warp >> 1) * 32; nbase = (warp & 1) * 32; }

    unsigned sA[2], sB[2];
    sA[0] = (unsigned)__cvta_generic_to_shared(Ash);
    sA[1] = sA[0] + AST * 2;
    sB[0] = (unsigned)__cvta_generic_to_shared(Bsf);
    sB[1] = sB[0] + BST * 4;

    float acc[MT][4][4];
#pragma unroll
    for (int mt = 0; mt < MT; mt++)
#pragma unroll
        for (int nt = 0; nt < 4; nt++)
#pragma unroll
            for (int c = 0; c < 4; c++) acc[mt][nt][c] = 0.f;

    auto prefetch = [&](int s, int k0) {
        // A: 128 rows x 32 halves = 8KB -> 512 cp16
#pragma unroll
        for (int i = 0; i < 2; i++) {
            int lin = i * 256 + tid;
            int m = lin >> 2, f8 = lin & 3;
            cp16(sA[s] + (m * APH + f8 * 8) * 2,
                 A + (size_t)(row0 + m) * lda + k0 + f8 * 8, 16);
        }
        if (TB) {
            // B: BN rows x 32 floats
#pragma unroll
            for (int i = 0; i < BN / 32; i++) {
                int lin = i * 256 + tid;
                int n = lin >> 3, f4 = lin & 7;
                int gn = col0 + n;
                cp16(sB[s] + (n * BPT + f4 * 4) * 4,
                     B + (size_t)gn * ldb + k0 + f4 * 4, (gn < N) ? 16 : 0);
            }
        } else {
            // B: 32 rows x BN floats
#pragma unroll
            for (int i = 0; i < BN / 32; i++) {
                int lin = i * 256 + tid;
                int kk = lin / (BN / 4), f4 = lin % (BN / 4);
                cp16(sB[s] + (kk * BPN + f4 * 4) * 4,
                     B + (size_t)(k0 + kk) * ldb + col0 + f4 * 4, 16);
            }
        }
        cp_commit();
    };

    prefetch(0, 0);

    for (int ks = 0; ks < nk; ks++) {
        int cur = ks & 1, nxt = cur ^ 1;
        bool more = (ks + 1) < nk;
        if (more) prefetch(nxt, (ks + 1) * BKT2);

        if (more) cp_wait<1>(); else cp_wait<0>();
        __syncthreads();

        const __half* As = Ash + cur * AST;
        const float*  Bs = Bsf + cur * BST;

#pragma unroll
        for (int kb = 0; kb < BKT2; kb += 16) {
            unsigned af[MT][4];
#pragma unroll
            for (int mt = 0; mt < MT; mt++) {
                int mrow = mbase + mt * 16 + l28;
                af[mt][0] = *(const unsigned*)&As[mrow * APH + kb + 2 * l4];
                af[mt][1] = *(const unsigned*)&As[(mrow + 8) * APH + kb + 2 * l4];
                af[mt][2] = *(const unsigned*)&As[mrow * APH + kb + 2 * l4 + 8];
                af[mt][3] = *(const unsigned*)&As[(mrow + 8) * APH + kb + 2 * l4 + 8];
            }
            unsigned bf[4][2];
#pragma unroll
            for (int nt = 0; nt < 4; nt++) {
                int ncol = nbase + nt * 8 + l28;
                if (TB) {
                    bf[nt][0] = packh2(*(const float2*)&Bs[ncol * BPT + kb + 2 * l4]);
                    bf[nt][1] = packh2(*(const float2*)&Bs[ncol * BPT + kb + 2 * l4 + 8]);
                } else {
                    bf[nt][0] = packh(Bs[(kb + 2 * l4) * BPN + ncol],
                                      Bs[(kb + 2 * l4 + 1) * BPN + ncol]);
                    bf[nt][1] = packh(Bs[(kb + 2 * l4 + 8) * BPN + ncol],
                                      Bs[(kb + 2 * l4 + 9) * BPN + ncol]);
                }
            }
#pragma unroll
            for (int mt = 0; mt < MT; mt++)
#pragma unroll
                for (int nt = 0; nt < 4; nt++)
                    mma_f16(acc[mt][nt], af[mt][0], af[mt][1], af[mt][2], af[mt][3],
                            bf[nt][0], bf[nt][1]);
        }
        __syncthreads();
    }

#pragma unroll
    for (int mt = 0; mt < MT; mt++) {
#pragma unroll
        for (int nt = 0; nt < 4; nt++) {
#pragma unroll
            for (int c = 0; c < 4; c++) {
                int gr = row0 + mbase + mt * 16 + l28 + ((c >= 2) ? 8 : 0);
                int gc = col0 + nbase + nt * 8 + l4 * 2 + (c & 1);
                if (gc >= N) continue;
                float v = alpha * acc[mt][nt][c];
                if (bias) v += bias[gc];
                if (res) v += res[(size_t)gr * ldc + gc];
                if (do_gelu) v = 0.5f * v * (1.f + erff(v * 0.70710678118654752f));
                size_t idx = (size_t)gr * ldc + gc;
                if (out_mode == 2)      ((__half*)C)[idx] = __float2half(v);
                else if (out_mode == 1) ((float*)C)[idx] = tf32f(v);
                else                    ((float*)C)[idx] = v;
            }
        }
    }
}

static inline Ptr3 one(const float* b, void* c) {
    Ptr3 p; p.b0 = b; p.b1 = nullptr; p.b2 = nullptr;
    p.c0 = c; p.c1 = nullptr; p.c2 = nullptr; return p;
}

// GEMM dynamic smem sizes
#define SM_A    (2 * 128 * APH * 2)
#define SM_TB   (SM_A + 2 * 128 * 40 * 4)
#define SM_NT128 (SM_A + 2 * 32 * 132 * 4)
#define SM_NT64  (SM_A + 2 * 32 * 68 * 4)

// ================= fused causal flash attention (tf32, R7 pipeline) =========
#define FKP 68
#define FVP 72
#define FA_SMEM ((2 * 128 * FKP + 2 * 128 * FVP) * 4)

__global__ void __launch_bounds__(256, 1)
flash_kernel(const float* __restrict__ q, const float* __restrict__ k,
             const float* __restrict__ v, __half* __restrict__ o) {
    extern __shared__ __align__(16) float fsm[];
    float* Ksm[2] = { fsm, fsm + 128 * FKP };
    float* Vsm[2] = { fsm + 2 * 128 * FKP, fsm + 2 * 128 * FKP + 128 * FVP };
    unsigned uK[2], uV[2];
    uK[0] = (unsigned)__cvta_generic_to_shared(Ksm[0]);
    uK[1] = (unsigned)__cvta_generic_to_shared(Ksm[1]);
    uV[0] = (unsigned)__cvta_generic_to_shared(Vsm[0]);
    uV[1] = (unsigned)__cvta_generic_to_shared(Vsm[1]);

    int rb = 15 - blockIdx.x;
    int hb = blockIdx.y * HDIM;
    int row0 = rb * 128;

    int tid = threadIdx.x, lane = tid & 31, w = tid >> 5;
    int l4 = lane & 3, l28 = lane >> 2;
    int rl0 = w * 16 + l28;
    int rl1 = rl0 + 8;
    int grow0 = row0 + rl0, grow1 = row0 + rl1;

    unsigned qa[8][4];
#pragma unroll
    for (int c = 0; c < 8; c++) {
        qa[c][0] = __float_as_uint(0.125f * q[(size_t)grow0 * DD + hb + 8 * c + l4]);
        qa[c][1] = __float_as_uint(0.125f * q[(size_t)grow1 * DD + hb + 8 * c + l4]);
        qa[c][2] = __float_as_uint(0.125f * q[(size_t)grow0 * DD + hb + 8 * c + l4 + 4]);
        qa[c][3] = __float_as_uint(0.125f * q[(size_t)grow1 * DD + hb + 8 * c + l4 + 4]);
    }

    float oacc[8][4];
#pragma unroll
    for (int n2 = 0; n2 < 8; n2++)
#pragma unroll
        for (int c = 0; c < 4; c++) oacc[n2][c] = 0.f;
    float mA = -1e30f, mB = -1e30f, lA = 0.f, lB = 0.f;

    auto prefetch = [&](int j, int s) {
#pragma unroll
        for (int i = 0; i < 8; i++) {
            int lin = i * 256 + tid;
            int r = lin >> 4, f4 = lin & 15;
            const float* gk = k + (size_t)(j * 128 + r) * DD + hb + f4 * 4;
            const float* gv = v + (size_t)(j * 128 + r) * DD + hb + f4 * 4;
            cp16(uK[s] + (r * FKP + f4 * 4) * 4, gk, 16);
            cp16(uV[s] + (r * FVP + f4 * 4) * 4, gv, 16);
        }
        cp_commit();
    };

    int src0 = (lane & ~3) | (l4 >> 1);
    int src1 = src0 + 2;
    bool par = (l4 & 1) != 0;

    prefetch(0, 0);

    for (int j = 0; j <= rb; j++) {
        int s = j & 1;
        bool more = j < rb;
        if (more) prefetch(j + 1, s ^ 1);
        if (more) cp_wait<1>(); else cp_wait<0>();
        __syncthreads();

        float sacc[16][4];
#pragma unroll
        for (int t = 0; t < 16; t++)
#pragma unroll
            for (int c = 0; c < 4; c++) sacc[t][c] = 0.f;
#pragma unroll
        for (int c = 0; c < 8; c++) {
#pragma unroll
            for (int t = 0; t < 16; t++) {
                unsigned b0 = __float_as_uint(Ksm[s][(t * 8 + l28) * FKP + 8 * c + l4]);
                unsigned b1 = __float_as_uint(Ksm[s][(t * 8 + l28) * FKP + 8 * c + l4 + 4]);
                mma_tf32(sacc[t], qa[c][0], qa[c][1], qa[c][2], qa[c][3], b0, b1);
            }
        }

        if (j == rb) {
#pragma unroll
            for (int t = 0; t < 16; t++) {
                int cb = 8 * t + 2 * l4;
                if (cb     > rl0) sacc[t][0] = -1e30f;
                if (cb + 1 > rl0) sacc[t][1] = -1e30f;
                if (cb     > rl1) sacc[t][2] = -1e30f;
                if (cb + 1 > rl1) sacc[t][3] = -1e30f;
            }
        }

        float tmA = -1e30f, tmB = -1e30f;
#pragma unroll
        for (int t = 0; t < 16; t++) {
            tmA = fmaxf(tmA, fmaxf(sacc[t][0], sacc[t][1]));
            tmB = fmaxf(tmB, fmaxf(sacc[t][2], sacc[t][3]));
        }
        tmA = fmaxf(tmA, __shfl_xor_sync(0xffffffffu, tmA, 1));
        tmA = fmaxf(tmA, __shfl_xor_sync(0xffffffffu, tmA, 2));
        tmB = fmaxf(tmB, __shfl_xor_sync(0xffffffffu, tmB, 1));
        tmB = fmaxf(tmB, __shfl_xor_sync(0xffffffffu, tmB, 2));

        float mnA = fmaxf(mA, tmA), mnB = fmaxf(mB, tmB);
        float cA = __expf(mA - mnA), cB = __expf(mB - mnB);
        mA = mnA; mB = mnB;

        float tsA = 0.f, tsB = 0.f;
#pragma unroll
        for (int t = 0; t < 16; t++) {
            sacc[t][0] = __expf(sacc[t][0] - mA);
            sacc[t][1] = __expf(sacc[t][1] - mA);
            sacc[t][2] = __expf(sacc[t][2] - mB);
            sacc[t][3] = __expf(sacc[t][3] - mB);
            tsA += sacc[t][0] + sacc[t][1];
            tsB += sacc[t][2] + sacc[t][3];
        }
        tsA += __shfl_xor_sync(0xffffffffu, tsA, 1);
        tsA += __shfl_xor_sync(0xffffffffu, tsA, 2);
        tsB += __shfl_xor_sync(0xffffffffu, tsB, 1);
        tsB += __shfl_xor_sync(0xffffffffu, tsB, 2);
        lA = lA * cA + tsA;
        lB = lB * cB + tsB;

#pragma unroll
        for (int n2 = 0; n2 < 8; n2++) {
            oacc[n2][0] *= cA; oacc[n2][1] *= cA;
            oacc[n2][2] *= cB; oacc[n2][3] *= cB;
        }

#pragma unroll
        for (int kc = 0; kc < 16; kc++) {
            float v00 = __shfl_sync(0xffffffffu, sacc[kc][0], src0);
            float v01 = __shfl_sync(0xffffffffu, sacc[kc][1], src0);
            float v10 = __shfl_sync(0xffffffffu, sacc[kc][2], src0);
            float v11 = __shfl_sync(0xffffffffu, sacc[kc][3], src0);
            float w00 = __shfl_sync(0xffffffffu, sacc[kc][0], src1);
            float w01 = __shfl_sync(0xffffffffu, sacc[kc][1], src1);
            float w10 = __shfl_sync(0xffffffffu, sacc[kc][2], src1);
            float w11 = __shfl_sync(0xffffffffu, sacc[kc][3], src1);
            unsigned a0 = f2tf(par ? v01 : v00);
            unsigned a1 = f2tf(par ? v11 : v10);
            unsigned a2 = f2tf(par ? w01 : w00);
            unsigned a3 = f2tf(par ? w11 : w10);
#pragma unroll
            for (int n2 = 0; n2 < 8; n2++) {
                unsigned b0 = __float_as_uint(Vsm[s][(kc * 8 + l4) * FVP + n2 * 8 + l28]);
                unsigned b1 = __float_as_uint(Vsm[s][(kc * 8 + l4 + 4) * FVP + n2 * 8 + l28]);
                mma_tf32(oacc[n2], a0, a1, a2, a3, b0, b1);
            }
        }
        __syncthreads();
    }

    // output feeds Wo GEMM A-side (half)
    float iA = 1.f / lA, iB = 1.f / lB;
#pragma unroll
    for (int n2 = 0; n2 < 8; n2++) {
        *(__half2*)&o[(size_t)grow0 * DD + hb + n2 * 8 + 2 * l4] =
            __floats2half2_rn(oacc[n2][0] * iA, oacc[n2][1] * iA);
        *(__half2*)&o[(size_t)grow1 * DD + hb + n2 * 8 + 2 * l4] =
            __floats2half2_rn(oacc[n2][2] * iB, oacc[n2][3] * iB);
    }
}

// ---------------- host orchestration ----------------
extern "C" void kernel_launch(void* const* d_in, const int* in_sizes, int n_in,
                              void* d_out, int out_size) {
    const int*   ids  = (const int*)d_in[0];
    const float* emb  = (const float*)d_in[1];
    const float* Wq   = (const float*)d_in[2];
    const float* Wk   = (const float*)d_in[3];
    const float* Wv   = (const float*)d_in[4];
    const float* Wo   = (const float*)d_in[5];
    const float* ln1g = (const float*)d_in[6];
    const float* ln1b = (const float*)d_in[7];
    const float* ln2g = (const float*)d_in[8];
    const float* ln2b = (const float*)d_in[9];
    const float* W1   = (const float*)d_in[10];
    const float* b1   = (const float*)d_in[11];
    const float* W2   = (const float*)d_in[12];
    const float* b2   = (const float*)d_in[13];
    const float* lnfg = (const float*)d_in[14];
    const float* lnfb = (const float*)d_in[15];
    float* out = (float*)d_out;

    float *x, *q, *k, *v;
    __half *h, *mlp;
    cudaGetSymbolAddress((void**)&x,   g_x);
    cudaGetSymbolAddress((void**)&h,   g_h);
    cudaGetSymbolAddress((void**)&q,   g_q);
    cudaGetSymbolAddress((void**)&k,   g_k);
    cudaGetSymbolAddress((void**)&v,   g_v);
    cudaGetSymbolAddress((void**)&mlp, g_mlp);

    cudaFuncSetAttribute(flash_kernel,
                         cudaFuncAttributeMaxDynamicSharedMemorySize, FA_SMEM);
    cudaFuncSetAttribute(tgemm_kernel<128, false>,
                         cudaFuncAttributeMaxDynamicSharedMemorySize, SM_NT128);
    cudaFuncSetAttribute(tgemm_kernel<64, false>,
                         cudaFuncAttributeMaxDynamicSharedMemorySize, SM_NT64);
    cudaFuncSetAttribute(tgemm_kernel<128, true>,
                         cudaFuncAttributeMaxDynamicSharedMemorySize, SM_TB);

    embed_kernel<<<SS, 256>>>(ids, emb, x);

    for (int l = 0; l < NL; l++) {
        const size_t wofs = (size_t)l * DD * DD;
        layernorm_kernel<<<SS, 256>>>(x, ln1g + l * DD, ln1b + l * DD, h);

        // fused QKV (fp32 out, tf32-rounded; q,k re-rounded by rope, v used raw)
        {
            Ptr3 p;
            p.b0 = Wq + wofs; p.b1 = Wk + wofs; p.b2 = Wv + wofs;
            p.c0 = q; p.c1 = k; p.c2 = v;
            tgemm_kernel<128, false><<<dim3(SS / 128, DD / 128, 3), 256, SM_NT128>>>(
                h, DD, 0, p, DD, 0, DD, 0,
                SS, DD, DD, 1.f, nullptr, nullptr, 0, 1, 1);
        }

        rope_kernel<<<(SS * NH * 32 + 255) / 256, 256>>>(q, k);

        flash_kernel<<<dim3(SS / 128, NH), 256, FA_SMEM>>>(q, k, v, h);

        // x = x + attn @ Wo (fp32 out)
        tgemm_kernel<64, false><<<dim3(SS / 128, DD / 64, 1), 256, SM_NT64>>>(
            h, DD, 0, one(Wo + wofs, x), DD, 0, DD, 0,
            SS, DD, DD, 1.f, nullptr, x, 0, 0, 0);

        layernorm_kernel<<<SS, 256>>>(x, ln2g + l * DD, ln2b + l * DD, h);

        // mlp = gelu(h @ W1 + b1) -> half (feeds W2 A-side)
        tgemm_kernel<128, false><<<dim3(SS / 128, DMLP / 128, 1), 256, SM_NT128>>>(
            h, DD, 0, one(W1 + (size_t)l * DD * DMLP, mlp), DMLP, 0, DMLP, 0,
            SS, DMLP, DD, 1.f, b1 + (size_t)l * DMLP, nullptr, 1, 0, 2);

        // x = x + mlp @ W2 + b2 (fp32 out)
        tgemm_kernel<64, false><<<dim3(SS / 128, DD / 64, 1), 256, SM_NT64>>>(
            mlp, DMLP, 0, one(W2 + (size_t)l * DMLP * DD, x), DD, 0, DD, 0,
            SS, DD, DMLP, 1.f, b2 + (size_t)l * DD, x, 0, 0, 0);
    }

    layernorm_kernel<<<SS, 256>>>(x, lnfg, lnfb, h);

    // logits = h @ emb^T
    tgemm_kernel<128, true><<<dim3(SS / 128, (NV + 127) / 128, 1), 256, SM_TB>>>(
        h, DD, 0, one(emb, out), DD, 0, NV, 0,
        SS, NV, DD, 1.f, nullptr, nullptr, 0, 0, 0);
}

// round 12
// speedup vs baseline: 1.5361x; 1.0296x over previous
#include <cuda_runtime.h>
#include <cuda_fp16.h>
#include <math.h>
#include <stdint.h>

#define SS   2048
#define DD   1024
#define NL   4
#define NH   16
#define HDIM 64
#define NV   50257
#define DMLP 4096

// ---------------- scratch ----------------
__device__ float  g_x[SS * DD];
__device__ __half g_h[SS * DD];
__device__ float  g_q[SS * DD];
__device__ float  g_k[SS * DD];
__device__ float  g_v[SS * DD];
__device__ __half g_mlp[SS * DMLP];
// half transposed weights [l][n][k] and half emb [n][k]
__device__ __half g_wqh[(size_t)NL * DD * DD];
__device__ __half g_wkh[(size_t)NL * DD * DD];
__device__ __half g_wvh[(size_t)NL * DD * DD];
__device__ __half g_woh[(size_t)NL * DD * DD];
__device__ __half g_w1h[(size_t)NL * DMLP * DD];
__device__ __half g_w2h[(size_t)NL * DD * DMLP];
__device__ __half g_embh[(size_t)NV * DD];

// ---------------- helpers ----------------
__device__ __forceinline__ unsigned f2tf(float f) {
    unsigned u;
    asm("cvt.rna.tf32.f32 %0, %1;" : "=r"(u) : "f"(f));
    return u;
}
__device__ __forceinline__ float tf32f(float f) {
    return __uint_as_float(f2tf(f));
}

// ---------------- weight transpose + half convert: W[K][N] -> Wt[N][K] -----
__global__ void transph_kernel(const float* __restrict__ W, __half* __restrict__ Wt,
                               int K, int N, long long wstride, long long tstride) {
    __shared__ float tile[32][33];
    const float* Wz = W + (size_t)blockIdx.z * wstride;
    __half* Tz = Wt + (size_t)blockIdx.z * tstride;
    int n0 = blockIdx.x * 32, k0 = blockIdx.y * 32;
    int tx = threadIdx.x & 31, ty = threadIdx.x >> 5;
#pragma unroll
    for (int i = 0; i < 4; i++)
        tile[ty + i * 8][tx] = Wz[(size_t)(k0 + ty + i * 8) * N + n0 + tx];
    __syncthreads();
#pragma unroll
    for (int i = 0; i < 4; i++)
        Tz[(size_t)(n0 + ty + i * 8) * K + k0 + tx] = __float2half(tile[tx][ty + i * 8]);
}

// ---------------- straight half convert (emb) ----------------
__global__ void convh_kernel(const float4* __restrict__ in,
                             uint2* __restrict__ out, long long n4) {
    long long i = blockIdx.x * (long long)blockDim.x + threadIdx.x;
    long long stride = (long long)gridDim.x * blockDim.x;
    for (; i < n4; i += stride) {
        float4 t = in[i];
        unsigned lo, hi;
        asm("cvt.rn.f16x2.f32 %0, %1, %2;" : "=r"(lo) : "f"(t.y), "f"(t.x));
        asm("cvt.rn.f16x2.f32 %0, %1, %2;" : "=r"(hi) : "f"(t.w), "f"(t.z));
        out[i] = make_uint2(lo, hi);
    }
}

// ---------------- embedding gather ----------------
__global__ void embed_kernel(const int* __restrict__ ids,
                             const float* __restrict__ emb,
                             float* __restrict__ x) {
    int t = blockIdx.x;
    int id = ids[t];
    if (id < 0) id = 0;
    if (id >= NV) id = NV - 1;
    const float* src = emb + (size_t)id * DD;
    float* dst = x + (size_t)t * DD;
    for (int d = threadIdx.x; d < DD; d += blockDim.x) dst[d] = src[d];
}

// ---------------- layernorm (half out) ----------------
__global__ void layernorm_kernel(const float* __restrict__ x,
                                 const float* __restrict__ g,
                                 const float* __restrict__ b,
                                 __half* __restrict__ out) {
    __shared__ float red[256];
    int row = blockIdx.x;
    const float* xr = x + (size_t)row * DD;
    float s = 0.f;
    for (int d = threadIdx.x; d < DD; d += 256) s += xr[d];
    red[threadIdx.x] = s;
    __syncthreads();
    for (int o = 128; o > 0; o >>= 1) {
        if (threadIdx.x < o) red[threadIdx.x] += red[threadIdx.x + o];
        __syncthreads();
    }
    float mean = red[0] * (1.f / DD);
    __syncthreads();
    float v = 0.f;
    for (int d = threadIdx.x; d < DD; d += 256) {
        float t = xr[d] - mean;
        v += t * t;
    }
    red[threadIdx.x] = v;
    __syncthreads();
    for (int o = 128; o > 0; o >>= 1) {
        if (threadIdx.x < o) red[threadIdx.x] += red[threadIdx.x + o];
        __syncthreads();
    }
    float inv = rsqrtf(red[0] * (1.f / DD) + 1e-5f);
    __half* orow = out + (size_t)row * DD;
    for (int d = threadIdx.x; d < DD; d += 256)
        orow[d] = __float2half((xr[d] - mean) * inv * g[d] + b[d]);
}

// ---------------- RoPE (tf32-rounded fp32 for flash) ----------------
__global__ void rope_kernel(float* __restrict__ q, float* __restrict__ k) {
    int idx = blockIdx.x * blockDim.x + threadIdx.x;
    int i = idx & 31;
    int rest = idx >> 5;
    int h = rest & (NH - 1);
    int t = rest >> 4;
    if (t >= SS) return;
    float inv_freq = powf(10000.f, -(float)i / 32.f);
    float ang = (float)t * inv_freq;
    float c = cosf(ang), s = sinf(ang);
    size_t base = (size_t)t * DD + h * HDIM;
    float x1 = q[base + i], x2 = q[base + i + 32];
    q[base + i]      = tf32f(x1 * c - x2 * s);
    q[base + i + 32] = tf32f(x2 * c + x1 * s);
    float y1 = k[base + i], y2 = k[base + i + 32];
    k[base + i]      = tf32f(y1 * c - y2 * s);
    k[base + i + 32] = tf32f(y2 * c + y1 * s);
}

// ---------------- PTX helpers ----------------
__device__ __forceinline__ void cp16(unsigned dst, const void* src, int bytes) {
    asm volatile("cp.async.cg.shared.global [%0], [%1], 16, %2;"
                 :: "r"(dst), "l"(src), "r"(bytes));
}
__device__ __forceinline__ void cp_commit() {
    asm volatile("cp.async.commit_group;");
}
template <int N>
__device__ __forceinline__ void cp_wait() {
    asm volatile("cp.async.wait_group %0;" :: "n"(N));
}
__device__ __forceinline__ void mma_tf32(float c[4], unsigned a0, unsigned a1,
                                         unsigned a2, unsigned a3,
                                         unsigned b0, unsigned b1) {
    asm volatile(
        "mma.sync.aligned.m16n8k8.row.col.f32.tf32.tf32.f32 "
        "{%0,%1,%2,%3}, {%4,%5,%6,%7}, {%8,%9}, {%0,%1,%2,%3};"
        : "+f"(c[0]), "+f"(c[1]), "+f"(c[2]), "+f"(c[3])
        : "r"(a0), "r"(a1), "r"(a2), "r"(a3), "r"(b0), "r"(b1));
}
__device__ __forceinline__ void mma_f16(float c[4], unsigned a0, unsigned a1,
                                        unsigned a2, unsigned a3,
                                        unsigned b0, unsigned b1) {
    asm volatile(
        "mma.sync.aligned.m16n8k16.row.col.f32.f16.f16.f32 "
        "{%0,%1,%2,%3}, {%4,%5,%6,%7}, {%8,%9}, {%0,%1,%2,%3};"
        : "+f"(c[0]), "+f"(c[1]), "+f"(c[2]), "+f"(c[3])
        : "r"(a0), "r"(a1), "r"(a2), "r"(a3), "r"(b0), "r"(b1));
}

// ================= all-half GEMM: A[m][k] half, B[n][k] half, BK=32 ========
// Zero conversions in the mainloop. Pitches 40 halves -> conflict-free.
#define BKT2 32
#define APH  40

struct HPtr3 {
    const __half* b0; const __half* b1; const __half* b2;
    void* c0; void* c1; void* c2;
};

template <int BN>
__global__ void __launch_bounds__(256, 2)
hgemm_kernel(const __half* __restrict__ A, int lda, long long strideA,
             HPtr3 p, int ldb,
             int ldc, long long strideC,
             int M, int N, int K, float alpha,
             const float* __restrict__ bias,
             const float* __restrict__ res,
             int do_gelu, int multiB, int out_mode) {  // 0 f32, 1 f32+tf32, 2 f16
    const int MT  = (BN == 128) ? 4 : 2;
    const int AST = 128 * APH;      // halves
    const int BST = BN * APH;       // halves

    extern __shared__ __align__(16) __half dsm[];
    __half* Ash = dsm;
    __half* Bsh = dsm + 2 * AST;

    int z = blockIdx.z;
    const __half* B;
    void* C;
    if (multiB) {
        B = (z == 0) ? p.b0 : (z == 1) ? p.b1 : p.b2;
        C = (z == 0) ? p.c0 : (z == 1) ? p.c1 : p.c2;
    } else {
        B = p.b0;
        C = (out_mode == 2) ? (void*)((__half*)p.c0 + (size_t)z * strideC)
                            : (void*)((float*)p.c0 + (size_t)z * strideC);
        if (res) res += (size_t)z * strideC;
    }
    A += (size_t)z * strideA;

    int row0 = blockIdx.x * 128;
    int col0 = blockIdx.y * BN;
    int nk = K / BKT2;

    int tid = threadIdx.x;
    int lane = tid & 31, warp = tid >> 5;
    int l4 = lane & 3, l28 = lane >> 2;
    int mbase, nbase;
    if (BN == 128) { mbase = (warp >> 2) * 64; nbase = (warp & 3) * 32; }
    else           { mbase = (warp >> 1) * 32; nbase = (warp & 1) * 32; }

    unsigned sA[2], sB[2];
    sA[0] = (unsigned)__cvta_generic_to_shared(Ash);
    sA[1] = sA[0] + AST * 2;
    sB[0] = (unsigned)__cvta_generic_to_shared(Bsh);
    sB[1] = sB[0] + BST * 2;

    float acc[MT][4][4];
#pragma unroll
    for (int mt = 0; mt < MT; mt++)
#pragma unroll
        for (int nt = 0; nt < 4; nt++)
#pragma unroll
            for (int c = 0; c < 4; c++) acc[mt][nt][c] = 0.f;

    auto prefetch = [&](int s, int k0) {
#pragma unroll
        for (int i = 0; i < 2; i++) {
            int lin = i * 256 + tid;
            int m = lin >> 2, f8 = lin & 3;
            cp16(sA[s] + (m * APH + f8 * 8) * 2,
                 A + (size_t)(row0 + m) * lda + k0 + f8 * 8, 16);
        }
#pragma unroll
        for (int i = 0; i < BN / 64; i++) {
            int lin = i * 256 + tid;
            int n = lin >> 2, f8 = lin & 3;
            int gn = col0 + n;
            cp16(sB[s] + (n * APH + f8 * 8) * 2,
                 B + (size_t)gn * ldb + k0 + f8 * 8, (gn < N) ? 16 : 0);
        }
        cp_commit();
    };

    prefetch(0, 0);

    for (int ks = 0; ks < nk; ks++) {
        int cur = ks & 1, nxt = cur ^ 1;
        bool more = (ks + 1) < nk;
        if (more) prefetch(nxt, (ks + 1) * BKT2);

        if (more) cp_wait<1>(); else cp_wait<0>();
        __syncthreads();

        const __half* As = Ash + cur * AST;
        const __half* Bs = Bsh + cur * BST;

#pragma unroll
        for (int kb = 0; kb < BKT2; kb += 16) {
            unsigned af[MT][4];
#pragma unroll
            for (int mt = 0; mt < MT; mt++) {
                int mrow = mbase + mt * 16 + l28;
                af[mt][0] = *(const unsigned*)&As[mrow * APH + kb + 2 * l4];
                af[mt][1] = *(const unsigned*)&As[(mrow + 8) * APH + kb + 2 * l4];
                af[mt][2] = *(const unsigned*)&As[mrow * APH + kb + 2 * l4 + 8];
                af[mt][3] = *(const unsigned*)&As[(mrow + 8) * APH + kb + 2 * l4 + 8];
            }
            unsigned bf[4][2];
#pragma unroll
            for (int nt = 0; nt < 4; nt++) {
                int ncol = nbase + nt * 8 + l28;
                bf[nt][0] = *(const unsigned*)&Bs[ncol * APH + kb + 2 * l4];
                bf[nt][1] = *(const unsigned*)&Bs[ncol * APH + kb + 2 * l4 + 8];
            }
#pragma unroll
            for (int mt = 0; mt < MT; mt++)
#pragma unroll
                for (int nt = 0; nt < 4; nt++)
                    mma_f16(acc[mt][nt], af[mt][0], af[mt][1], af[mt][2], af[mt][3],
                            bf[nt][0], bf[nt][1]);
        }
        __syncthreads();
    }

#pragma unroll
    for (int mt = 0; mt < MT; mt++) {
#pragma unroll
        for (int nt = 0; nt < 4; nt++) {
#pragma unroll
            for (int c = 0; c < 4; c++) {
                int gr = row0 + mbase + mt * 16 + l28 + ((c >= 2) ? 8 : 0);
                int gc = col0 + nbase + nt * 8 + l4 * 2 + (c & 1);
                if (gc >= N) continue;
                float v = alpha * acc[mt][nt][c];
                if (bias) v += bias[gc];
                if (res) v += res[(size_t)gr * ldc + gc];
                if (do_gelu) v = 0.5f * v * (1.f + erff(v * 0.70710678118654752f));
                size_t idx = (size_t)gr * ldc + gc;
                if (out_mode == 2)      ((__half*)C)[idx] = __float2half(v);
                else if (out_mode == 1) ((float*)C)[idx] = tf32f(v);
                else                    ((float*)C)[idx] = v;
            }
        }
    }
}

static inline HPtr3 oneh(const __half* b, void* c) {
    HPtr3 p; p.b0 = b; p.b1 = nullptr; p.b2 = nullptr;
    p.c0 = c; p.c1 = nullptr; p.c2 = nullptr; return p;
}

#define SM128 (4 * 128 * APH * 2)           // 40 KB
#define SM64  (2 * 128 * APH * 2 + 2 * 64 * APH * 2)   // 30 KB

// ================= fused causal flash attention (tf32, unchanged) ==========
#define FKP 68
#define FVP 72
#define FA_SMEM ((2 * 128 * FKP + 2 * 128 * FVP) * 4)

__global__ void __launch_bounds__(256, 1)
flash_kernel(const float* __restrict__ q, const float* __restrict__ k,
             const float* __restrict__ v, __half* __restrict__ o) {
    extern __shared__ __align__(16) float fsm[];
    float* Ksm[2] = { fsm, fsm + 128 * FKP };
    float* Vsm[2] = { fsm + 2 * 128 * FKP, fsm + 2 * 128 * FKP + 128 * FVP };
    unsigned uK[2], uV[2];
    uK[0] = (unsigned)__cvta_generic_to_shared(Ksm[0]);
    uK[1] = (unsigned)__cvta_generic_to_shared(Ksm[1]);
    uV[0] = (unsigned)__cvta_generic_to_shared(Vsm[0]);
    uV[1] = (unsigned)__cvta_generic_to_shared(Vsm[1]);

    int rb = 15 - blockIdx.x;
    int hb = blockIdx.y * HDIM;
    int row0 = rb * 128;

    int tid = threadIdx.x, lane = tid & 31, w = tid >> 5;
    int l4 = lane & 3, l28 = lane >> 2;
    int rl0 = w * 16 + l28;
    int rl1 = rl0 + 8;
    int grow0 = row0 + rl0, grow1 = row0 + rl1;

    unsigned qa[8][4];
#pragma unroll
    for (int c = 0; c < 8; c++) {
        qa[c][0] = __float_as_uint(0.125f * q[(size_t)grow0 * DD + hb + 8 * c + l4]);
        qa[c][1] = __float_as_uint(0.125f * q[(size_t)grow1 * DD + hb + 8 * c + l4]);
        qa[c][2] = __float_as_uint(0.125f * q[(size_t)grow0 * DD + hb + 8 * c + l4 + 4]);
        qa[c][3] = __float_as_uint(0.125f * q[(size_t)grow1 * DD + hb + 8 * c + l4 + 4]);
    }

    float oacc[8][4];
#pragma unroll
    for (int n2 = 0; n2 < 8; n2++)
#pragma unroll
        for (int c = 0; c < 4; c++) oacc[n2][c] = 0.f;
    float mA = -1e30f, mB = -1e30f, lA = 0.f, lB = 0.f;

    auto prefetch = [&](int j, int s) {
#pragma unroll
        for (int i = 0; i < 8; i++) {
            int lin = i * 256 + tid;
            int r = lin >> 4, f4 = lin & 15;
            const float* gk = k + (size_t)(j * 128 + r) * DD + hb + f4 * 4;
            const float* gv = v + (size_t)(j * 128 + r) * DD + hb + f4 * 4;
            cp16(uK[s] + (r * FKP + f4 * 4) * 4, gk, 16);
            cp16(uV[s] + (r * FVP + f4 * 4) * 4, gv, 16);
        }
        cp_commit();
    };

    int src0 = (lane & ~3) | (l4 >> 1);
    int src1 = src0 + 2;
    bool par = (l4 & 1) != 0;

    prefetch(0, 0);

    for (int j = 0; j <= rb; j++) {
        int s = j & 1;
        bool more = j < rb;
        if (more) prefetch(j + 1, s ^ 1);
        if (more) cp_wait<1>(); else cp_wait<0>();
        __syncthreads();

        float sacc[16][4];
#pragma unroll
        for (int t = 0; t < 16; t++)
#pragma unroll
            for (int c = 0; c < 4; c++) sacc[t][c] = 0.f;
#pragma unroll
        for (int c = 0; c < 8; c++) {
#pragma unroll
            for (int t = 0; t < 16; t++) {
                unsigned b0 = __float_as_uint(Ksm[s][(t * 8 + l28) * FKP + 8 * c + l4]);
                unsigned b1 = __float_as_uint(Ksm[s][(t * 8 + l28) * FKP + 8 * c + l4 + 4]);
                mma_tf32(sacc[t], qa[c][0], qa[c][1], qa[c][2], qa[c][3], b0, b1);
            }
        }

        if (j == rb) {
#pragma unroll
            for (int t = 0; t < 16; t++) {
                int cb = 8 * t + 2 * l4;
                if (cb     > rl0) sacc[t][0] = -1e30f;
                if (cb + 1 > rl0) sacc[t][1] = -1e30f;
                if (cb     > rl1) sacc[t][2] = -1e30f;
                if (cb + 1 > rl1) sacc[t][3] = -1e30f;
            }
        }

        float tmA = -1e30f, tmB = -1e30f;
#pragma unroll
        for (int t = 0; t < 16; t++) {
            tmA = fmaxf(tmA, fmaxf(sacc[t][0], sacc[t][1]));
            tmB = fmaxf(tmB, fmaxf(sacc[t][2], sacc[t][3]));
        }
        tmA = fmaxf(tmA, __shfl_xor_sync(0xffffffffu, tmA, 1));
        tmA = fmaxf(tmA, __shfl_xor_sync(0xffffffffu, tmA, 2));
        tmB = fmaxf(tmB, __shfl_xor_sync(0xffffffffu, tmB, 1));
        tmB = fmaxf(tmB, __shfl_xor_sync(0xffffffffu, tmB, 2));

        float mnA = fmaxf(mA, tmA), mnB = fmaxf(mB, tmB);
        float cA = __expf(mA - mnA), cB = __expf(mB - mnB);
        mA = mnA; mB = mnB;

        float tsA = 0.f, tsB = 0.f;
#pragma unroll
        for (int t = 0; t < 16; t++) {
            sacc[t][0] = __expf(sacc[t][0] - mA);
            sacc[t][1] = __expf(sacc[t][1] - mA);
            sacc[t][2] = __expf(sacc[t][2] - mB);
            sacc[t][3] = __expf(sacc[t][3] - mB);
            tsA += sacc[t][0] + sacc[t][1];
            tsB += sacc[t][2] + sacc[t][3];
        }
        tsA += __shfl_xor_sync(0xffffffffu, tsA, 1);
        tsA += __shfl_xor_sync(0xffffffffu, tsA, 2);
        tsB += __shfl_xor_sync(0xffffffffu, tsB, 1);
        tsB += __shfl_xor_sync(0xffffffffu, tsB, 2);
        lA = lA * cA + tsA;
        lB = lB * cB + tsB;

#pragma unroll
        for (int n2 = 0; n2 < 8; n2++) {
            oacc[n2][0] *= cA; oacc[n2][1] *= cA;
            oacc[n2][2] *= cB; oacc[n2][3] *= cB;
        }

#pragma unroll
        for (int kc = 0; kc < 16; kc++) {
            float v00 = __shfl_sync(0xffffffffu, sacc[kc][0], src0);
            float v01 = __shfl_sync(0xffffffffu, sacc[kc][1], src0);
            float v10 = __shfl_sync(0xffffffffu, sacc[kc][2], src0);
            float v11 = __shfl_sync(0xffffffffu, sacc[kc][3], src0);
            float w00 = __shfl_sync(0xffffffffu, sacc[kc][0], src1);
            float w01 = __shfl_sync(0xffffffffu, sacc[kc][1], src1);
            float w10 = __shfl_sync(0xffffffffu, sacc[kc][2], src1);
            float w11 = __shfl_sync(0xffffffffu, sacc[kc][3], src1);
            unsigned a0 = f2tf(par ? v01 : v00);
            unsigned a1 = f2tf(par ? v11 : v10);
            unsigned a2 = f2tf(par ? w01 : w00);
            unsigned a3 = f2tf(par ? w11 : w10);
#pragma unroll
            for (int n2 = 0; n2 < 8; n2++) {
                unsigned b0 = __float_as_uint(Vsm[s][(kc * 8 + l4) * FVP + n2 * 8 + l28]);
                unsigned b1 = __float_as_uint(Vsm[s][(kc * 8 + l4 + 4) * FVP + n2 * 8 + l28]);
                mma_tf32(oacc[n2], a0, a1, a2, a3, b0, b1);
            }
        }
        __syncthreads();
    }

    float iA = 1.f / lA, iB = 1.f / lB;
#pragma unroll
    for (int n2 = 0; n2 < 8; n2++) {
        *(__half2*)&o[(size_t)grow0 * DD + hb + n2 * 8 + 2 * l4] =
            __floats2half2_rn(oacc[n2][0] * iA, oacc[n2][1] * iA);
        *(__half2*)&o[(size_t)grow1 * DD + hb + n2 * 8 + 2 * l4] =
            __floats2half2_rn(oacc[n2][2] * iB, oacc[n2][3] * iB);
    }
}

// ---------------- host orchestration ----------------
extern "C" void kernel_launch(void* const* d_in, const int* in_sizes, int n_in,
                              void* d_out, int out_size) {
    const int*   ids  = (const int*)d_in[0];
    const float* emb  = (const float*)d_in[1];
    const float* Wq   = (const float*)d_in[2];
    const float* Wk   = (const float*)d_in[3];
    const float* Wv   = (const float*)d_in[4];
    const float* Wo   = (const float*)d_in[5];
    const float* ln1g = (const float*)d_in[6];
    const float* ln1b = (const float*)d_in[7];
    const float* ln2g = (const float*)d_in[8];
    const float* ln2b = (const float*)d_in[9];
    const float* W1   = (const float*)d_in[10];
    const float* b1   = (const float*)d_in[11];
    const float* W2   = (const float*)d_in[12];
    const float* b2   = (const float*)d_in[13];
    const float* lnfg = (const float*)d_in[14];
    const float* lnfb = (const float*)d_in[15];
    float* out = (float*)d_out;

    float *x, *q, *k, *v;
    __half *h, *mlp, *wqh, *wkh, *wvh, *woh, *w1h, *w2h, *embh;
    cudaGetSymbolAddress((void**)&x,    g_x);
    cudaGetSymbolAddress((void**)&h,    g_h);
    cudaGetSymbolAddress((void**)&q,    g_q);
    cudaGetSymbolAddress((void**)&k,    g_k);
    cudaGetSymbolAddress((void**)&v,    g_v);
    cudaGetSymbolAddress((void**)&mlp,  g_mlp);
    cudaGetSymbolAddress((void**)&wqh,  g_wqh);
    cudaGetSymbolAddress((void**)&wkh,  g_wkh);
    cudaGetSymbolAddress((void**)&wvh,  g_wvh);
    cudaGetSymbolAddress((void**)&woh,  g_woh);
    cudaGetSymbolAddress((void**)&w1h,  g_w1h);
    cudaGetSymbolAddress((void**)&w2h,  g_w2h);
    cudaGetSymbolAddress((void**)&embh, g_embh);

    cudaFuncSetAttribute(flash_kernel,
                         cudaFuncAttributeMaxDynamicSharedMemorySize, FA_SMEM);
    cudaFuncSetAttribute(hgemm_kernel<128>,
                         cudaFuncAttributeMaxDynamicSharedMemorySize, SM128);
    cudaFuncSetAttribute(hgemm_kernel<64>,
                         cudaFuncAttributeMaxDynamicSharedMemorySize, SM64);

    // per-call weight transposition / half conversion
    transph_kernel<<<dim3(32, 32, NL), 256>>>(Wq, wqh, DD, DD,
                                              (long long)DD * DD, (long long)DD * DD);
    transph_kernel<<<dim3(32, 32, NL), 256>>>(Wk, wkh, DD, DD,
                                              (long long)DD * DD, (long long)DD * DD);
    transph_kernel<<<dim3(32, 32, NL), 256>>>(Wv, wvh, DD, DD,
                                              (long long)DD * DD, (long long)DD * DD);
    transph_kernel<<<dim3(32, 32, NL), 256>>>(Wo, woh, DD, DD,
                                              (long long)DD * DD, (long long)DD * DD);
    transph_kernel<<<dim3(DMLP / 32, 32, NL), 256>>>(W1, w1h, DD, DMLP,
                                                     (long long)DD * DMLP, (long long)DD * DMLP);
    transph_kernel<<<dim3(32, DMLP / 32, NL), 256>>>(W2, w2h, DMLP, DD,
                                                     (long long)DMLP * DD, (long long)DMLP * DD);
    convh_kernel<<<4096, 256>>>((const float4*)emb, (uint2*)embh,
                                (long long)NV * DD / 4);

    embed_kernel<<<SS, 256>>>(ids, emb, x);

    for (int l = 0; l < NL; l++) {
        const size_t wofs = (size_t)l * DD * DD;
        layernorm_kernel<<<SS, 256>>>(x, ln1g + l * DD, ln1b + l * DD, h);

        // fused QKV (fp32 out tf32-rounded; q,k re-rounded by rope)
        {
            HPtr3 p;
            p.b0 = wqh + wofs; p.b1 = wkh + wofs; p.b2 = wvh + wofs;
            p.c0 = q; p.c1 = k; p.c2 = v;
            hgemm_kernel<128><<<dim3(SS / 128, DD / 128, 3), 256, SM128>>>(
                h, DD, 0, p, DD, DD, 0,
                SS, DD, DD, 1.f, nullptr, nullptr, 0, 1, 1);
        }

        rope_kernel<<<(SS * NH * 32 + 255) / 256, 256>>>(q, k);

        flash_kernel<<<dim3(SS / 128, NH), 256, FA_SMEM>>>(q, k, v, h);

        // x = x + attn @ Wo
        hgemm_kernel<64><<<dim3(SS / 128, DD / 64, 1), 256, SM64>>>(
            h, DD, 0, oneh(woh + wofs, x), DD, DD, 0,
            SS, DD, DD, 1.f, nullptr, x, 0, 0, 0);

        layernorm_kernel<<<SS, 256>>>(x, ln2g + l * DD, ln2b + l * DD, h);

        // mlp = gelu(h @ W1 + b1) -> half
        hgemm_kernel<128><<<dim3(SS / 128, DMLP / 128, 1), 256, SM128>>>(
            h, DD, 0, oneh(w1h + (size_t)l * DD * DMLP, mlp), DD, DMLP, 0,
            SS, DMLP, DD, 1.f, b1 + (size_t)l * DMLP, nullptr, 1, 0, 2);

        // x = x + mlp @ W2 + b2
        hgemm_kernel<64><<<dim3(SS / 128, DD / 64, 1), 256, SM64>>>(
            mlp, DMLP, 0, oneh(w2h + (size_t)l * DD * DMLP, x), DMLP, DD, 0,
            SS, DD, DMLP, 1.f, b2 + (size_t)l * DD, x, 0, 0, 0);
    }

    layernorm_kernel<<<SS, 256>>>(x, lnfg, lnfb, h);

    // logits = h @ embh^T
    hgemm_kernel<128><<<dim3(SS / 128, (NV + 127) / 128, 1), 256, SM128>>>(
        h, DD, 0, oneh(embh, out), DD, NV, 0,
        SS, NV, DD, 1.f, nullptr, nullptr, 0, 0, 0);
}

// round 13
// speedup vs baseline: 1.5640x; 1.0182x over previous
#include <cuda_runtime.h>
#include <cuda_fp16.h>
#include <math.h>
#include <stdint.h>

#define SS   2048
#define DD   1024
#define NL   4
#define NH   16
#define HDIM 64
#define NV   50257
#define DMLP 4096

// ---------------- scratch ----------------
__device__ float  g_x[SS * DD];
__device__ __half g_h[SS * DD];
__device__ float  g_q[SS * DD];
__device__ float  g_k[SS * DD];
__device__ float  g_v[SS * DD];
__device__ __half g_mlp[SS * DMLP];
// half transposed weights [l][n][k] and half emb [n][k]
__device__ __half g_wqh[(size_t)NL * DD * DD];
__device__ __half g_wkh[(size_t)NL * DD * DD];
__device__ __half g_wvh[(size_t)NL * DD * DD];
__device__ __half g_woh[(size_t)NL * DD * DD];
__device__ __half g_w1h[(size_t)NL * DMLP * DD];
__device__ __half g_w2h[(size_t)NL * DD * DMLP];
__device__ __half g_embh[(size_t)NV * DD];

// ---------------- helpers ----------------
__device__ __forceinline__ unsigned f2tf(float f) {
    unsigned u;
    asm("cvt.rna.tf32.f32 %0, %1;" : "=r"(u) : "f"(f));
    return u;
}
__device__ __forceinline__ float tf32f(float f) {
    return __uint_as_float(f2tf(f));
}

// ---------------- weight transpose + half convert: W[K][N] -> Wt[N][K] -----
__global__ void transph_kernel(const float* __restrict__ W, __half* __restrict__ Wt,
                               int K, int N, long long wstride, long long tstride) {
    __shared__ float tile[32][33];
    const float* Wz = W + (size_t)blockIdx.z * wstride;
    __half* Tz = Wt + (size_t)blockIdx.z * tstride;
    int n0 = blockIdx.x * 32, k0 = blockIdx.y * 32;
    int tx = threadIdx.x & 31, ty = threadIdx.x >> 5;
#pragma unroll
    for (int i = 0; i < 4; i++)
        tile[ty + i * 8][tx] = Wz[(size_t)(k0 + ty + i * 8) * N + n0 + tx];
    __syncthreads();
#pragma unroll
    for (int i = 0; i < 4; i++)
        Tz[(size_t)(n0 + ty + i * 8) * K + k0 + tx] = __float2half(tile[tx][ty + i * 8]);
}

// ---------------- straight half convert (emb) ----------------
__global__ void convh_kernel(const float4* __restrict__ in,
                             uint2* __restrict__ out, long long n4) {
    long long i = blockIdx.x * (long long)blockDim.x + threadIdx.x;
    long long stride = (long long)gridDim.x * blockDim.x;
    for (; i < n4; i += stride) {
        float4 t = in[i];
        unsigned lo, hi;
        asm("cvt.rn.f16x2.f32 %0, %1, %2;" : "=r"(lo) : "f"(t.y), "f"(t.x));
        asm("cvt.rn.f16x2.f32 %0, %1, %2;" : "=r"(hi) : "f"(t.w), "f"(t.z));
        out[i] = make_uint2(lo, hi);
    }
}

// ---------------- embedding gather ----------------
__global__ void embed_kernel(const int* __restrict__ ids,
                             const float* __restrict__ emb,
                             float* __restrict__ x) {
    int t = blockIdx.x;
    int id = ids[t];
    if (id < 0) id = 0;
    if (id >= NV) id = NV - 1;
    const float* src = emb + (size_t)id * DD;
    float* dst = x + (size_t)t * DD;
    for (int d = threadIdx.x; d < DD; d += blockDim.x) dst[d] = src[d];
}

// ---------------- layernorm (half out) ----------------
__global__ void layernorm_kernel(const float* __restrict__ x,
                                 const float* __restrict__ g,
                                 const float* __restrict__ b,
                                 __half* __restrict__ out) {
    __shared__ float red[256];
    int row = blockIdx.x;
    const float* xr = x + (size_t)row * DD;
    float s = 0.f;
    for (int d = threadIdx.x; d < DD; d += 256) s += xr[d];
    red[threadIdx.x] = s;
    __syncthreads();
    for (int o = 128; o > 0; o >>= 1) {
        if (threadIdx.x < o) red[threadIdx.x] += red[threadIdx.x + o];
        __syncthreads();
    }
    float mean = red[0] * (1.f / DD);
    __syncthreads();
    float v = 0.f;
    for (int d = threadIdx.x; d < DD; d += 256) {
        float t = xr[d] - mean;
        v += t * t;
    }
    red[threadIdx.x] = v;
    __syncthreads();
    for (int o = 128; o > 0; o >>= 1) {
        if (threadIdx.x < o) red[threadIdx.x] += red[threadIdx.x + o];
        __syncthreads();
    }
    float inv = rsqrtf(red[0] * (1.f / DD) + 1e-5f);
    __half* orow = out + (size_t)row * DD;
    for (int d = threadIdx.x; d < DD; d += 256)
        orow[d] = __float2half((xr[d] - mean) * inv * g[d] + b[d]);
}

// ---------------- RoPE (tf32-rounded fp32 for flash) ----------------
__global__ void rope_kernel(float* __restrict__ q, float* __restrict__ k) {
    int idx = blockIdx.x * blockDim.x + threadIdx.x;
    int i = idx & 31;
    int rest = idx >> 5;
    int h = rest & (NH - 1);
    int t = rest >> 4;
    if (t >= SS) return;
    float inv_freq = powf(10000.f, -(float)i / 32.f);
    float ang = (float)t * inv_freq;
    float c = cosf(ang), s = sinf(ang);
    size_t base = (size_t)t * DD + h * HDIM;
    float x1 = q[base + i], x2 = q[base + i + 32];
    q[base + i]      = tf32f(x1 * c - x2 * s);
    q[base + i + 32] = tf32f(x2 * c + x1 * s);
    float y1 = k[base + i], y2 = k[base + i + 32];
    k[base + i]      = tf32f(y1 * c - y2 * s);
    k[base + i + 32] = tf32f(y2 * c + y1 * s);
}

// ---------------- PTX helpers ----------------
__device__ __forceinline__ void cp16(unsigned dst, const void* src, int bytes) {
    asm volatile("cp.async.cg.shared.global [%0], [%1], 16, %2;"
                 :: "r"(dst), "l"(src), "r"(bytes));
}
__device__ __forceinline__ void cp_commit() {
    asm volatile("cp.async.commit_group;");
}
template <int N>
__device__ __forceinline__ void cp_wait() {
    asm volatile("cp.async.wait_group %0;" :: "n"(N));
}
__device__ __forceinline__ void mma_tf32(float c[4], unsigned a0, unsigned a1,
                                         unsigned a2, unsigned a3,
                                         unsigned b0, unsigned b1) {
    asm volatile(
        "mma.sync.aligned.m16n8k8.row.col.f32.tf32.tf32.f32 "
        "{%0,%1,%2,%3}, {%4,%5,%6,%7}, {%8,%9}, {%0,%1,%2,%3};"
        : "+f"(c[0]), "+f"(c[1]), "+f"(c[2]), "+f"(c[3])
        : "r"(a0), "r"(a1), "r"(a2), "r"(a3), "r"(b0), "r"(b1));
}
__device__ __forceinline__ void mma_f16(float c[4], unsigned a0, unsigned a1,
                                        unsigned a2, unsigned a3,
                                        unsigned b0, unsigned b1) {
    asm volatile(
        "mma.sync.aligned.m16n8k16.row.col.f32.f16.f16.f32 "
        "{%0,%1,%2,%3}, {%4,%5,%6,%7}, {%8,%9}, {%0,%1,%2,%3};"
        : "+f"(c[0]), "+f"(c[1]), "+f"(c[2]), "+f"(c[3])
        : "r"(a0), "r"(a1), "r"(a2), "r"(a3), "r"(b0), "r"(b1));
}

// ================= all-half GEMM: BK=32, 3-stage cp.async ring =============
#define BKT2 32
#define APH  40

struct HPtr3 {
    const __half* b0; const __half* b1; const __half* b2;
    void* c0; void* c1; void* c2;
};

template <int BN>
__global__ void __launch_bounds__(256, 2)
hgemm_kernel(const __half* __restrict__ A, int lda, long long strideA,
             HPtr3 p, int ldb,
             int ldc, long long strideC,
             int M, int N, int K, float alpha,
             const float* __restrict__ bias,
             const float* __restrict__ res,
             int do_gelu, int multiB, int out_mode) {  // 0 f32, 1 f32+tf32, 2 f16
    const int MT  = (BN == 128) ? 4 : 2;
    const int AST = 128 * APH;      // halves per A stage
    const int BST = BN * APH;       // halves per B stage
    const int STG = AST + BST;      // halves per stage (A then B)

    extern __shared__ __align__(16) __half dsm[];

    int z = blockIdx.z;
    const __half* B;
    void* C;
    if (multiB) {
        B = (z == 0) ? p.b0 : (z == 1) ? p.b1 : p.b2;
        C = (z == 0) ? p.c0 : (z == 1) ? p.c1 : p.c2;
    } else {
        B = p.b0;
        C = (out_mode == 2) ? (void*)((__half*)p.c0 + (size_t)z * strideC)
                            : (void*)((float*)p.c0 + (size_t)z * strideC);
        if (res) res += (size_t)z * strideC;
    }
    A += (size_t)z * strideA;

    int row0 = blockIdx.x * 128;
    int col0 = blockIdx.y * BN;
    int nk = K / BKT2;

    int tid = threadIdx.x;
    int lane = tid & 31, warp = tid >> 5;
    int l4 = lane & 3, l28 = lane >> 2;
    int mbase, nbase;
    if (BN == 128) { mbase = (warp >> 2) * 64; nbase = (warp & 3) * 32; }
    else           { mbase = (warp >> 1) * 32; nbase = (warp & 1) * 32; }

    unsigned sbase = (unsigned)__cvta_generic_to_shared(dsm);

    float acc[MT][4][4];
#pragma unroll
    for (int mt = 0; mt < MT; mt++)
#pragma unroll
        for (int nt = 0; nt < 4; nt++)
#pragma unroll
            for (int c = 0; c < 4; c++) acc[mt][nt][c] = 0.f;

    auto prefetch = [&](int s, int k0) {
        unsigned sA = sbase + s * STG * 2;
        unsigned sB = sA + AST * 2;
#pragma unroll
        for (int i = 0; i < 2; i++) {
            int lin = i * 256 + tid;
            int m = lin >> 2, f8 = lin & 3;
            cp16(sA + (m * APH + f8 * 8) * 2,
                 A + (size_t)(row0 + m) * lda + k0 + f8 * 8, 16);
        }
#pragma unroll
        for (int i = 0; i < BN / 64; i++) {
            int lin = i * 256 + tid;
            int n = lin >> 2, f8 = lin & 3;
            int gn = col0 + n;
            cp16(sB + (n * APH + f8 * 8) * 2,
                 B + (size_t)gn * ldb + k0 + f8 * 8, (gn < N) ? 16 : 0);
        }
        cp_commit();
    };

    prefetch(0, 0);
    if (nk > 1) prefetch(1, BKT2);

    int cur = 0;
    for (int ks = 0; ks < nk; ks++) {
        if (ks + 2 < nk) prefetch((cur + 2) % 3, (ks + 2) * BKT2);

        // group ks was issued 2 iterations ago; keep newer groups in flight
        if (ks + 2 < nk)      cp_wait<2>();
        else if (ks + 1 < nk) cp_wait<1>();
        else                  cp_wait<0>();
        __syncthreads();

        const __half* As = dsm + cur * STG;
        const __half* Bs = As + AST;

#pragma unroll
        for (int kb = 0; kb < BKT2; kb += 16) {
            unsigned af[MT][4];
#pragma unroll
            for (int mt = 0; mt < MT; mt++) {
                int mrow = mbase + mt * 16 + l28;
                af[mt][0] = *(const unsigned*)&As[mrow * APH + kb + 2 * l4];
                af[mt][1] = *(const unsigned*)&As[(mrow + 8) * APH + kb + 2 * l4];
                af[mt][2] = *(const unsigned*)&As[mrow * APH + kb + 2 * l4 + 8];
                af[mt][3] = *(const unsigned*)&As[(mrow + 8) * APH + kb + 2 * l4 + 8];
            }
            unsigned bf[4][2];
#pragma unroll
            for (int nt = 0; nt < 4; nt++) {
                int ncol = nbase + nt * 8 + l28;
                bf[nt][0] = *(const unsigned*)&Bs[ncol * APH + kb + 2 * l4];
                bf[nt][1] = *(const unsigned*)&Bs[ncol * APH + kb + 2 * l4 + 8];
            }
#pragma unroll
            for (int mt = 0; mt < MT; mt++)
#pragma unroll
                for (int nt = 0; nt < 4; nt++)
                    mma_f16(acc[mt][nt], af[mt][0], af[mt][1], af[mt][2], af[mt][3],
                            bf[nt][0], bf[nt][1]);
        }
        __syncthreads();
        cur = (cur + 1) % 3;
    }

#pragma unroll
    for (int mt = 0; mt < MT; mt++) {
#pragma unroll
        for (int nt = 0; nt < 4; nt++) {
#pragma unroll
            for (int c = 0; c < 4; c++) {
                int gr = row0 + mbase + mt * 16 + l28 + ((c >= 2) ? 8 : 0);
                int gc = col0 + nbase + nt * 8 + l4 * 2 + (c & 1);
                if (gc >= N) continue;
                float v = alpha * acc[mt][nt][c];
                if (bias) v += bias[gc];
                if (res) v += res[(size_t)gr * ldc + gc];
                if (do_gelu) v = 0.5f * v * (1.f + erff(v * 0.70710678118654752f));
                size_t idx = (size_t)gr * ldc + gc;
                if (out_mode == 2)      ((__half*)C)[idx] = __float2half(v);
                else if (out_mode == 1) ((float*)C)[idx] = tf32f(v);
                else                    ((float*)C)[idx] = v;
            }
        }
    }
}

static inline HPtr3 oneh(const __half* b, void* c) {
    HPtr3 p; p.b0 = b; p.b1 = nullptr; p.b2 = nullptr;
    p.c0 = c; p.c1 = nullptr; p.c2 = nullptr; return p;
}

#define SM128 (3 * (128 + 128) * APH * 2)   // 61440 B
#define SM64  (3 * (128 + 64)  * APH * 2)   // 46080 B

// ================= fused causal flash attention (tf32, unchanged) ==========
#define FKP 68
#define FVP 72
#define FA_SMEM ((2 * 128 * FKP + 2 * 128 * FVP) * 4)

__global__ void __launch_bounds__(256, 1)
flash_kernel(const float* __restrict__ q, const float* __restrict__ k,
             const float* __restrict__ v, __half* __restrict__ o) {
    extern __shared__ __align__(16) float fsm[];
    float* Ksm[2] = { fsm, fsm + 128 * FKP };
    float* Vsm[2] = { fsm + 2 * 128 * FKP, fsm + 2 * 128 * FKP + 128 * FVP };
    unsigned uK[2], uV[2];
    uK[0] = (unsigned)__cvta_generic_to_shared(Ksm[0]);
    uK[1] = (unsigned)__cvta_generic_to_shared(Ksm[1]);
    uV[0] = (unsigned)__cvta_generic_to_shared(Vsm[0]);
    uV[1] = (unsigned)__cvta_generic_to_shared(Vsm[1]);

    int rb = 15 - blockIdx.x;
    int hb = blockIdx.y * HDIM;
    int row0 = rb * 128;

    int tid = threadIdx.x, lane = tid & 31, w = tid >> 5;
    int l4 = lane & 3, l28 = lane >> 2;
    int rl0 = w * 16 + l28;
    int rl1 = rl0 + 8;
    int grow0 = row0 + rl0, grow1 = row0 + rl1;

    unsigned qa[8][4];
#pragma unroll
    for (int c = 0; c < 8; c++) {
        qa[c][0] = __float_as_uint(0.125f * q[(size_t)grow0 * DD + hb + 8 * c + l4]);
        qa[c][1] = __float_as_uint(0.125f * q[(size_t)grow1 * DD + hb + 8 * c + l4]);
        qa[c][2] = __float_as_uint(0.125f * q[(size_t)grow0 * DD + hb + 8 * c + l4 + 4]);
        qa[c][3] = __float_as_uint(0.125f * q[(size_t)grow1 * DD + hb + 8 * c + l4 + 4]);
    }

    float oacc[8][4];
#pragma unroll
    for (int n2 = 0; n2 < 8; n2++)
#pragma unroll
        for (int c = 0; c < 4; c++) oacc[n2][c] = 0.f;
    float mA = -1e30f, mB = -1e30f, lA = 0.f, lB = 0.f;

    auto prefetch = [&](int j, int s) {
#pragma unroll
        for (int i = 0; i < 8; i++) {
            int lin = i * 256 + tid;
            int r = lin >> 4, f4 = lin & 15;
            const float* gk = k + (size_t)(j * 128 + r) * DD + hb + f4 * 4;
            const float* gv = v + (size_t)(j * 128 + r) * DD + hb + f4 * 4;
            cp16(uK[s] + (r * FKP + f4 * 4) * 4, gk, 16);
            cp16(uV[s] + (r * FVP + f4 * 4) * 4, gv, 16);
        }
        cp_commit();
    };

    int src0 = (lane & ~3) | (l4 >> 1);
    int src1 = src0 + 2;
    bool par = (l4 & 1) != 0;

    prefetch(0, 0);

    for (int j = 0; j <= rb; j++) {
        int s = j & 1;
        bool more = j < rb;
        if (more) prefetch(j + 1, s ^ 1);
        if (more) cp_wait<1>(); else cp_wait<0>();
        __syncthreads();

        float sacc[16][4];
#pragma unroll
        for (int t = 0; t < 16; t++)
#pragma unroll
            for (int c = 0; c < 4; c++) sacc[t][c] = 0.f;
#pragma unroll
        for (int c = 0; c < 8; c++) {
#pragma unroll
            for (int t = 0; t < 16; t++) {
                unsigned b0 = __float_as_uint(Ksm[s][(t * 8 + l28) * FKP + 8 * c + l4]);
                unsigned b1 = __float_as_uint(Ksm[s][(t * 8 + l28) * FKP + 8 * c + l4 + 4]);
                mma_tf32(sacc[t], qa[c][0], qa[c][1], qa[c][2], qa[c][3], b0, b1);
            }
        }

        if (j == rb) {
#pragma unroll
            for (int t = 0; t < 16; t++) {
                int cb = 8 * t + 2 * l4;
                if (cb     > rl0) sacc[t][0] = -1e30f;
                if (cb + 1 > rl0) sacc[t][1] = -1e30f;
                if (cb     > rl1) sacc[t][2] = -1e30f;
                if (cb + 1 > rl1) sacc[t][3] = -1e30f;
            }
        }

        float tmA = -1e30f, tmB = -1e30f;
#pragma unroll
        for (int t = 0; t < 16; t++) {
            tmA = fmaxf(tmA, fmaxf(sacc[t][0], sacc[t][1]));
            tmB = fmaxf(tmB, fmaxf(sacc[t][2], sacc[t][3]));
        }
        tmA = fmaxf(tmA, __shfl_xor_sync(0xffffffffu, tmA, 1));
        tmA = fmaxf(tmA, __shfl_xor_sync(0xffffffffu, tmA, 2));
        tmB = fmaxf(tmB, __shfl_xor_sync(0xffffffffu, tmB, 1));
        tmB = fmaxf(tmB, __shfl_xor_sync(0xffffffffu, tmB, 2));

        float mnA = fmaxf(mA, tmA), mnB = fmaxf(mB, tmB);
        float cA = __expf(mA - mnA), cB = __expf(mB - mnB);
        mA = mnA; mB = mnB;

        float tsA = 0.f, tsB = 0.f;
#pragma unroll
        for (int t = 0; t < 16; t++) {
            sacc[t][0] = __expf(sacc[t][0] - mA);
            sacc[t][1] = __expf(sacc[t][1] - mA);
            sacc[t][2] = __expf(sacc[t][2] - mB);
            sacc[t][3] = __expf(sacc[t][3] - mB);
            tsA += sacc[t][0] + sacc[t][1];
            tsB += sacc[t][2] + sacc[t][3];
        }
        tsA += __shfl_xor_sync(0xffffffffu, tsA, 1);
        tsA += __shfl_xor_sync(0xffffffffu, tsA, 2);
        tsB += __shfl_xor_sync(0xffffffffu, tsB, 1);
        tsB += __shfl_xor_sync(0xffffffffu, tsB, 2);
        lA = lA * cA + tsA;
        lB = lB * cB + tsB;

#pragma unroll
        for (int n2 = 0; n2 < 8; n2++) {
            oacc[n2][0] *= cA; oacc[n2][1] *= cA;
            oacc[n2][2] *= cB; oacc[n2][3] *= cB;
        }

#pragma unroll
        for (int kc = 0; kc < 16; kc++) {
            float v00 = __shfl_sync(0xffffffffu, sacc[kc][0], src0);
            float v01 = __shfl_sync(0xffffffffu, sacc[kc][1], src0);
            float v10 = __shfl_sync(0xffffffffu, sacc[kc][2], src0);
            float v11 = __shfl_sync(0xffffffffu, sacc[kc][3], src0);
            float w00 = __shfl_sync(0xffffffffu, sacc[kc][0], src1);
            float w01 = __shfl_sync(0xffffffffu, sacc[kc][1], src1);
            float w10 = __shfl_sync(0xffffffffu, sacc[kc][2], src1);
            float w11 = __shfl_sync(0xffffffffu, sacc[kc][3], src1);
            unsigned a0 = f2tf(par ? v01 : v00);
            unsigned a1 = f2tf(par ? v11 : v10);
            unsigned a2 = f2tf(par ? w01 : w00);
            unsigned a3 = f2tf(par ? w11 : w10);
#pragma unroll
            for (int n2 = 0; n2 < 8; n2++) {
                unsigned b0 = __float_as_uint(Vsm[s][(kc * 8 + l4) * FVP + n2 * 8 + l28]);
                unsigned b1 = __float_as_uint(Vsm[s][(kc * 8 + l4 + 4) * FVP + n2 * 8 + l28]);
                mma_tf32(oacc[n2], a0, a1, a2, a3, b0, b1);
            }
        }
        __syncthreads();
    }

    float iA = 1.f / lA, iB = 1.f / lB;
#pragma unroll
    for (int n2 = 0; n2 < 8; n2++) {
        *(__half2*)&o[(size_t)grow0 * DD + hb + n2 * 8 + 2 * l4] =
            __floats2half2_rn(oacc[n2][0] * iA, oacc[n2][1] * iA);
        *(__half2*)&o[(size_t)grow1 * DD + hb + n2 * 8 + 2 * l4] =
            __floats2half2_rn(oacc[n2][2] * iB, oacc[n2][3] * iB);
    }
}

// ---------------- host orchestration ----------------
extern "C" void kernel_launch(void* const* d_in, const int* in_sizes, int n_in,
                              void* d_out, int out_size) {
    const int*   ids  = (const int*)d_in[0];
    const float* emb  = (const float*)d_in[1];
    const float* Wq   = (const float*)d_in[2];
    const float* Wk   = (const float*)d_in[3];
    const float* Wv   = (const float*)d_in[4];
    const float* Wo   = (const float*)d_in[5];
    const float* ln1g = (const float*)d_in[6];
    const float* ln1b = (const float*)d_in[7];
    const float* ln2g = (const float*)d_in[8];
    const float* ln2b = (const float*)d_in[9];
    const float* W1   = (const float*)d_in[10];
    const float* b1   = (const float*)d_in[11];
    const float* W2   = (const float*)d_in[12];
    const float* b2   = (const float*)d_in[13];
    const float* lnfg = (const float*)d_in[14];
    const float* lnfb = (const float*)d_in[15];
    float* out = (float*)d_out;

    float *x, *q, *k, *v;
    __half *h, *mlp, *wqh, *wkh, *wvh, *woh, *w1h, *w2h, *embh;
    cudaGetSymbolAddress((void**)&x,    g_x);
    cudaGetSymbolAddress((void**)&h,    g_h);
    cudaGetSymbolAddress((void**)&q,    g_q);
    cudaGetSymbolAddress((void**)&k,    g_k);
    cudaGetSymbolAddress((void**)&v,    g_v);
    cudaGetSymbolAddress((void**)&mlp,  g_mlp);
    cudaGetSymbolAddress((void**)&wqh,  g_wqh);
    cudaGetSymbolAddress((void**)&wkh,  g_wkh);
    cudaGetSymbolAddress((void**)&wvh,  g_wvh);
    cudaGetSymbolAddress((void**)&woh,  g_woh);
    cudaGetSymbolAddress((void**)&w1h,  g_w1h);
    cudaGetSymbolAddress((void**)&w2h,  g_w2h);
    cudaGetSymbolAddress((void**)&embh, g_embh);

    cudaFuncSetAttribute(flash_kernel,
                         cudaFuncAttributeMaxDynamicSharedMemorySize, FA_SMEM);
    cudaFuncSetAttribute(hgemm_kernel<128>,
                         cudaFuncAttributeMaxDynamicSharedMemorySize, SM128);
    cudaFuncSetAttribute(hgemm_kernel<64>,
                         cudaFuncAttributeMaxDynamicSharedMemorySize, SM64);

    // per-call weight transposition / half conversion
    transph_kernel<<<dim3(32, 32, NL), 256>>>(Wq, wqh, DD, DD,
                                              (long long)DD * DD, (long long)DD * DD);
    transph_kernel<<<dim3(32, 32, NL), 256>>>(Wk, wkh, DD, DD,
                                              (long long)DD * DD, (long long)DD * DD);
    transph_kernel<<<dim3(32, 32, NL), 256>>>(Wv, wvh, DD, DD,
                                              (long long)DD * DD, (long long)DD * DD);
    transph_kernel<<<dim3(32, 32, NL), 256>>>(Wo, woh, DD, DD,
                                              (long long)DD * DD, (long long)DD * DD);
    transph_kernel<<<dim3(DMLP / 32, 32, NL), 256>>>(W1, w1h, DD, DMLP,
                                                     (long long)DD * DMLP, (long long)DD * DMLP);
    transph_kernel<<<dim3(32, DMLP / 32, NL), 256>>>(W2, w2h, DMLP, DD,
                                                     (long long)DMLP * DD, (long long)DMLP * DD);
    convh_kernel<<<4096, 256>>>((const float4*)emb, (uint2*)embh,
                                (long long)NV * DD / 4);

    embed_kernel<<<SS, 256>>>(ids, emb, x);

    for (int l = 0; l < NL; l++) {
        const size_t wofs = (size_t)l * DD * DD;
        layernorm_kernel<<<SS, 256>>>(x, ln1g + l * DD, ln1b + l * DD, h);

        // fused QKV (fp32 out tf32-rounded; q,k re-rounded by rope)
        {
            HPtr3 p;
            p.b0 = wqh + wofs; p.b1 = wkh + wofs; p.b2 = wvh + wofs;
            p.c0 = q; p.c1 = k; p.c2 = v;
            hgemm_kernel<128><<<dim3(SS / 128, DD / 128, 3), 256, SM128>>>(
                h, DD, 0, p, DD, DD, 0,
                SS, DD, DD, 1.f, nullptr, nullptr, 0, 1, 1);
        }

        rope_kernel<<<(SS * NH * 32 + 255) / 256, 256>>>(q, k);

        flash_kernel<<<dim3(SS / 128, NH), 256, FA_SMEM>>>(q, k, v, h);

        // x = x + attn @ Wo
        hgemm_kernel<64><<<dim3(SS / 128, DD / 64, 1), 256, SM64>>>(
            h, DD, 0, oneh(woh + wofs, x), DD, DD, 0,
            SS, DD, DD, 1.f, nullptr, x, 0, 0, 0);

        layernorm_kernel<<<SS, 256>>>(x, ln2g + l * DD, ln2b + l * DD, h);

        // mlp = gelu(h @ W1 + b1) -> half
        hgemm_kernel<128><<<dim3(SS / 128, DMLP / 128, 1), 256, SM128>>>(
            h, DD, 0, oneh(w1h + (size_t)l * DD * DMLP, mlp), DD, DMLP, 0,
            SS, DMLP, DD, 1.f, b1 + (size_t)l * DMLP, nullptr, 1, 0, 2);

        // x = x + mlp @ W2 + b2
        hgemm_kernel<64><<<dim3(SS / 128, DD / 64, 1), 256, SM64>>>(
            mlp, DMLP, 0, oneh(w2h + (size_t)l * DD * DMLP, x), DMLP, DD, 0,
            SS, DD, DMLP, 1.f, b2 + (size_t)l * DD, x, 0, 0, 0);
    }

    layernorm_kernel<<<SS, 256>>>(x, lnfg, lnfb, h);

    // logits = h @ embh^T
    hgemm_kernel<128><<<dim3(SS / 128, (NV + 127) / 128, 1), 256, SM128>>>(
        h, DD, 0, oneh(embh, out), DD, NV, 0,
        SS, NV, DD, 1.f, nullptr, nullptr, 0, 0, 0);
}

// round 14
// speedup vs baseline: 1.6893x; 1.0801x over previous
#include <cuda_runtime.h>
#include <cuda_fp16.h>
#include <math.h>
#include <stdint.h>

#define SS   2048
#define DD   1024
#define NL   4
#define NH   16
#define HDIM 64
#define NV   50257
#define DMLP 4096

// ---------------- scratch ----------------
__device__ float  g_x[SS * DD];
__device__ __half g_h[SS * DD];
__device__ __half g_q[SS * DD];
__device__ __half g_k[SS * DD];
__device__ __half g_v[SS * DD];
__device__ __half g_mlp[SS * DMLP];
// half transposed weights [l][n][k] and half emb [n][k]
__device__ __half g_wqh[(size_t)NL * DD * DD];
__device__ __half g_wkh[(size_t)NL * DD * DD];
__device__ __half g_wvh[(size_t)NL * DD * DD];
__device__ __half g_woh[(size_t)NL * DD * DD];
__device__ __half g_w1h[(size_t)NL * DMLP * DD];
__device__ __half g_w2h[(size_t)NL * DD * DMLP];
__device__ __half g_embh[(size_t)NV * DD];

// ---------------- helpers ----------------
__device__ __forceinline__ unsigned f2tf(float f) {
    unsigned u;
    asm("cvt.rna.tf32.f32 %0, %1;" : "=r"(u) : "f"(f));
    return u;
}
__device__ __forceinline__ float tf32f(float f) {
    return __uint_as_float(f2tf(f));
}
__device__ __forceinline__ unsigned packh(float a, float b) {
    unsigned d;
    asm("cvt.rn.f16x2.f32 %0, %1, %2;" : "=r"(d) : "f"(b), "f"(a));
    return d;
}

// ---------------- weight transpose + half convert: W[K][N] -> Wt[N][K] -----
__global__ void transph_kernel(const float* __restrict__ W, __half* __restrict__ Wt,
                               int K, int N, long long wstride, long long tstride) {
    __shared__ float tile[32][33];
    const float* Wz = W + (size_t)blockIdx.z * wstride;
    __half* Tz = Wt + (size_t)blockIdx.z * tstride;
    int n0 = blockIdx.x * 32, k0 = blockIdx.y * 32;
    int tx = threadIdx.x & 31, ty = threadIdx.x >> 5;
#pragma unroll
    for (int i = 0; i < 4; i++)
        tile[ty + i * 8][tx] = Wz[(size_t)(k0 + ty + i * 8) * N + n0 + tx];
    __syncthreads();
#pragma unroll
    for (int i = 0; i < 4; i++)
        Tz[(size_t)(n0 + ty + i * 8) * K + k0 + tx] = __float2half(tile[tx][ty + i * 8]);
}

// ---------------- straight half convert (emb) ----------------
__global__ void convh_kernel(const float4* __restrict__ in,
                             uint2* __restrict__ out, long long n4) {
    long long i = blockIdx.x * (long long)blockDim.x + threadIdx.x;
    long long stride = (long long)gridDim.x * blockDim.x;
    for (; i < n4; i += stride) {
        float4 t = in[i];
        unsigned lo, hi;
        asm("cvt.rn.f16x2.f32 %0, %1, %2;" : "=r"(lo) : "f"(t.y), "f"(t.x));
        asm("cvt.rn.f16x2.f32 %0, %1, %2;" : "=r"(hi) : "f"(t.w), "f"(t.z));
        out[i] = make_uint2(lo, hi);
    }
}

// ---------------- embedding gather ----------------
__global__ void embed_kernel(const int* __restrict__ ids,
                             const float* __restrict__ emb,
                             float* __restrict__ x) {
    int t = blockIdx.x;
    int id = ids[t];
    if (id < 0) id = 0;
    if (id >= NV) id = NV - 1;
    const float* src = emb + (size_t)id * DD;
    float* dst = x + (size_t)t * DD;
    for (int d = threadIdx.x; d < DD; d += blockDim.x) dst[d] = src[d];
}

// ---------------- layernorm (half out) ----------------
__global__ void layernorm_kernel(const float* __restrict__ x,
                                 const float* __restrict__ g,
                                 const float* __restrict__ b,
                                 __half* __restrict__ out) {
    __shared__ float red[256];
    int row = blockIdx.x;
    const float* xr = x + (size_t)row * DD;
    float s = 0.f;
    for (int d = threadIdx.x; d < DD; d += 256) s += xr[d];
    red[threadIdx.x] = s;
    __syncthreads();
    for (int o = 128; o > 0; o >>= 1) {
        if (threadIdx.x < o) red[threadIdx.x] += red[threadIdx.x + o];
        __syncthreads();
    }
    float mean = red[0] * (1.f / DD);
    __syncthreads();
    float v = 0.f;
    for (int d = threadIdx.x; d < DD; d += 256) {
        float t = xr[d] - mean;
        v += t * t;
    }
    red[threadIdx.x] = v;
    __syncthreads();
    for (int o = 128; o > 0; o >>= 1) {
        if (threadIdx.x < o) red[threadIdx.x] += red[threadIdx.x + o];
        __syncthreads();
    }
    float inv = rsqrtf(red[0] * (1.f / DD) + 1e-5f);
    __half* orow = out + (size_t)row * DD;
    for (int d = threadIdx.x; d < DD; d += 256)
        orow[d] = __float2half((xr[d] - mean) * inv * g[d] + b[d]);
}

// ---------------- RoPE on half q/k ----------------
__global__ void rope_kernel(__half* __restrict__ q, __half* __restrict__ k) {
    int idx = blockIdx.x * blockDim.x + threadIdx.x;
    int i = idx & 31;
    int rest = idx >> 5;
    int h = rest & (NH - 1);
    int t = rest >> 4;
    if (t >= SS) return;
    float inv_freq = powf(10000.f, -(float)i / 32.f);
    float ang = (float)t * inv_freq;
    float c = cosf(ang), s = sinf(ang);
    size_t base = (size_t)t * DD + h * HDIM;
    float x1 = __half2float(q[base + i]), x2 = __half2float(q[base + i + 32]);
    q[base + i]      = __float2half(x1 * c - x2 * s);
    q[base + i + 32] = __float2half(x2 * c + x1 * s);
    float y1 = __half2float(k[base + i]), y2 = __half2float(k[base + i + 32]);
    k[base + i]      = __float2half(y1 * c - y2 * s);
    k[base + i + 32] = __float2half(y2 * c + y1 * s);
}

// ---------------- PTX helpers ----------------
__device__ __forceinline__ void cp16(unsigned dst, const void* src, int bytes) {
    asm volatile("cp.async.cg.shared.global [%0], [%1], 16, %2;"
                 :: "r"(dst), "l"(src), "r"(bytes));
}
__device__ __forceinline__ void cp_commit() {
    asm volatile("cp.async.commit_group;");
}
template <int N>
__device__ __forceinline__ void cp_wait() {
    asm volatile("cp.async.wait_group %0;" :: "n"(N));
}
__device__ __forceinline__ void mma_f16(float c[4], unsigned a0, unsigned a1,
                                        unsigned a2, unsigned a3,
                                        unsigned b0, unsigned b1) {
    asm volatile(
        "mma.sync.aligned.m16n8k16.row.col.f32.f16.f16.f32 "
        "{%0,%1,%2,%3}, {%4,%5,%6,%7}, {%8,%9}, {%0,%1,%2,%3};"
        : "+f"(c[0]), "+f"(c[1]), "+f"(c[2]), "+f"(c[3])
        : "r"(a0), "r"(a1), "r"(a2), "r"(a3), "r"(b0), "r"(b1));
}
__device__ __forceinline__ void ldsm_x4_trans(unsigned& r0, unsigned& r1,
                                              unsigned& r2, unsigned& r3,
                                              unsigned addr) {
    asm volatile("ldmatrix.sync.aligned.m8n8.x4.trans.shared.b16 {%0,%1,%2,%3}, [%4];"
                 : "=r"(r0), "=r"(r1), "=r"(r2), "=r"(r3) : "r"(addr));
}

// ================= all-half GEMM: BK=32, 3-stage cp.async ring (R13) =======
#define BKT2 32
#define APH  40

struct HPtr3 {
    const __half* b0; const __half* b1; const __half* b2;
    void* c0; void* c1; void* c2;
};

template <int BN>
__global__ void __launch_bounds__(256, 2)
hgemm_kernel(const __half* __restrict__ A, int lda, long long strideA,
             HPtr3 p, int ldb,
             int ldc, long long strideC,
             int M, int N, int K, float alpha,
             const float* __restrict__ bias,
             const float* __restrict__ res,
             int do_gelu, int multiB, int out_mode) {  // 0 f32, 1 f32+tf32, 2 f16
    const int MT  = (BN == 128) ? 4 : 2;
    const int AST = 128 * APH;
    const int BST = BN * APH;
    const int STG = AST + BST;

    extern __shared__ __align__(16) __half dsm[];

    int z = blockIdx.z;
    const __half* B;
    void* C;
    if (multiB) {
        B = (z == 0) ? p.b0 : (z == 1) ? p.b1 : p.b2;
        C = (z == 0) ? p.c0 : (z == 1) ? p.c1 : p.c2;
    } else {
        B = p.b0;
        C = (out_mode == 2) ? (void*)((__half*)p.c0 + (size_t)z * strideC)
                            : (void*)((float*)p.c0 + (size_t)z * strideC);
        if (res) res += (size_t)z * strideC;
    }
    A += (size_t)z * strideA;

    int row0 = blockIdx.x * 128;
    int col0 = blockIdx.y * BN;
    int nk = K / BKT2;

    int tid = threadIdx.x;
    int lane = tid & 31, warp = tid >> 5;
    int l4 = lane & 3, l28 = lane >> 2;
    int mbase, nbase;
    if (BN == 128) { mbase = (warp >> 2) * 64; nbase = (warp & 3) * 32; }
    else           { mbase = (warp >> 1) * 32; nbase = (warp & 1) * 32; }

    unsigned sbase = (unsigned)__cvta_generic_to_shared(dsm);

    float acc[MT][4][4];
#pragma unroll
    for (int mt = 0; mt < MT; mt++)
#pragma unroll
        for (int nt = 0; nt < 4; nt++)
#pragma unroll
            for (int c = 0; c < 4; c++) acc[mt][nt][c] = 0.f;

    auto prefetch = [&](int s, int k0) {
        unsigned sA = sbase + s * STG * 2;
        unsigned sB = sA + AST * 2;
#pragma unroll
        for (int i = 0; i < 2; i++) {
            int lin = i * 256 + tid;
            int m = lin >> 2, f8 = lin & 3;
            cp16(sA + (m * APH + f8 * 8) * 2,
                 A + (size_t)(row0 + m) * lda + k0 + f8 * 8, 16);
        }
#pragma unroll
        for (int i = 0; i < BN / 64; i++) {
            int lin = i * 256 + tid;
            int n = lin >> 2, f8 = lin & 3;
            int gn = col0 + n;
            cp16(sB + (n * APH + f8 * 8) * 2,
                 B + (size_t)gn * ldb + k0 + f8 * 8, (gn < N) ? 16 : 0);
        }
        cp_commit();
    };

    prefetch(0, 0);
    if (nk > 1) prefetch(1, BKT2);

    int cur = 0;
    for (int ks = 0; ks < nk; ks++) {
        if (ks + 2 < nk) prefetch((cur + 2) % 3, (ks + 2) * BKT2);

        if (ks + 2 < nk)      cp_wait<2>();
        else if (ks + 1 < nk) cp_wait<1>();
        else                  cp_wait<0>();
        __syncthreads();

        const __half* As = dsm + cur * STG;
        const __half* Bs = As + AST;

#pragma unroll
        for (int kb = 0; kb < BKT2; kb += 16) {
            unsigned af[MT][4];
#pragma unroll
            for (int mt = 0; mt < MT; mt++) {
                int mrow = mbase + mt * 16 + l28;
                af[mt][0] = *(const unsigned*)&As[mrow * APH + kb + 2 * l4];
                af[mt][1] = *(const unsigned*)&As[(mrow + 8) * APH + kb + 2 * l4];
                af[mt][2] = *(const unsigned*)&As[mrow * APH + kb + 2 * l4 + 8];
                af[mt][3] = *(const unsigned*)&As[(mrow + 8) * APH + kb + 2 * l4 + 8];
            }
            unsigned bf[4][2];
#pragma unroll
            for (int nt = 0; nt < 4; nt++) {
                int ncol = nbase + nt * 8 + l28;
                bf[nt][0] = *(const unsigned*)&Bs[ncol * APH + kb + 2 * l4];
                bf[nt][1] = *(const unsigned*)&Bs[ncol * APH + kb + 2 * l4 + 8];
            }
#pragma unroll
            for (int mt = 0; mt < MT; mt++)
#pragma unroll
                for (int nt = 0; nt < 4; nt++)
                    mma_f16(acc[mt][nt], af[mt][0], af[mt][1], af[mt][2], af[mt][3],
                            bf[nt][0], bf[nt][1]);
        }
        __syncthreads();
        cur = (cur + 1) % 3;
    }

#pragma unroll
    for (int mt = 0; mt < MT; mt++) {
#pragma unroll
        for (int nt = 0; nt < 4; nt++) {
#pragma unroll
            for (int c = 0; c < 4; c++) {
                int gr = row0 + mbase + mt * 16 + l28 + ((c >= 2) ? 8 : 0);
                int gc = col0 + nbase + nt * 8 + l4 * 2 + (c & 1);
                if (gc >= N) continue;
                float v = alpha * acc[mt][nt][c];
                if (bias) v += bias[gc];
                if (res) v += res[(size_t)gr * ldc + gc];
                if (do_gelu) v = 0.5f * v * (1.f + erff(v * 0.70710678118654752f));
                size_t idx = (size_t)gr * ldc + gc;
                if (out_mode == 2)      ((__half*)C)[idx] = __float2half(v);
                else if (out_mode == 1) ((float*)C)[idx] = tf32f(v);
                else                    ((float*)C)[idx] = v;
            }
        }
    }
}

static inline HPtr3 oneh(const __half* b, void* c) {
    HPtr3 p; p.b0 = b; p.b1 = nullptr; p.b2 = nullptr;
    p.c0 = c; p.c1 = nullptr; p.c2 = nullptr; return p;
}

#define SM128 (3 * (128 + 128) * APH * 2)
#define SM64  (3 * (128 + 64)  * APH * 2)

// ================= fp16 fused causal flash attention ==================
// q/k/v half. S = (q/8) k^T and O += P v both via m16n8k16; P-fragments are
// direct repacks of the S accumulator (no shuffles); V b-frags via ldmatrix.trans.
#define KPH 72
#define FA_SMEM (2 * 2 * 128 * KPH * 2)     // K+V, 2 stages, half = 73728 B

__global__ void __launch_bounds__(256, 2)
flash_kernel(const __half* __restrict__ q, const __half* __restrict__ k,
             const __half* __restrict__ v, __half* __restrict__ o) {
    extern __shared__ __align__(16) __half hsm[];
    __half* Ksm[2] = { hsm, hsm + 128 * KPH };
    __half* Vsm[2] = { hsm + 2 * 128 * KPH, hsm + 3 * 128 * KPH };
    unsigned uK[2], uV[2];
    uK[0] = (unsigned)__cvta_generic_to_shared(Ksm[0]);
    uK[1] = (unsigned)__cvta_generic_to_shared(Ksm[1]);
    uV[0] = (unsigned)__cvta_generic_to_shared(Vsm[0]);
    uV[1] = (unsigned)__cvta_generic_to_shared(Vsm[1]);

    int rb = 15 - blockIdx.x;
    int hb = blockIdx.y * HDIM;
    int row0 = rb * 128;

    int tid = threadIdx.x, lane = tid & 31, w = tid >> 5;
    int l4 = lane & 3, l28 = lane >> 2;
    int rl0 = w * 16 + l28;
    int rl1 = rl0 + 8;
    int grow0 = row0 + rl0, grow1 = row0 + rl1;

    // Q fragments (half2, scale 1/8 folded — exact exponent shift)
    const __half2 sc8 = __float2half2_rn(0.125f);
    unsigned qa[4][4];
#pragma unroll
    for (int c = 0; c < 4; c++) {
        __half2 t0 = __hmul2(*(const __half2*)&q[(size_t)grow0 * DD + hb + 16 * c + 2 * l4], sc8);
        __half2 t1 = __hmul2(*(const __half2*)&q[(size_t)grow1 * DD + hb + 16 * c + 2 * l4], sc8);
        __half2 t2 = __hmul2(*(const __half2*)&q[(size_t)grow0 * DD + hb + 16 * c + 2 * l4 + 8], sc8);
        __half2 t3 = __hmul2(*(const __half2*)&q[(size_t)grow1 * DD + hb + 16 * c + 2 * l4 + 8], sc8);
        qa[c][0] = *(unsigned*)&t0; qa[c][1] = *(unsigned*)&t1;
        qa[c][2] = *(unsigned*)&t2; qa[c][3] = *(unsigned*)&t3;
    }

    float oacc[8][4];
#pragma unroll
    for (int n2 = 0; n2 < 8; n2++)
#pragma unroll
        for (int c = 0; c < 4; c++) oacc[n2][c] = 0.f;
    float mA = -1e30f, mB = -1e30f, lA = 0.f, lB = 0.f;

    auto prefetch = [&](int j, int s) {
#pragma unroll
        for (int i = 0; i < 4; i++) {
            int lin = i * 256 + tid;
            int r = lin >> 3, f = lin & 7;
            cp16(uK[s] + (r * KPH + f * 8) * 2,
                 k + (size_t)(j * 128 + r) * DD + hb + f * 8, 16);
            cp16(uV[s] + (r * KPH + f * 8) * 2,
                 v + (size_t)(j * 128 + r) * DD + hb + f * 8, 16);
        }
        cp_commit();
    };

    prefetch(0, 0);

    for (int j = 0; j <= rb; j++) {
        int s = j & 1;
        bool more = j < rb;
        if (more) prefetch(j + 1, s ^ 1);
        if (more) cp_wait<1>(); else cp_wait<0>();
        __syncthreads();

        // ---- S = (q/8) k^T : 4 k16 chunks x 16 n-tiles ----
        float sacc[16][4];
#pragma unroll
        for (int t = 0; t < 16; t++)
#pragma unroll
            for (int c = 0; c < 4; c++) sacc[t][c] = 0.f;
#pragma unroll
        for (int c = 0; c < 4; c++) {
#pragma unroll
            for (int t = 0; t < 16; t++) {
                unsigned b0 = *(const unsigned*)&Ksm[s][(t * 8 + l28) * KPH + 16 * c + 2 * l4];
                unsigned b1 = *(const unsigned*)&Ksm[s][(t * 8 + l28) * KPH + 16 * c + 2 * l4 + 8];
                mma_f16(sacc[t], qa[c][0], qa[c][1], qa[c][2], qa[c][3], b0, b1);
            }
        }

        if (j == rb) {
#pragma unroll
            for (int t = 0; t < 16; t++) {
                int cb = 8 * t + 2 * l4;
                if (cb     > rl0) sacc[t][0] = -1e30f;
                if (cb + 1 > rl0) sacc[t][1] = -1e30f;
                if (cb     > rl1) sacc[t][2] = -1e30f;
                if (cb + 1 > rl1) sacc[t][3] = -1e30f;
            }
        }

        float tmA = -1e30f, tmB = -1e30f;
#pragma unroll
        for (int t = 0; t < 16; t++) {
            tmA = fmaxf(tmA, fmaxf(sacc[t][0], sacc[t][1]));
            tmB = fmaxf(tmB, fmaxf(sacc[t][2], sacc[t][3]));
        }
        tmA = fmaxf(tmA, __shfl_xor_sync(0xffffffffu, tmA, 1));
        tmA = fmaxf(tmA, __shfl_xor_sync(0xffffffffu, tmA, 2));
        tmB = fmaxf(tmB, __shfl_xor_sync(0xffffffffu, tmB, 1));
        tmB = fmaxf(tmB, __shfl_xor_sync(0xffffffffu, tmB, 2));

        float mnA = fmaxf(mA, tmA), mnB = fmaxf(mB, tmB);
        float cA = __expf(mA - mnA), cB = __expf(mB - mnB);
        mA = mnA; mB = mnB;

        float tsA = 0.f, tsB = 0.f;
#pragma unroll
        for (int t = 0; t < 16; t++) {
            sacc[t][0] = __expf(sacc[t][0] - mA);
            sacc[t][1] = __expf(sacc[t][1] - mA);
            sacc[t][2] = __expf(sacc[t][2] - mB);
            sacc[t][3] = __expf(sacc[t][3] - mB);
            tsA += sacc[t][0] + sacc[t][1];
            tsB += sacc[t][2] + sacc[t][3];
        }
        tsA += __shfl_xor_sync(0xffffffffu, tsA, 1);
        tsA += __shfl_xor_sync(0xffffffffu, tsA, 2);
        tsB += __shfl_xor_sync(0xffffffffu, tsB, 1);
        tsB += __shfl_xor_sync(0xffffffffu, tsB, 2);
        lA = lA * cA + tsA;
        lB = lB * cB + tsB;

#pragma unroll
        for (int n2 = 0; n2 < 8; n2++) {
            oacc[n2][0] *= cA; oacc[n2][1] *= cA;
            oacc[n2][2] *= cB; oacc[n2][3] *= cB;
        }

        // ---- O += P @ V : P frags = direct accumulator repack ----
#pragma unroll
        for (int kc = 0; kc < 8; kc++) {
            unsigned a0 = packh(sacc[2 * kc][0],     sacc[2 * kc][1]);
            unsigned a1 = packh(sacc[2 * kc][2],     sacc[2 * kc][3]);
            unsigned a2 = packh(sacc[2 * kc + 1][0], sacc[2 * kc + 1][1]);
            unsigned a3 = packh(sacc[2 * kc + 1][2], sacc[2 * kc + 1][3]);
            unsigned vrow = (unsigned)(16 * kc + (lane & 7) + 8 * ((lane >> 3) & 1));
#pragma unroll
            for (int pq = 0; pq < 4; pq++) {
                unsigned b0, b1, b2, b3;
                unsigned addr = uV[s] + (vrow * KPH + pq * 16 + 8 * (lane >> 4)) * 2;
                ldsm_x4_trans(b0, b1, b2, b3, addr);
                mma_f16(oacc[2 * pq],     a0, a1, a2, a3, b0, b1);
                mma_f16(oacc[2 * pq + 1], a0, a1, a2, a3, b2, b3);
            }
        }
        __syncthreads();
    }

    float iA = 1.f / lA, iB = 1.f / lB;
#pragma unroll
    for (int n2 = 0; n2 < 8; n2++) {
        *(__half2*)&o[(size_t)grow0 * DD + hb + n2 * 8 + 2 * l4] =
            __floats2half2_rn(oacc[n2][0] * iA, oacc[n2][1] * iA);
        *(__half2*)&o[(size_t)grow1 * DD + hb + n2 * 8 + 2 * l4] =
            __floats2half2_rn(oacc[n2][2] * iB, oacc[n2][3] * iB);
    }
}

// ---------------- host orchestration ----------------
extern "C" void kernel_launch(void* const* d_in, const int* in_sizes, int n_in,
                              void* d_out, int out_size) {
    const int*   ids  = (const int*)d_in[0];
    const float* emb  = (const float*)d_in[1];
    const float* Wq   = (const float*)d_in[2];
    const float* Wk   = (const float*)d_in[3];
    const float* Wv   = (const float*)d_in[4];
    const float* Wo   = (const float*)d_in[5];
    const float* ln1g = (const float*)d_in[6];
    const float* ln1b = (const float*)d_in[7];
    const float* ln2g = (const float*)d_in[8];
    const float* ln2b = (const float*)d_in[9];
    const float* W1   = (const float*)d_in[10];
    const float* b1   = (const float*)d_in[11];
    const float* W2   = (const float*)d_in[12];
    const float* b2   = (const float*)d_in[13];
    const float* lnfg = (const float*)d_in[14];
    const float* lnfb = (const float*)d_in[15];
    float* out = (float*)d_out;

    float *x;
    __half *h, *q, *k, *v, *mlp, *wqh, *wkh, *wvh, *woh, *w1h, *w2h, *embh;
    cudaGetSymbolAddress((void**)&x,    g_x);
    cudaGetSymbolAddress((void**)&h,    g_h);
    cudaGetSymbolAddress((void**)&q,    g_q);
    cudaGetSymbolAddress((void**)&k,    g_k);
    cudaGetSymbolAddress((void**)&v,    g_v);
    cudaGetSymbolAddress((void**)&mlp,  g_mlp);
    cudaGetSymbolAddress((void**)&wqh,  g_wqh);
    cudaGetSymbolAddress((void**)&wkh,  g_wkh);
    cudaGetSymbolAddress((void**)&wvh,  g_wvh);
    cudaGetSymbolAddress((void**)&woh,  g_woh);
    cudaGetSymbolAddress((void**)&w1h,  g_w1h);
    cudaGetSymbolAddress((void**)&w2h,  g_w2h);
    cudaGetSymbolAddress((void**)&embh, g_embh);

    cudaFuncSetAttribute(flash_kernel,
                         cudaFuncAttributeMaxDynamicSharedMemorySize, FA_SMEM);
    cudaFuncSetAttribute(hgemm_kernel<128>,
                         cudaFuncAttributeMaxDynamicSharedMemorySize, SM128);
    cudaFuncSetAttribute(hgemm_kernel<64>,
                         cudaFuncAttributeMaxDynamicSharedMemorySize, SM64);

    // per-call weight transposition / half conversion
    transph_kernel<<<dim3(32, 32, NL), 256>>>(Wq, wqh, DD, DD,
                                              (long long)DD * DD, (long long)DD * DD);
    transph_kernel<<<dim3(32, 32, NL), 256>>>(Wk, wkh, DD, DD,
                                              (long long)DD * DD, (long long)DD * DD);
    transph_kernel<<<dim3(32, 32, NL), 256>>>(Wv, wvh, DD, DD,
                                              (long long)DD * DD, (long long)DD * DD);
    transph_kernel<<<dim3(32, 32, NL), 256>>>(Wo, woh, DD, DD,
                                              (long long)DD * DD, (long long)DD * DD);
    transph_kernel<<<dim3(DMLP / 32, 32, NL), 256>>>(W1, w1h, DD, DMLP,
                                                     (long long)DD * DMLP, (long long)DD * DMLP);
    transph_kernel<<<dim3(32, DMLP / 32, NL), 256>>>(W2, w2h, DMLP, DD,
                                                     (long long)DMLP * DD, (long long)DMLP * DD);
    convh_kernel<<<4096, 256>>>((const float4*)emb, (uint2*)embh,
                                (long long)NV * DD / 4);

    embed_kernel<<<SS, 256>>>(ids, emb, x);

    for (int l = 0; l < NL; l++) {
        const size_t wofs = (size_t)l * DD * DD;
        layernorm_kernel<<<SS, 256>>>(x, ln1g + l * DD, ln1b + l * DD, h);

        // fused QKV -> half q,k,v
        {
            HPtr3 p;
            p.b0 = wqh + wofs; p.b1 = wkh + wofs; p.b2 = wvh + wofs;
            p.c0 = q; p.c1 = k; p.c2 = v;
            hgemm_kernel<128><<<dim3(SS / 128, DD / 128, 3), 256, SM128>>>(
                h, DD, 0, p, DD, DD, 0,
                SS, DD, DD, 1.f, nullptr, nullptr, 0, 1, 2);
        }

        rope_kernel<<<(SS * NH * 32 + 255) / 256, 256>>>(q, k);

        flash_kernel<<<dim3(SS / 128, NH), 256, FA_SMEM>>>(q, k, v, h);

        // x = x + attn @ Wo
        hgemm_kernel<64><<<dim3(SS / 128, DD / 64, 1), 256, SM64>>>(
            h, DD, 0, oneh(woh + wofs, x), DD, DD, 0,
            SS, DD, DD, 1.f, nullptr, x, 0, 0, 0);

        layernorm_kernel<<<SS, 256>>>(x, ln2g + l * DD, ln2b + l * DD, h);

        // mlp = gelu(h @ W1 + b1) -> half
        hgemm_kernel<128><<<dim3(SS / 128, DMLP / 128, 1), 256, SM128>>>(
            h, DD, 0, oneh(w1h + (size_t)l * DD * DMLP, mlp), DD, DMLP, 0,
            SS, DMLP, DD, 1.f, b1 + (size_t)l * DMLP, nullptr, 1, 0, 2);

        // x = x + mlp @ W2 + b2
        hgemm_kernel<64><<<dim3(SS / 128, DD / 64, 1), 256, SM64>>>(
            mlp, DMLP, 0, oneh(w2h + (size_t)l * DD * DMLP, x), DMLP, DD, 0,
            SS, DD, DMLP, 1.f, b2 + (size_t)l * DD, x, 0, 0, 0);
    }

    layernorm_kernel<<<SS, 256>>>(x, lnfg, lnfb, h);

    // logits = h @ embh^T
    hgemm_kernel<128><<<dim3(SS / 128, (NV + 127) / 128, 1), 256, SM128>>>(
        h, DD, 0, oneh(embh, out), DD, NV, 0,
        SS, NV, DD, 1.f, nullptr, nullptr, 0, 0, 0);
}

// round 15
// speedup vs baseline: 1.7912x; 1.0604x over previous
#include <cuda_runtime.h>
#include <cuda_fp16.h>
#include <math.h>
#include <stdint.h>

#define SS   2048
#define DD   1024
#define NL   4
#define NH   16
#define HDIM 64
#define NV   50257
#define DMLP 4096

// ---------------- scratch ----------------
__device__ float  g_x[SS * DD];
__device__ __half g_h[SS * DD];
__device__ __half g_q[SS * DD];
__device__ __half g_k[SS * DD];
__device__ __half g_v[SS * DD];
__device__ __half g_mlp[SS * DMLP];
__device__ __half g_wqh[(size_t)NL * DD * DD];
__device__ __half g_wkh[(size_t)NL * DD * DD];
__device__ __half g_wvh[(size_t)NL * DD * DD];
__device__ __half g_woh[(size_t)NL * DD * DD];
__device__ __half g_w1h[(size_t)NL * DMLP * DD];
__device__ __half g_w2h[(size_t)NL * DD * DMLP];
__device__ __half g_embh[(size_t)NV * DD];

// ---------------- helpers ----------------
__device__ __forceinline__ unsigned f2tf(float f) {
    unsigned u;
    asm("cvt.rna.tf32.f32 %0, %1;" : "=r"(u) : "f"(f));
    return u;
}
__device__ __forceinline__ float tf32f(float f) {
    return __uint_as_float(f2tf(f));
}
__device__ __forceinline__ unsigned packh(float a, float b) {
    unsigned d;
    asm("cvt.rn.f16x2.f32 %0, %1, %2;" : "=r"(d) : "f"(b), "f"(a));
    return d;
}

// ---------------- weight transpose + half convert: W[K][N] -> Wt[N][K] -----
__global__ void transph_kernel(const float* __restrict__ W, __half* __restrict__ Wt,
                               int K, int N, long long wstride, long long tstride) {
    __shared__ float tile[32][33];
    const float* Wz = W + (size_t)blockIdx.z * wstride;
    __half* Tz = Wt + (size_t)blockIdx.z * tstride;
    int n0 = blockIdx.x * 32, k0 = blockIdx.y * 32;
    int tx = threadIdx.x & 31, ty = threadIdx.x >> 5;
#pragma unroll
    for (int i = 0; i < 4; i++)
        tile[ty + i * 8][tx] = Wz[(size_t)(k0 + ty + i * 8) * N + n0 + tx];
    __syncthreads();
#pragma unroll
    for (int i = 0; i < 4; i++)
        Tz[(size_t)(n0 + ty + i * 8) * K + k0 + tx] = __float2half(tile[tx][ty + i * 8]);
}

// ---------------- straight half convert (emb) ----------------
__global__ void convh_kernel(const float4* __restrict__ in,
                             uint2* __restrict__ out, long long n4) {
    long long i = blockIdx.x * (long long)blockDim.x + threadIdx.x;
    long long stride = (long long)gridDim.x * blockDim.x;
    for (; i < n4; i += stride) {
        float4 t = in[i];
        unsigned lo, hi;
        asm("cvt.rn.f16x2.f32 %0, %1, %2;" : "=r"(lo) : "f"(t.y), "f"(t.x));
        asm("cvt.rn.f16x2.f32 %0, %1, %2;" : "=r"(hi) : "f"(t.w), "f"(t.z));
        out[i] = make_uint2(lo, hi);
    }
}

// ---------------- embedding gather ----------------
__global__ void embed_kernel(const int* __restrict__ ids,
                             const float* __restrict__ emb,
                             float* __restrict__ x) {
    int t = blockIdx.x;
    int id = ids[t];
    if (id < 0) id = 0;
    if (id >= NV) id = NV - 1;
    const float* src = emb + (size_t)id * DD;
    float* dst = x + (size_t)t * DD;
    for (int d = threadIdx.x; d < DD; d += blockDim.x) dst[d] = src[d];
}

// ---------------- layernorm (half out) ----------------
__global__ void layernorm_kernel(const float* __restrict__ x,
                                 const float* __restrict__ g,
                                 const float* __restrict__ b,
                                 __half* __restrict__ out) {
    __shared__ float red[256];
    int row = blockIdx.x;
    const float* xr = x + (size_t)row * DD;
    float s = 0.f;
    for (int d = threadIdx.x; d < DD; d += 256) s += xr[d];
    red[threadIdx.x] = s;
    __syncthreads();
    for (int o = 128; o > 0; o >>= 1) {
        if (threadIdx.x < o) red[threadIdx.x] += red[threadIdx.x + o];
        __syncthreads();
    }
    float mean = red[0] * (1.f / DD);
    __syncthreads();
    float v = 0.f;
    for (int d = threadIdx.x; d < DD; d += 256) {
        float t = xr[d] - mean;
        v += t * t;
    }
    red[threadIdx.x] = v;
    __syncthreads();
    for (int o = 128; o > 0; o >>= 1) {
        if (threadIdx.x < o) red[threadIdx.x] += red[threadIdx.x + o];
        __syncthreads();
    }
    float inv = rsqrtf(red[0] * (1.f / DD) + 1e-5f);
    __half* orow = out + (size_t)row * DD;
    for (int d = threadIdx.x; d < DD; d += 256)
        orow[d] = __float2half((xr[d] - mean) * inv * g[d] + b[d]);
}

// ---------------- RoPE on half q/k ----------------
__global__ void rope_kernel(__half* __restrict__ q, __half* __restrict__ k) {
    int idx = blockIdx.x * blockDim.x + threadIdx.x;
    int i = idx & 31;
    int rest = idx >> 5;
    int h = rest & (NH - 1);
    int t = rest >> 4;
    if (t >= SS) return;
    float inv_freq = powf(10000.f, -(float)i / 32.f);
    float ang = (float)t * inv_freq;
    float c = cosf(ang), s = sinf(ang);
    size_t base = (size_t)t * DD + h * HDIM;
    float x1 = __half2float(q[base + i]), x2 = __half2float(q[base + i + 32]);
    q[base + i]      = __float2half(x1 * c - x2 * s);
    q[base + i + 32] = __float2half(x2 * c + x1 * s);
    float y1 = __half2float(k[base + i]), y2 = __half2float(k[base + i + 32]);
    k[base + i]      = __float2half(y1 * c - y2 * s);
    k[base + i + 32] = __float2half(y2 * c + y1 * s);
}

// ---------------- PTX helpers ----------------
__device__ __forceinline__ void cp16(unsigned dst, const void* src, int bytes) {
    asm volatile("cp.async.cg.shared.global [%0], [%1], 16, %2;"
                 :: "r"(dst), "l"(src), "r"(bytes));
}
__device__ __forceinline__ void cp_commit() {
    asm volatile("cp.async.commit_group;");
}
template <int N>
__device__ __forceinline__ void cp_wait() {
    asm volatile("cp.async.wait_group %0;" :: "n"(N));
}
__device__ __forceinline__ void mma_f16(float c[4], unsigned a0, unsigned a1,
                                        unsigned a2, unsigned a3,
                                        unsigned b0, unsigned b1) {
    asm volatile(
        "mma.sync.aligned.m16n8k16.row.col.f32.f16.f16.f32 "
        "{%0,%1,%2,%3}, {%4,%5,%6,%7}, {%8,%9}, {%0,%1,%2,%3};"
        : "+f"(c[0]), "+f"(c[1]), "+f"(c[2]), "+f"(c[3])
        : "r"(a0), "r"(a1), "r"(a2), "r"(a3), "r"(b0), "r"(b1));
}
__device__ __forceinline__ void ldsm_x4(unsigned& r0, unsigned& r1,
                                        unsigned& r2, unsigned& r3,
                                        unsigned addr) {
    asm volatile("ldmatrix.sync.aligned.m8n8.x4.shared.b16 {%0,%1,%2,%3}, [%4];"
                 : "=r"(r0), "=r"(r1), "=r"(r2), "=r"(r3) : "r"(addr));
}
__device__ __forceinline__ void ldsm_x4_trans(unsigned& r0, unsigned& r1,
                                              unsigned& r2, unsigned& r3,
                                              unsigned addr) {
    asm volatile("ldmatrix.sync.aligned.m8n8.x4.trans.shared.b16 {%0,%1,%2,%3}, [%4];"
                 : "=r"(r0), "=r"(r1), "=r"(r2), "=r"(r3) : "r"(addr));
}

// ================= all-half GEMM: BK=32, 3-stage ring, ldmatrix frags ======
#define BKT2 32
#define APH  40

struct HPtr3 {
    const __half* b0; const __half* b1; const __half* b2;
    void* c0; void* c1; void* c2;
};

template <int BN>
__global__ void __launch_bounds__(256, 2)
hgemm_kernel(const __half* __restrict__ A, int lda, long long strideA,
             HPtr3 p, int ldb,
             int ldc, long long strideC,
             int M, int N, int K, float alpha,
             const float* __restrict__ bias,
             const float* __restrict__ res,
             int do_gelu, int multiB, int out_mode) {  // 0 f32, 1 f32+tf32, 2 f16
    const int MT  = (BN == 128) ? 4 : 2;
    const int AST = 128 * APH;
    const int BST = BN * APH;
    const int STG = AST + BST;

    extern __shared__ __align__(16) __half dsm[];

    int z = blockIdx.z;
    const __half* B;
    void* C;
    if (multiB) {
        B = (z == 0) ? p.b0 : (z == 1) ? p.b1 : p.b2;
        C = (z == 0) ? p.c0 : (z == 1) ? p.c1 : p.c2;
    } else {
        B = p.b0;
        C = (out_mode == 2) ? (void*)((__half*)p.c0 + (size_t)z * strideC)
                            : (void*)((float*)p.c0 + (size_t)z * strideC);
        if (res) res += (size_t)z * strideC;
    }
    A += (size_t)z * strideA;

    int row0 = blockIdx.x * 128;
    int col0 = blockIdx.y * BN;
    int nk = K / BKT2;

    int tid = threadIdx.x;
    int lane = tid & 31, warp = tid >> 5;
    int l4 = lane & 3, l28 = lane >> 2;
    int mbase, nbase;
    if (BN == 128) { mbase = (warp >> 2) * 64; nbase = (warp & 3) * 32; }
    else           { mbase = (warp >> 1) * 32; nbase = (warp & 1) * 32; }

    unsigned sbase = (unsigned)__cvta_generic_to_shared(dsm);

    // ldmatrix per-lane row/col offsets (in halves)
    int a_lrow = lane & 15;            // row within m16
    int a_lcol = 8 * (lane >> 4);      // 0 or 8 (k split)
    int b_lrow = (lane & 7) + 8 * (lane >> 4);     // row within n16
    int b_lcol = 8 * ((lane >> 3) & 1);            // 0 or 8 (k split)

    float acc[MT][4][4];
#pragma unroll
    for (int mt = 0; mt < MT; mt++)
#pragma unroll
        for (int nt = 0; nt < 4; nt++)
#pragma unroll
            for (int c = 0; c < 4; c++) acc[mt][nt][c] = 0.f;

    auto prefetch = [&](int s, int k0) {
        unsigned sA = sbase + s * STG * 2;
        unsigned sB = sA + AST * 2;
#pragma unroll
        for (int i = 0; i < 2; i++) {
            int lin = i * 256 + tid;
            int m = lin >> 2, f8 = lin & 3;
            cp16(sA + (m * APH + f8 * 8) * 2,
                 A + (size_t)(row0 + m) * lda + k0 + f8 * 8, 16);
        }
#pragma unroll
        for (int i = 0; i < BN / 64; i++) {
            int lin = i * 256 + tid;
            int n = lin >> 2, f8 = lin & 3;
            int gn = col0 + n;
            cp16(sB + (n * APH + f8 * 8) * 2,
                 B + (size_t)gn * ldb + k0 + f8 * 8, (gn < N) ? 16 : 0);
        }
        cp_commit();
    };

    prefetch(0, 0);
    if (nk > 1) prefetch(1, BKT2);

    int cur = 0;
    for (int ks = 0; ks < nk; ks++) {
        if (ks + 2 < nk) prefetch((cur + 2) % 3, (ks + 2) * BKT2);

        if (ks + 2 < nk)      cp_wait<2>();
        else if (ks + 1 < nk) cp_wait<1>();
        else                  cp_wait<0>();
        __syncthreads();

        unsigned uA = sbase + cur * STG * 2;
        unsigned uB = uA + AST * 2;

#pragma unroll
        for (int kb = 0; kb < BKT2; kb += 16) {
            unsigned af[MT][4];
#pragma unroll
            for (int mt = 0; mt < MT; mt++) {
                unsigned addr = uA + (((mbase + mt * 16 + a_lrow) * APH) + kb + a_lcol) * 2;
                ldsm_x4(af[mt][0], af[mt][1], af[mt][2], af[mt][3], addr);
            }
            unsigned bf[4][2];
#pragma unroll
            for (int np = 0; np < 2; np++) {
                unsigned addr = uB + (((nbase + np * 16 + b_lrow) * APH) + kb + b_lcol) * 2;
                ldsm_x4(bf[np * 2][0], bf[np * 2][1], bf[np * 2 + 1][0], bf[np * 2 + 1][1], addr);
            }
#pragma unroll
            for (int mt = 0; mt < MT; mt++)
#pragma unroll
                for (int nt = 0; nt < 4; nt++)
                    mma_f16(acc[mt][nt], af[mt][0], af[mt][1], af[mt][2], af[mt][3],
                            bf[nt][0], bf[nt][1]);
        }
        __syncthreads();
        cur = (cur + 1) % 3;
    }

#pragma unroll
    for (int mt = 0; mt < MT; mt++) {
#pragma unroll
        for (int nt = 0; nt < 4; nt++) {
#pragma unroll
            for (int c = 0; c < 4; c++) {
                int gr = row0 + mbase + mt * 16 + l28 + ((c >= 2) ? 8 : 0);
                int gc = col0 + nbase + nt * 8 + l4 * 2 + (c & 1);
                if (gc >= N) continue;
                float v = alpha * acc[mt][nt][c];
                if (bias) v += bias[gc];
                if (res) v += res[(size_t)gr * ldc + gc];
                if (do_gelu) v = 0.5f * v * (1.f + erff(v * 0.70710678118654752f));
                size_t idx = (size_t)gr * ldc + gc;
                if (out_mode == 2)      ((__half*)C)[idx] = __float2half(v);
                else if (out_mode == 1) ((float*)C)[idx] = tf32f(v);
                else                    ((float*)C)[idx] = v;
            }
        }
    }
}

static inline HPtr3 oneh(const __half* b, void* c) {
    HPtr3 p; p.b0 = b; p.b1 = nullptr; p.b2 = nullptr;
    p.c0 = c; p.c1 = nullptr; p.c2 = nullptr; return p;
}

#define SM128 (3 * (128 + 128) * APH * 2)
#define SM64  (3 * (128 + 64)  * APH * 2)

// ================= fp16 fused causal flash attention (R14, proven) =========
#define KPH 72
#define FA_SMEM (2 * 2 * 128 * KPH * 2)

__global__ void __launch_bounds__(256, 2)
flash_kernel(const __half* __restrict__ q, const __half* __restrict__ k,
             const __half* __restrict__ v, __half* __restrict__ o) {
    extern __shared__ __align__(16) __half hsm[];
    __half* Ksm[2] = { hsm, hsm + 128 * KPH };
    unsigned uK[2], uV[2];
    uK[0] = (unsigned)__cvta_generic_to_shared(Ksm[0]);
    uK[1] = (unsigned)__cvta_generic_to_shared(Ksm[1]);
    uV[0] = (unsigned)__cvta_generic_to_shared(hsm + 2 * 128 * KPH);
    uV[1] = (unsigned)__cvta_generic_to_shared(hsm + 3 * 128 * KPH);

    int rb = 15 - blockIdx.x;
    int hb = blockIdx.y * HDIM;
    int row0 = rb * 128;

    int tid = threadIdx.x, lane = tid & 31, w = tid >> 5;
    int l4 = lane & 3, l28 = lane >> 2;
    int rl0 = w * 16 + l28;
    int rl1 = rl0 + 8;
    int grow0 = row0 + rl0, grow1 = row0 + rl1;

    const __half2 sc8 = __float2half2_rn(0.125f);
    unsigned qa[4][4];
#pragma unroll
    for (int c = 0; c < 4; c++) {
        __half2 t0 = __hmul2(*(const __half2*)&q[(size_t)grow0 * DD + hb + 16 * c + 2 * l4], sc8);
        __half2 t1 = __hmul2(*(const __half2*)&q[(size_t)grow1 * DD + hb + 16 * c + 2 * l4], sc8);
        __half2 t2 = __hmul2(*(const __half2*)&q[(size_t)grow0 * DD + hb + 16 * c + 2 * l4 + 8], sc8);
        __half2 t3 = __hmul2(*(const __half2*)&q[(size_t)grow1 * DD + hb + 16 * c + 2 * l4 + 8], sc8);
        qa[c][0] = *(unsigned*)&t0; qa[c][1] = *(unsigned*)&t1;
        qa[c][2] = *(unsigned*)&t2; qa[c][3] = *(unsigned*)&t3;
    }

    float oacc[8][4];
#pragma unroll
    for (int n2 = 0; n2 < 8; n2++)
#pragma unroll
        for (int c = 0; c < 4; c++) oacc[n2][c] = 0.f;
    float mA = -1e30f, mB = -1e30f, lA = 0.f, lB = 0.f;

    auto prefetch = [&](int j, int s) {
#pragma unroll
        for (int i = 0; i < 4; i++) {
            int lin = i * 256 + tid;
            int r = lin >> 3, f = lin & 7;
            cp16(uK[s] + (r * KPH + f * 8) * 2,
                 k + (size_t)(j * 128 + r) * DD + hb + f * 8, 16);
            cp16(uV[s] + (r * KPH + f * 8) * 2,
                 v + (size_t)(j * 128 + r) * DD + hb + f * 8, 16);
        }
        cp_commit();
    };

    prefetch(0, 0);

    for (int j = 0; j <= rb; j++) {
        int s = j & 1;
        bool more = j < rb;
        if (more) prefetch(j + 1, s ^ 1);
        if (more) cp_wait<1>(); else cp_wait<0>();
        __syncthreads();

        float sacc[16][4];
#pragma unroll
        for (int t = 0; t < 16; t++)
#pragma unroll
            for (int c = 0; c < 4; c++) sacc[t][c] = 0.f;
#pragma unroll
        for (int c = 0; c < 4; c++) {
#pragma unroll
            for (int t = 0; t < 16; t++) {
                unsigned b0 = *(const unsigned*)&Ksm[s][(t * 8 + l28) * KPH + 16 * c + 2 * l4];
                unsigned b1 = *(const unsigned*)&Ksm[s][(t * 8 + l28) * KPH + 16 * c + 2 * l4 + 8];
                mma_f16(sacc[t], qa[c][0], qa[c][1], qa[c][2], qa[c][3], b0, b1);
            }
        }

        if (j == rb) {
#pragma unroll
            for (int t = 0; t < 16; t++) {
                int cb = 8 * t + 2 * l4;
                if (cb     > rl0) sacc[t][0] = -1e30f;
                if (cb + 1 > rl0) sacc[t][1] = -1e30f;
                if (cb     > rl1) sacc[t][2] = -1e30f;
                if (cb + 1 > rl1) sacc[t][3] = -1e30f;
            }
        }

        float tmA = -1e30f, tmB = -1e30f;
#pragma unroll
        for (int t = 0; t < 16; t++) {
            tmA = fmaxf(tmA, fmaxf(sacc[t][0], sacc[t][1]));
            tmB = fmaxf(tmB, fmaxf(sacc[t][2], sacc[t][3]));
        }
        tmA = fmaxf(tmA, __shfl_xor_sync(0xffffffffu, tmA, 1));
        tmA = fmaxf(tmA, __shfl_xor_sync(0xffffffffu, tmA, 2));
        tmB = fmaxf(tmB, __shfl_xor_sync(0xffffffffu, tmB, 1));
        tmB = fmaxf(tmB, __shfl_xor_sync(0xffffffffu, tmB, 2));

        float mnA = fmaxf(mA, tmA), mnB = fmaxf(mB, tmB);
        float cA = __expf(mA - mnA), cB = __expf(mB - mnB);
        mA = mnA; mB = mnB;

        float tsA = 0.f, tsB = 0.f;
#pragma unroll
        for (int t = 0; t < 16; t++) {
            sacc[t][0] = __expf(sacc[t][0] - mA);
            sacc[t][1] = __expf(sacc[t][1] - mA);
            sacc[t][2] = __expf(sacc[t][2] - mB);
            sacc[t][3] = __expf(sacc[t][3] - mB);
            tsA += sacc[t][0] + sacc[t][1];
            tsB += sacc[t][2] + sacc[t][3];
        }
        tsA += __shfl_xor_sync(0xffffffffu, tsA, 1);
        tsA += __shfl_xor_sync(0xffffffffu, tsA, 2);
        tsB += __shfl_xor_sync(0xffffffffu, tsB, 1);
        tsB += __shfl_xor_sync(0xffffffffu, tsB, 2);
        lA = lA * cA + tsA;
        lB = lB * cB + tsB;

#pragma unroll
        for (int n2 = 0; n2 < 8; n2++) {
            oacc[n2][0] *= cA; oacc[n2][1] *= cA;
            oacc[n2][2] *= cB; oacc[n2][3] *= cB;
        }

#pragma unroll
        for (int kc = 0; kc < 8; kc++) {
            unsigned a0 = packh(sacc[2 * kc][0],     sacc[2 * kc][1]);
            unsigned a1 = packh(sacc[2 * kc][2],     sacc[2 * kc][3]);
            unsigned a2 = packh(sacc[2 * kc + 1][0], sacc[2 * kc + 1][1]);
            unsigned a3 = packh(sacc[2 * kc + 1][2], sacc[2 * kc + 1][3]);
            unsigned vrow = (unsigned)(16 * kc + (lane & 7) + 8 * ((lane >> 3) & 1));
#pragma unroll
            for (int pq = 0; pq < 4; pq++) {
                unsigned b0, b1, b2, b3;
                unsigned addr = uV[s] + (vrow * KPH + pq * 16 + 8 * (lane >> 4)) * 2;
                ldsm_x4_trans(b0, b1, b2, b3, addr);
                mma_f16(oacc[2 * pq],     a0, a1, a2, a3, b0, b1);
                mma_f16(oacc[2 * pq + 1], a0, a1, a2, a3, b2, b3);
            }
        }
        __syncthreads();
    }

    float iA = 1.f / lA, iB = 1.f / lB;
#pragma unroll
    for (int n2 = 0; n2 < 8; n2++) {
        *(__half2*)&o[(size_t)grow0 * DD + hb + n2 * 8 + 2 * l4] =
            __floats2half2_rn(oacc[n2][0] * iA, oacc[n2][1] * iA);
        *(__half2*)&o[(size_t)grow1 * DD + hb + n2 * 8 + 2 * l4] =
            __floats2half2_rn(oacc[n2][2] * iB, oacc[n2][3] * iB);
    }
}

// ---------------- host orchestration ----------------
extern "C" void kernel_launch(void* const* d_in, const int* in_sizes, int n_in,
                              void* d_out, int out_size) {
    const int*   ids  = (const int*)d_in[0];
    const float* emb  = (const float*)d_in[1];
    const float* Wq   = (const float*)d_in[2];
    const float* Wk   = (const float*)d_in[3];
    const float* Wv   = (const float*)d_in[4];
    const float* Wo   = (const float*)d_in[5];
    const float* ln1g = (const float*)d_in[6];
    const float* ln1b = (const float*)d_in[7];
    const float* ln2g = (const float*)d_in[8];
    const float* ln2b = (const float*)d_in[9];
    const float* W1   = (const float*)d_in[10];
    const float* b1   = (const float*)d_in[11];
    const float* W2   = (const float*)d_in[12];
    const float* b2   = (const float*)d_in[13];
    const float* lnfg = (const float*)d_in[14];
    const float* lnfb = (const float*)d_in[15];
    float* out = (float*)d_out;

    float *x;
    __half *h, *q, *k, *v, *mlp, *wqh, *wkh, *wvh, *woh, *w1h, *w2h, *embh;
    cudaGetSymbolAddress((void**)&x,    g_x);
    cudaGetSymbolAddress((void**)&h,    g_h);
    cudaGetSymbolAddress((void**)&q,    g_q);
    cudaGetSymbolAddress((void**)&k,    g_k);
    cudaGetSymbolAddress((void**)&v,    g_v);
    cudaGetSymbolAddress((void**)&mlp,  g_mlp);
    cudaGetSymbolAddress((void**)&wqh,  g_wqh);
    cudaGetSymbolAddress((void**)&wkh,  g_wkh);
    cudaGetSymbolAddress((void**)&wvh,  g_wvh);
    cudaGetSymbolAddress((void**)&woh,  g_woh);
    cudaGetSymbolAddress((void**)&w1h,  g_w1h);
    cudaGetSymbolAddress((void**)&w2h,  g_w2h);
    cudaGetSymbolAddress((void**)&embh, g_embh);

    cudaFuncSetAttribute(flash_kernel,
                         cudaFuncAttributeMaxDynamicSharedMemorySize, FA_SMEM);
    cudaFuncSetAttribute(hgemm_kernel<128>,
                         cudaFuncAttributeMaxDynamicSharedMemorySize, SM128);
    cudaFuncSetAttribute(hgemm_kernel<64>,
                         cudaFuncAttributeMaxDynamicSharedMemorySize, SM64);

    transph_kernel<<<dim3(32, 32, NL), 256>>>(Wq, wqh, DD, DD,
                                              (long long)DD * DD, (long long)DD * DD);
    transph_kernel<<<dim3(32, 32, NL), 256>>>(Wk, wkh, DD, DD,
                                              (long long)DD * DD, (long long)DD * DD);
    transph_kernel<<<dim3(32, 32, NL), 256>>>(Wv, wvh, DD, DD,
                                              (long long)DD * DD, (long long)DD * DD);
    transph_kernel<<<dim3(32, 32, NL), 256>>>(Wo, woh, DD, DD,
                                              (long long)DD * DD, (long long)DD * DD);
    transph_kernel<<<dim3(DMLP / 32, 32, NL), 256>>>(W1, w1h, DD, DMLP,
                                                     (long long)DD * DMLP, (long long)DD * DMLP);
    transph_kernel<<<dim3(32, DMLP / 32, NL), 256>>>(W2, w2h, DMLP, DD,
                                                     (long long)DMLP * DD, (long long)DMLP * DD);
    convh_kernel<<<4096, 256>>>((const float4*)emb, (uint2*)embh,
                                (long long)NV * DD / 4);

    embed_kernel<<<SS, 256>>>(ids, emb, x);

    for (int l = 0; l < NL; l++) {
        const size_t wofs = (size_t)l * DD * DD;
        layernorm_kernel<<<SS, 256>>>(x, ln1g + l * DD, ln1b + l * DD, h);

        {
            HPtr3 p;
            p.b0 = wqh + wofs; p.b1 = wkh + wofs; p.b2 = wvh + wofs;
            p.c0 = q; p.c1 = k; p.c2 = v;
            hgemm_kernel<128><<<dim3(SS / 128, DD / 128, 3), 256, SM128>>>(
                h, DD, 0, p, DD, DD, 0,
                SS, DD, DD, 1.f, nullptr, nullptr, 0, 1, 2);
        }

        rope_kernel<<<(SS * NH * 32 + 255) / 256, 256>>>(q, k);

        flash_kernel<<<dim3(SS / 128, NH), 256, FA_SMEM>>>(q, k, v, h);

        hgemm_kernel<64><<<dim3(SS / 128, DD / 64, 1), 256, SM64>>>(
            h, DD, 0, oneh(woh + wofs, x), DD, DD, 0,
            SS, DD, DD, 1.f, nullptr, x, 0, 0, 0);

        layernorm_kernel<<<SS, 256>>>(x, ln2g + l * DD, ln2b + l * DD, h);

        hgemm_kernel<128><<<dim3(SS / 128, DMLP / 128, 1), 256, SM128>>>(
            h, DD, 0, oneh(w1h + (size_t)l * DD * DMLP, mlp), DD, DMLP, 0,
            SS, DMLP, DD, 1.f, b1 + (size_t)l * DMLP, nullptr, 1, 0, 2);

        hgemm_kernel<64><<<dim3(SS / 128, DD / 64, 1), 256, SM64>>>(
            mlp, DMLP, 0, oneh(w2h + (size_t)l * DD * DMLP, x), DMLP, DD, 0,
            SS, DD, DMLP, 1.f, b2 + (size_t)l * DD, x, 0, 0, 0);
    }

    layernorm_kernel<<<SS, 256>>>(x, lnfg, lnfb, h);

    hgemm_kernel<128><<<dim3(SS / 128, (NV + 127) / 128, 1), 256, SM128>>>(
        h, DD, 0, oneh(embh, out), DD, NV, 0,
        SS, NV, DD, 1.f, nullptr, nullptr, 0, 0, 0);
}

// round 16
// speedup vs baseline: 1.9947x; 1.1136x over previous
#include <cuda_runtime.h>
#include <cuda_fp16.h>
#include <math.h>
#include <stdint.h>

#define SS   2048
#define DD   1024
#define NL   4
#define NH   16
#define HDIM 64
#define NV   50257
#define DMLP 4096

// ---------------- scratch ----------------
__device__ float  g_x[SS * DD];
__device__ __half g_h[SS * DD];
__device__ __half g_q[SS * DD];
__device__ __half g_k[SS * DD];
__device__ __half g_v[SS * DD];
__device__ __half g_mlp[SS * DMLP];
__device__ __half g_wqh[(size_t)NL * DD * DD];
__device__ __half g_wkh[(size_t)NL * DD * DD];
__device__ __half g_wvh[(size_t)NL * DD * DD];
__device__ __half g_woh[(size_t)NL * DD * DD];
__device__ __half g_w1h[(size_t)NL * DMLP * DD];
__device__ __half g_w2h[(size_t)NL * DD * DMLP];
__device__ __half g_embh[(size_t)NV * DD];

// ---------------- helpers ----------------
__device__ __forceinline__ unsigned f2tf(float f) {
    unsigned u;
    asm("cvt.rna.tf32.f32 %0, %1;" : "=r"(u) : "f"(f));
    return u;
}
__device__ __forceinline__ float tf32f(float f) {
    return __uint_as_float(f2tf(f));
}
__device__ __forceinline__ unsigned packh(float a, float b) {
    unsigned d;
    asm("cvt.rn.f16x2.f32 %0, %1, %2;" : "=r"(d) : "f"(b), "f"(a));
    return d;
}

// ---------------- weight transpose + half convert: W[K][N] -> Wt[N][K] -----
__global__ void transph_kernel(const float* __restrict__ W, __half* __restrict__ Wt,
                               int K, int N, long long wstride, long long tstride) {
    __shared__ float tile[32][33];
    const float* Wz = W + (size_t)blockIdx.z * wstride;
    __half* Tz = Wt + (size_t)blockIdx.z * tstride;
    int n0 = blockIdx.x * 32, k0 = blockIdx.y * 32;
    int tx = threadIdx.x & 31, ty = threadIdx.x >> 5;
#pragma unroll
    for (int i = 0; i < 4; i++)
        tile[ty + i * 8][tx] = Wz[(size_t)(k0 + ty + i * 8) * N + n0 + tx];
    __syncthreads();
#pragma unroll
    for (int i = 0; i < 4; i++)
        Tz[(size_t)(n0 + ty + i * 8) * K + k0 + tx] = __float2half(tile[tx][ty + i * 8]);
}

// ---------------- straight half convert (emb) ----------------
__global__ void convh_kernel(const float4* __restrict__ in,
                             uint2* __restrict__ out, long long n4) {
    long long i = blockIdx.x * (long long)blockDim.x + threadIdx.x;
    long long stride = (long long)gridDim.x * blockDim.x;
    for (; i < n4; i += stride) {
        float4 t = in[i];
        unsigned lo, hi;
        asm("cvt.rn.f16x2.f32 %0, %1, %2;" : "=r"(lo) : "f"(t.y), "f"(t.x));
        asm("cvt.rn.f16x2.f32 %0, %1, %2;" : "=r"(hi) : "f"(t.w), "f"(t.z));
        out[i] = make_uint2(lo, hi);
    }
}

// ---------------- embedding gather ----------------
__global__ void embed_kernel(const int* __restrict__ ids,
                             const float* __restrict__ emb,
                             float* __restrict__ x) {
    int t = blockIdx.x;
    int id = ids[t];
    if (id < 0) id = 0;
    if (id >= NV) id = NV - 1;
    const float* src = emb + (size_t)id * DD;
    float* dst = x + (size_t)t * DD;
    for (int d = threadIdx.x; d < DD; d += blockDim.x) dst[d] = src[d];
}

// ---------------- layernorm (half out) ----------------
__global__ void layernorm_kernel(const float* __restrict__ x,
                                 const float* __restrict__ g,
                                 const float* __restrict__ b,
                                 __half* __restrict__ out) {
    __shared__ float red[256];
    int row = blockIdx.x;
    const float* xr = x + (size_t)row * DD;
    float s = 0.f;
    for (int d = threadIdx.x; d < DD; d += 256) s += xr[d];
    red[threadIdx.x] = s;
    __syncthreads();
    for (int o = 128; o > 0; o >>= 1) {
        if (threadIdx.x < o) red[threadIdx.x] += red[threadIdx.x + o];
        __syncthreads();
    }
    float mean = red[0] * (1.f / DD);
    __syncthreads();
    float v = 0.f;
    for (int d = threadIdx.x; d < DD; d += 256) {
        float t = xr[d] - mean;
        v += t * t;
    }
    red[threadIdx.x] = v;
    __syncthreads();
    for (int o = 128; o > 0; o >>= 1) {
        if (threadIdx.x < o) red[threadIdx.x] += red[threadIdx.x + o];
        __syncthreads();
    }
    float inv = rsqrtf(red[0] * (1.f / DD) + 1e-5f);
    __half* orow = out + (size_t)row * DD;
    for (int d = threadIdx.x; d < DD; d += 256)
        orow[d] = __float2half((xr[d] - mean) * inv * g[d] + b[d]);
}

// ---------------- RoPE on half q/k ----------------
__global__ void rope_kernel(__half* __restrict__ q, __half* __restrict__ k) {
    int idx = blockIdx.x * blockDim.x + threadIdx.x;
    int i = idx & 31;
    int rest = idx >> 5;
    int h = rest & (NH - 1);
    int t = rest >> 4;
    if (t >= SS) return;
    float inv_freq = powf(10000.f, -(float)i / 32.f);
    float ang = (float)t * inv_freq;
    float c = cosf(ang), s = sinf(ang);
    size_t base = (size_t)t * DD + h * HDIM;
    float x1 = __half2float(q[base + i]), x2 = __half2float(q[base + i + 32]);
    q[base + i]      = __float2half(x1 * c - x2 * s);
    q[base + i + 32] = __float2half(x2 * c + x1 * s);
    float y1 = __half2float(k[base + i]), y2 = __half2float(k[base + i + 32]);
    k[base + i]      = __float2half(y1 * c - y2 * s);
    k[base + i + 32] = __float2half(y2 * c + y1 * s);
}

// ---------------- PTX helpers ----------------
__device__ __forceinline__ void cp16(unsigned dst, const void* src, int bytes) {
    asm volatile("cp.async.cg.shared.global [%0], [%1], 16, %2;"
                 :: "r"(dst), "l"(src), "r"(bytes));
}
__device__ __forceinline__ void cp_commit() {
    asm volatile("cp.async.commit_group;");
}
template <int N>
__device__ __forceinline__ void cp_wait() {
    asm volatile("cp.async.wait_group %0;" :: "n"(N));
}
__device__ __forceinline__ void mma_f16(float c[4], unsigned a0, unsigned a1,
                                        unsigned a2, unsigned a3,
                                        unsigned b0, unsigned b1) {
    asm volatile(
        "mma.sync.aligned.m16n8k16.row.col.f32.f16.f16.f32 "
        "{%0,%1,%2,%3}, {%4,%5,%6,%7}, {%8,%9}, {%0,%1,%2,%3};"
        : "+f"(c[0]), "+f"(c[1]), "+f"(c[2]), "+f"(c[3])
        : "r"(a0), "r"(a1), "r"(a2), "r"(a3), "r"(b0), "r"(b1));
}
__device__ __forceinline__ void ldsm_x4(unsigned& r0, unsigned& r1,
                                        unsigned& r2, unsigned& r3,
                                        unsigned addr) {
    asm volatile("ldmatrix.sync.aligned.m8n8.x4.shared.b16 {%0,%1,%2,%3}, [%4];"
                 : "=r"(r0), "=r"(r1), "=r"(r2), "=r"(r3) : "r"(addr));
}
__device__ __forceinline__ void ldsm_x4_trans(unsigned& r0, unsigned& r1,
                                              unsigned& r2, unsigned& r3,
                                              unsigned addr) {
    asm volatile("ldmatrix.sync.aligned.m8n8.x4.trans.shared.b16 {%0,%1,%2,%3}, [%4];"
                 : "=r"(r0), "=r"(r1), "=r"(r2), "=r"(r3) : "r"(addr));
}

// ================= all-half GEMM: BK=64, 2-stage ring, ldmatrix frags ======
#define BKT2 64
#define APH  72        // 64 + 8 pad; row stride 144B -> ldmatrix conflict-free

struct HPtr3 {
    const __half* b0; const __half* b1; const __half* b2;
    void* c0; void* c1; void* c2;
};

template <int BN>
__global__ void __launch_bounds__(256, 2)
hgemm_kernel(const __half* __restrict__ A, int lda, long long strideA,
             HPtr3 p, int ldb,
             int ldc, long long strideC,
             int M, int N, int K, float alpha,
             const float* __restrict__ bias,
             const float* __restrict__ res,
             int do_gelu, int multiB, int out_mode) {  // 0 f32, 1 f32+tf32, 2 f16
    const int MT  = (BN == 128) ? 4 : 2;
    const int AST = 128 * APH;
    const int BST = BN * APH;
    const int STG = AST + BST;

    extern __shared__ __align__(16) __half dsm[];

    int z = blockIdx.z;
    const __half* B;
    void* C;
    if (multiB) {
        B = (z == 0) ? p.b0 : (z == 1) ? p.b1 : p.b2;
        C = (z == 0) ? p.c0 : (z == 1) ? p.c1 : p.c2;
    } else {
        B = p.b0;
        C = (out_mode == 2) ? (void*)((__half*)p.c0 + (size_t)z * strideC)
                            : (void*)((float*)p.c0 + (size_t)z * strideC);
        if (res) res += (size_t)z * strideC;
    }
    A += (size_t)z * strideA;

    int row0 = blockIdx.x * 128;
    int col0 = blockIdx.y * BN;
    int nk = K / BKT2;

    int tid = threadIdx.x;
    int lane = tid & 31, warp = tid >> 5;
    int l4 = lane & 3, l28 = lane >> 2;
    int mbase, nbase;
    if (BN == 128) { mbase = (warp >> 2) * 64; nbase = (warp & 3) * 32; }
    else           { mbase = (warp >> 1) * 32; nbase = (warp & 1) * 32; }

    unsigned sbase = (unsigned)__cvta_generic_to_shared(dsm);

    int a_lrow = lane & 15;
    int a_lcol = 8 * (lane >> 4);
    int b_lrow = (lane & 7) + 8 * (lane >> 4);
    int b_lcol = 8 * ((lane >> 3) & 1);

    float acc[MT][4][4];
#pragma unroll
    for (int mt = 0; mt < MT; mt++)
#pragma unroll
        for (int nt = 0; nt < 4; nt++)
#pragma unroll
            for (int c = 0; c < 4; c++) acc[mt][nt][c] = 0.f;

    auto prefetch = [&](int s, int k0) {
        unsigned sA = sbase + s * STG * 2;
        unsigned sB = sA + AST * 2;
        // A: 128 rows x 64 halves = 1024 x 16B -> 4 iters of 256
#pragma unroll
        for (int i = 0; i < 4; i++) {
            int lin = i * 256 + tid;
            int m = lin >> 3, f8 = lin & 7;
            cp16(sA + (m * APH + f8 * 8) * 2,
                 A + (size_t)(row0 + m) * lda + k0 + f8 * 8, 16);
        }
#pragma unroll
        for (int i = 0; i < BN / 32; i++) {
            int lin = i * 256 + tid;
            int n = lin >> 3, f8 = lin & 7;
            int gn = col0 + n;
            cp16(sB + (n * APH + f8 * 8) * 2,
                 B + (size_t)gn * ldb + k0 + f8 * 8, (gn < N) ? 16 : 0);
        }
        cp_commit();
    };

    prefetch(0, 0);

    for (int ks = 0; ks < nk; ks++) {
        int cur = ks & 1, nxt = cur ^ 1;
        bool more = (ks + 1) < nk;
        if (more) prefetch(nxt, (ks + 1) * BKT2);

        if (more) cp_wait<1>(); else cp_wait<0>();
        __syncthreads();

        unsigned uA = sbase + cur * STG * 2;
        unsigned uB = uA + AST * 2;

#pragma unroll
        for (int kb = 0; kb < BKT2; kb += 16) {
            unsigned af[MT][4];
#pragma unroll
            for (int mt = 0; mt < MT; mt++) {
                unsigned addr = uA + (((mbase + mt * 16 + a_lrow) * APH) + kb + a_lcol) * 2;
                ldsm_x4(af[mt][0], af[mt][1], af[mt][2], af[mt][3], addr);
            }
            unsigned bf[4][2];
#pragma unroll
            for (int np = 0; np < 2; np++) {
                unsigned addr = uB + (((nbase + np * 16 + b_lrow) * APH) + kb + b_lcol) * 2;
                ldsm_x4(bf[np * 2][0], bf[np * 2][1], bf[np * 2 + 1][0], bf[np * 2 + 1][1], addr);
            }
#pragma unroll
            for (int mt = 0; mt < MT; mt++)
#pragma unroll
                for (int nt = 0; nt < 4; nt++)
                    mma_f16(acc[mt][nt], af[mt][0], af[mt][1], af[mt][2], af[mt][3],
                            bf[nt][0], bf[nt][1]);
        }
        __syncthreads();
    }

#pragma unroll
    for (int mt = 0; mt < MT; mt++) {
#pragma unroll
        for (int nt = 0; nt < 4; nt++) {
#pragma unroll
            for (int c = 0; c < 4; c++) {
                int gr = row0 + mbase + mt * 16 + l28 + ((c >= 2) ? 8 : 0);
                int gc = col0 + nbase + nt * 8 + l4 * 2 + (c & 1);
                if (gc >= N) continue;
                float v = alpha * acc[mt][nt][c];
                if (bias) v += bias[gc];
                if (res) v += res[(size_t)gr * ldc + gc];
                if (do_gelu) v = 0.5f * v * (1.f + erff(v * 0.70710678118654752f));
                size_t idx = (size_t)gr * ldc + gc;
                if (out_mode == 2)      ((__half*)C)[idx] = __float2half(v);
                else if (out_mode == 1) ((float*)C)[idx] = tf32f(v);
                else                    ((float*)C)[idx] = v;
            }
        }
    }
}

static inline HPtr3 oneh(const __half* b, void* c) {
    HPtr3 p; p.b0 = b; p.b1 = nullptr; p.b2 = nullptr;
    p.c0 = c; p.c1 = nullptr; p.c2 = nullptr; return p;
}

#define SM128 (2 * (128 + 128) * APH * 2)   // 73728 B/CTA
#define SM64  (2 * (128 + 64)  * APH * 2)   // 55296 B/CTA

// ================= fp16 fused causal flash attention (R14, proven) =========
#define KPH 72
#define FA_SMEM (2 * 2 * 128 * KPH * 2)

__global__ void __launch_bounds__(256, 2)
flash_kernel(const __half* __restrict__ q, const __half* __restrict__ k,
             const __half* __restrict__ v, __half* __restrict__ o) {
    extern __shared__ __align__(16) __half hsm[];
    __half* Ksm[2] = { hsm, hsm + 128 * KPH };
    unsigned uK[2], uV[2];
    uK[0] = (unsigned)__cvta_generic_to_shared(Ksm[0]);
    uK[1] = (unsigned)__cvta_generic_to_shared(Ksm[1]);
    uV[0] = (unsigned)__cvta_generic_to_shared(hsm + 2 * 128 * KPH);
    uV[1] = (unsigned)__cvta_generic_to_shared(hsm + 3 * 128 * KPH);

    int rb = 15 - blockIdx.x;
    int hb = blockIdx.y * HDIM;
    int row0 = rb * 128;

    int tid = threadIdx.x, lane = tid & 31, w = tid >> 5;
    int l4 = lane & 3, l28 = lane >> 2;
    int rl0 = w * 16 + l28;
    int rl1 = rl0 + 8;
    int grow0 = row0 + rl0, grow1 = row0 + rl1;

    const __half2 sc8 = __float2half2_rn(0.125f);
    unsigned qa[4][4];
#pragma unroll
    for (int c = 0; c < 4; c++) {
        __half2 t0 = __hmul2(*(const __half2*)&q[(size_t)grow0 * DD + hb + 16 * c + 2 * l4], sc8);
        __half2 t1 = __hmul2(*(const __half2*)&q[(size_t)grow1 * DD + hb + 16 * c + 2 * l4], sc8);
        __half2 t2 = __hmul2(*(const __half2*)&q[(size_t)grow0 * DD + hb + 16 * c + 2 * l4 + 8], sc8);
        __half2 t3 = __hmul2(*(const __half2*)&q[(size_t)grow1 * DD + hb + 16 * c + 2 * l4 + 8], sc8);
        qa[c][0] = *(unsigned*)&t0; qa[c][1] = *(unsigned*)&t1;
        qa[c][2] = *(unsigned*)&t2; qa[c][3] = *(unsigned*)&t3;
    }

    float oacc[8][4];
#pragma unroll
    for (int n2 = 0; n2 < 8; n2++)
#pragma unroll
        for (int c = 0; c < 4; c++) oacc[n2][c] = 0.f;
    float mA = -1e30f, mB = -1e30f, lA = 0.f, lB = 0.f;

    auto prefetch = [&](int j, int s) {
#pragma unroll
        for (int i = 0; i < 4; i++) {
            int lin = i * 256 + tid;
            int r = lin >> 3, f = lin & 7;
            cp16(uK[s] + (r * KPH + f * 8) * 2,
                 k + (size_t)(j * 128 + r) * DD + hb + f * 8, 16);
            cp16(uV[s] + (r * KPH + f * 8) * 2,
                 v + (size_t)(j * 128 + r) * DD + hb + f * 8, 16);
        }
        cp_commit();
    };

    prefetch(0, 0);

    for (int j = 0; j <= rb; j++) {
        int s = j & 1;
        bool more = j < rb;
        if (more) prefetch(j + 1, s ^ 1);
        if (more) cp_wait<1>(); else cp_wait<0>();
        __syncthreads();

        float sacc[16][4];
#pragma unroll
        for (int t = 0; t < 16; t++)
#pragma unroll
            for (int c = 0; c < 4; c++) sacc[t][c] = 0.f;
#pragma unroll
        for (int c = 0; c < 4; c++) {
#pragma unroll
            for (int t = 0; t < 16; t++) {
                unsigned b0 = *(const unsigned*)&Ksm[s][(t * 8 + l28) * KPH + 16 * c + 2 * l4];
                unsigned b1 = *(const unsigned*)&Ksm[s][(t * 8 + l28) * KPH + 16 * c + 2 * l4 + 8];
                mma_f16(sacc[t], qa[c][0], qa[c][1], qa[c][2], qa[c][3], b0, b1);
            }
        }

        if (j == rb) {
#pragma unroll
            for (int t = 0; t < 16; t++) {
                int cb = 8 * t + 2 * l4;
                if (cb     > rl0) sacc[t][0] = -1e30f;
                if (cb + 1 > rl0) sacc[t][1] = -1e30f;
                if (cb     > rl1) sacc[t][2] = -1e30f;
                if (cb + 1 > rl1) sacc[t][3] = -1e30f;
            }
        }

        float tmA = -1e30f, tmB = -1e30f;
#pragma unroll
        for (int t = 0; t < 16; t++) {
            tmA = fmaxf(tmA, fmaxf(sacc[t][0], sacc[t][1]));
            tmB = fmaxf(tmB, fmaxf(sacc[t][2], sacc[t][3]));
        }
        tmA = fmaxf(tmA, __shfl_xor_sync(0xffffffffu, tmA, 1));
        tmA = fmaxf(tmA, __shfl_xor_sync(0xffffffffu, tmA, 2));
        tmB = fmaxf(tmB, __shfl_xor_sync(0xffffffffu, tmB, 1));
        tmB = fmaxf(tmB, __shfl_xor_sync(0xffffffffu, tmB, 2));

        float mnA = fmaxf(mA, tmA), mnB = fmaxf(mB, tmB);
        float cA = __expf(mA - mnA), cB = __expf(mB - mnB);
        mA = mnA; mB = mnB;

        float tsA = 0.f, tsB = 0.f;
#pragma unroll
        for (int t = 0; t < 16; t++) {
            sacc[t][0] = __expf(sacc[t][0] - mA);
            sacc[t][1] = __expf(sacc[t][1] - mA);
            sacc[t][2] = __expf(sacc[t][2] - mB);
            sacc[t][3] = __expf(sacc[t][3] - mB);
            tsA += sacc[t][0] + sacc[t][1];
            tsB += sacc[t][2] + sacc[t][3];
        }
        tsA += __shfl_xor_sync(0xffffffffu, tsA, 1);
        tsA += __shfl_xor_sync(0xffffffffu, tsA, 2);
        tsB += __shfl_xor_sync(0xffffffffu, tsB, 1);
        tsB += __shfl_xor_sync(0xffffffffu, tsB, 2);
        lA = lA * cA + tsA;
        lB = lB * cB + tsB;

#pragma unroll
        for (int n2 = 0; n2 < 8; n2++) {
            oacc[n2][0] *= cA; oacc[n2][1] *= cA;
            oacc[n2][2] *= cB; oacc[n2][3] *= cB;
        }

#pragma unroll
        for (int kc = 0; kc < 8; kc++) {
            unsigned a0 = packh(sacc[2 * kc][0],     sacc[2 * kc][1]);
            unsigned a1 = packh(sacc[2 * kc][2],     sacc[2 * kc][3]);
            unsigned a2 = packh(sacc[2 * kc + 1][0], sacc[2 * kc + 1][1]);
            unsigned a3 = packh(sacc[2 * kc + 1][2], sacc[2 * kc + 1][3]);
            unsigned vrow = (unsigned)(16 * kc + (lane & 7) + 8 * ((lane >> 3) & 1));
#pragma unroll
            for (int pq = 0; pq < 4; pq++) {
                unsigned b0, b1, b2, b3;
                unsigned addr = uV[s] + (vrow * KPH + pq * 16 + 8 * (lane >> 4)) * 2;
                ldsm_x4_trans(b0, b1, b2, b3, addr);
                mma_f16(oacc[2 * pq],     a0, a1, a2, a3, b0, b1);
                mma_f16(oacc[2 * pq + 1], a0, a1, a2, a3, b2, b3);
            }
        }
        __syncthreads();
    }

    float iA = 1.f / lA, iB = 1.f / lB;
#pragma unroll
    for (int n2 = 0; n2 < 8; n2++) {
        *(__half2*)&o[(size_t)grow0 * DD + hb + n2 * 8 + 2 * l4] =
            __floats2half2_rn(oacc[n2][0] * iA, oacc[n2][1] * iA);
        *(__half2*)&o[(size_t)grow1 * DD + hb + n2 * 8 + 2 * l4] =
            __floats2half2_rn(oacc[n2][2] * iB, oacc[n2][3] * iB);
    }
}

// ---------------- host orchestration ----------------
extern "C" void kernel_launch(void* const* d_in, const int* in_sizes, int n_in,
                              void* d_out, int out_size) {
    const int*   ids  = (const int*)d_in[0];
    const float* emb  = (const float*)d_in[1];
    const float* Wq   = (const float*)d_in[2];
    const float* Wk   = (const float*)d_in[3];
    const float* Wv   = (const float*)d_in[4];
    const float* Wo   = (const float*)d_in[5];
    const float* ln1g = (const float*)d_in[6];
    const float* ln1b = (const float*)d_in[7];
    const float* ln2g = (const float*)d_in[8];
    const float* ln2b = (const float*)d_in[9];
    const float* W1   = (const float*)d_in[10];
    const float* b1   = (const float*)d_in[11];
    const float* W2   = (const float*)d_in[12];
    const float* b2   = (const float*)d_in[13];
    const float* lnfg = (const float*)d_in[14];
    const float* lnfb = (const float*)d_in[15];
    float* out = (float*)d_out;

    float *x;
    __half *h, *q, *k, *v, *mlp, *wqh, *wkh, *wvh, *woh, *w1h, *w2h, *embh;
    cudaGetSymbolAddress((void**)&x,    g_x);
    cudaGetSymbolAddress((void**)&h,    g_h);
    cudaGetSymbolAddress((void**)&q,    g_q);
    cudaGetSymbolAddress((void**)&k,    g_k);
    cudaGetSymbolAddress((void**)&v,    g_v);
    cudaGetSymbolAddress((void**)&mlp,  g_mlp);
    cudaGetSymbolAddress((void**)&wqh,  g_wqh);
    cudaGetSymbolAddress((void**)&wkh,  g_wkh);
    cudaGetSymbolAddress((void**)&wvh,  g_wvh);
    cudaGetSymbolAddress((void**)&woh,  g_woh);
    cudaGetSymbolAddress((void**)&w1h,  g_w1h);
    cudaGetSymbolAddress((void**)&w2h,  g_w2h);
    cudaGetSymbolAddress((void**)&embh, g_embh);

    cudaFuncSetAttribute(flash_kernel,
                         cudaFuncAttributeMaxDynamicSharedMemorySize, FA_SMEM);
    cudaFuncSetAttribute(hgemm_kernel<128>,
                         cudaFuncAttributeMaxDynamicSharedMemorySize, SM128);
    cudaFuncSetAttribute(hgemm_kernel<64>,
                         cudaFuncAttributeMaxDynamicSharedMemorySize, SM64);

    transph_kernel<<<dim3(32, 32, NL), 256>>>(Wq, wqh, DD, DD,
                                              (long long)DD * DD, (long long)DD * DD);
    transph_kernel<<<dim3(32, 32, NL), 256>>>(Wk, wkh, DD, DD,
                                              (long long)DD * DD, (long long)DD * DD);
    transph_kernel<<<dim3(32, 32, NL), 256>>>(Wv, wvh, DD, DD,
                                              (long long)DD * DD, (long long)DD * DD);
    transph_kernel<<<dim3(32, 32, NL), 256>>>(Wo, woh, DD, DD,
                                              (long long)DD * DD, (long long)DD * DD);
    transph_kernel<<<dim3(DMLP / 32, 32, NL), 256>>>(W1, w1h, DD, DMLP,
                                                     (long long)DD * DMLP, (long long)DD * DMLP);
    transph_kernel<<<dim3(32, DMLP / 32, NL), 256>>>(W2, w2h, DMLP, DD,
                                                     (long long)DMLP * DD, (long long)DMLP * DD);
    convh_kernel<<<4096, 256>>>((const float4*)emb, (uint2*)embh,
                                (long long)NV * DD / 4);

    embed_kernel<<<SS, 256>>>(ids, emb, x);

    for (int l = 0; l < NL; l++) {
        const size_t wofs = (size_t)l * DD * DD;
        layernorm_kernel<<<SS, 256>>>(x, ln1g + l * DD, ln1b + l * DD, h);

        {
            HPtr3 p;
            p.b0 = wqh + wofs; p.b1 = wkh + wofs; p.b2 = wvh + wofs;
            p.c0 = q; p.c1 = k; p.c2 = v;
            hgemm_kernel<128><<<dim3(SS / 128, DD / 128, 3), 256, SM128>>>(
                h, DD, 0, p, DD, DD, 0,
                SS, DD, DD, 1.f, nullptr, nullptr, 0, 1, 2);
        }

        rope_kernel<<<(SS * NH * 32 + 255) / 256, 256>>>(q, k);

        flash_kernel<<<dim3(SS / 128, NH), 256, FA_SMEM>>>(q, k, v, h);

        hgemm_kernel<64><<<dim3(SS / 128, DD / 64, 1), 256, SM64>>>(
            h, DD, 0, oneh(woh + wofs, x), DD, DD, 0,
            SS, DD, DD, 1.f, nullptr, x, 0, 0, 0);

        layernorm_kernel<<<SS, 256>>>(x, ln2g + l * DD, ln2b + l * DD, h);

        hgemm_kernel<128><<<dim3(SS / 128, DMLP / 128, 1), 256, SM128>>>(
            h, DD, 0, oneh(w1h + (size_t)l * DD * DMLP, mlp), DD, DMLP, 0,
            SS, DMLP, DD, 1.f, b1 + (size_t)l * DMLP, nullptr, 1, 0, 2);

        hgemm_kernel<64><<<dim3(SS / 128, DD / 64, 1), 256, SM64>>>(
            mlp, DMLP, 0, oneh(w2h + (size_t)l * DD * DMLP, x), DMLP, DD, 0,
            SS, DD, DMLP, 1.f, b2 + (size_t)l * DD, x, 0, 0, 0);
    }

    layernorm_kernel<<<SS, 256>>>(x, lnfg, lnfb, h);

    hgemm_kernel<128><<<dim3(SS / 128, (NV + 127) / 128, 1), 256, SM128>>>(
        h, DD, 0, oneh(embh, out), DD, NV, 0,
        SS, NV, DD, 1.f, nullptr, nullptr, 0, 0, 0);
}

// round 17
// speedup vs baseline: 2.0504x; 1.0280x over previous
#include <cuda_runtime.h>
#include <cuda_fp16.h>
#include <math.h>
#include <stdint.h>

#define SS   2048
#define DD   1024
#define NL   4
#define NH   16
#define HDIM 64
#define NV   50257
#define DMLP 4096

// ---------------- scratch ----------------
__device__ float  g_x[SS * DD];
__device__ __half g_h[SS * DD];
__device__ __half g_q[SS * DD];
__device__ __half g_k[SS * DD];
__device__ __half g_v[SS * DD];
__device__ __half g_mlp[SS * DMLP];
__device__ __half g_wqh[(size_t)NL * DD * DD];
__device__ __half g_wkh[(size_t)NL * DD * DD];
__device__ __half g_wvh[(size_t)NL * DD * DD];
__device__ __half g_woh[(size_t)NL * DD * DD];
__device__ __half g_w1h[(size_t)NL * DMLP * DD];
__device__ __half g_w2h[(size_t)NL * DD * DMLP];
__device__ __half g_embh[(size_t)NV * DD];

// ---------------- helpers ----------------
__device__ __forceinline__ unsigned f2tf(float f) {
    unsigned u;
    asm("cvt.rna.tf32.f32 %0, %1;" : "=r"(u) : "f"(f));
    return u;
}
__device__ __forceinline__ float tf32f(float f) {
    return __uint_as_float(f2tf(f));
}
__device__ __forceinline__ unsigned packh(float a, float b) {
    unsigned d;
    asm("cvt.rn.f16x2.f32 %0, %1, %2;" : "=r"(d) : "f"(b), "f"(a));
    return d;
}

// ---------------- weight transpose + half convert: W[K][N] -> Wt[N][K] -----
__global__ void transph_kernel(const float* __restrict__ W, __half* __restrict__ Wt,
                               int K, int N, long long wstride, long long tstride) {
    __shared__ float tile[32][33];
    const float* Wz = W + (size_t)blockIdx.z * wstride;
    __half* Tz = Wt + (size_t)blockIdx.z * tstride;
    int n0 = blockIdx.x * 32, k0 = blockIdx.y * 32;
    int tx = threadIdx.x & 31, ty = threadIdx.x >> 5;
#pragma unroll
    for (int i = 0; i < 4; i++)
        tile[ty + i * 8][tx] = Wz[(size_t)(k0 + ty + i * 8) * N + n0 + tx];
    __syncthreads();
#pragma unroll
    for (int i = 0; i < 4; i++)
        Tz[(size_t)(n0 + ty + i * 8) * K + k0 + tx] = __float2half(tile[tx][ty + i * 8]);
}

// ---------------- straight half convert (emb) ----------------
__global__ void convh_kernel(const float4* __restrict__ in,
                             uint2* __restrict__ out, long long n4) {
    long long i = blockIdx.x * (long long)blockDim.x + threadIdx.x;
    long long stride = (long long)gridDim.x * blockDim.x;
    for (; i < n4; i += stride) {
        float4 t = in[i];
        unsigned lo, hi;
        asm("cvt.rn.f16x2.f32 %0, %1, %2;" : "=r"(lo) : "f"(t.y), "f"(t.x));
        asm("cvt.rn.f16x2.f32 %0, %1, %2;" : "=r"(hi) : "f"(t.w), "f"(t.z));
        out[i] = make_uint2(lo, hi);
    }
}

// ---------------- embedding gather ----------------
__global__ void embed_kernel(const int* __restrict__ ids,
                             const float* __restrict__ emb,
                             float* __restrict__ x) {
    int t = blockIdx.x;
    int id = ids[t];
    if (id < 0) id = 0;
    if (id >= NV) id = NV - 1;
    const float* src = emb + (size_t)id * DD;
    float* dst = x + (size_t)t * DD;
    for (int d = threadIdx.x; d < DD; d += blockDim.x) dst[d] = src[d];
}

// ---------------- layernorm (half out) ----------------
__global__ void layernorm_kernel(const float* __restrict__ x,
                                 const float* __restrict__ g,
                                 const float* __restrict__ b,
                                 __half* __restrict__ out) {
    __shared__ float red[256];
    int row = blockIdx.x;
    const float* xr = x + (size_t)row * DD;
    float s = 0.f;
    for (int d = threadIdx.x; d < DD; d += 256) s += xr[d];
    red[threadIdx.x] = s;
    __syncthreads();
    for (int o = 128; o > 0; o >>= 1) {
        if (threadIdx.x < o) red[threadIdx.x] += red[threadIdx.x + o];
        __syncthreads();
    }
    float mean = red[0] * (1.f / DD);
    __syncthreads();
    float v = 0.f;
    for (int d = threadIdx.x; d < DD; d += 256) {
        float t = xr[d] - mean;
        v += t * t;
    }
    red[threadIdx.x] = v;
    __syncthreads();
    for (int o = 128; o > 0; o >>= 1) {
        if (threadIdx.x < o) red[threadIdx.x] += red[threadIdx.x + o];
        __syncthreads();
    }
    float inv = rsqrtf(red[0] * (1.f / DD) + 1e-5f);
    __half* orow = out + (size_t)row * DD;
    for (int d = threadIdx.x; d < DD; d += 256)
        orow[d] = __float2half((xr[d] - mean) * inv * g[d] + b[d]);
}

// ---------------- RoPE on half q/k ----------------
__global__ void rope_kernel(__half* __restrict__ q, __half* __restrict__ k) {
    int idx = blockIdx.x * blockDim.x + threadIdx.x;
    int i = idx & 31;
    int rest = idx >> 5;
    int h = rest & (NH - 1);
    int t = rest >> 4;
    if (t >= SS) return;
    float inv_freq = powf(10000.f, -(float)i / 32.f);
    float ang = (float)t * inv_freq;
    float c = cosf(ang), s = sinf(ang);
    size_t base = (size_t)t * DD + h * HDIM;
    float x1 = __half2float(q[base + i]), x2 = __half2float(q[base + i + 32]);
    q[base + i]      = __float2half(x1 * c - x2 * s);
    q[base + i + 32] = __float2half(x2 * c + x1 * s);
    float y1 = __half2float(k[base + i]), y2 = __half2float(k[base + i + 32]);
    k[base + i]      = __float2half(y1 * c - y2 * s);
    k[base + i + 32] = __float2half(y2 * c + y1 * s);
}

// ---------------- PTX helpers ----------------
__device__ __forceinline__ void cp16(unsigned dst, const void* src, int bytes) {
    asm volatile("cp.async.cg.shared.global [%0], [%1], 16, %2;"
                 :: "r"(dst), "l"(src), "r"(bytes));
}
__device__ __forceinline__ void cp_commit() {
    asm volatile("cp.async.commit_group;");
}
template <int N>
__device__ __forceinline__ void cp_wait() {
    asm volatile("cp.async.wait_group %0;" :: "n"(N));
}
__device__ __forceinline__ void mma_f16(float c[4], unsigned a0, unsigned a1,
                                        unsigned a2, unsigned a3,
                                        unsigned b0, unsigned b1) {
    asm volatile(
        "mma.sync.aligned.m16n8k16.row.col.f32.f16.f16.f32 "
        "{%0,%1,%2,%3}, {%4,%5,%6,%7}, {%8,%9}, {%0,%1,%2,%3};"
        : "+f"(c[0]), "+f"(c[1]), "+f"(c[2]), "+f"(c[3])
        : "r"(a0), "r"(a1), "r"(a2), "r"(a3), "r"(b0), "r"(b1));
}
__device__ __forceinline__ void ldsm_x4(unsigned& r0, unsigned& r1,
                                        unsigned& r2, unsigned& r3,
                                        unsigned addr) {
    asm volatile("ldmatrix.sync.aligned.m8n8.x4.shared.b16 {%0,%1,%2,%3}, [%4];"
                 : "=r"(r0), "=r"(r1), "=r"(r2), "=r"(r3) : "r"(addr));
}
__device__ __forceinline__ void ldsm_x4_trans(unsigned& r0, unsigned& r1,
                                              unsigned& r2, unsigned& r3,
                                              unsigned addr) {
    asm volatile("ldmatrix.sync.aligned.m8n8.x4.trans.shared.b16 {%0,%1,%2,%3}, [%4];"
                 : "=r"(r0), "=r"(r1), "=r"(r2), "=r"(r3) : "r"(addr));
}

// ================= all-half GEMM: BK=64, 2-stage ring, ldmatrix (R16) ======
#define BKT2 64
#define APH  72

struct HPtr3 {
    const __half* b0; const __half* b1; const __half* b2;
    void* c0; void* c1; void* c2;
};

template <int BN>
__global__ void __launch_bounds__(256, 2)
hgemm_kernel(const __half* __restrict__ A, int lda, long long strideA,
             HPtr3 p, int ldb,
             int ldc, long long strideC,
             int M, int N, int K, float alpha,
             const float* __restrict__ bias,
             const float* __restrict__ res,
             int do_gelu, int multiB, int out_mode) {
    const int MT  = (BN == 128) ? 4 : 2;
    const int AST = 128 * APH;
    const int BST = BN * APH;
    const int STG = AST + BST;

    extern __shared__ __align__(16) __half dsm[];

    int z = blockIdx.z;
    const __half* B;
    void* C;
    if (multiB) {
        B = (z == 0) ? p.b0 : (z == 1) ? p.b1 : p.b2;
        C = (z == 0) ? p.c0 : (z == 1) ? p.c1 : p.c2;
    } else {
        B = p.b0;
        C = (out_mode == 2) ? (void*)((__half*)p.c0 + (size_t)z * strideC)
                            : (void*)((float*)p.c0 + (size_t)z * strideC);
        if (res) res += (size_t)z * strideC;
    }
    A += (size_t)z * strideA;

    int row0 = blockIdx.x * 128;
    int col0 = blockIdx.y * BN;
    int nk = K / BKT2;

    int tid = threadIdx.x;
    int lane = tid & 31, warp = tid >> 5;
    int l4 = lane & 3, l28 = lane >> 2;
    int mbase, nbase;
    if (BN == 128) { mbase = (warp >> 2) * 64; nbase = (warp & 3) * 32; }
    else           { mbase = (warp >> 1) * 32; nbase = (warp & 1) * 32; }

    unsigned sbase = (unsigned)__cvta_generic_to_shared(dsm);

    int a_lrow = lane & 15;
    int a_lcol = 8 * (lane >> 4);
    int b_lrow = (lane & 7) + 8 * (lane >> 4);
    int b_lcol = 8 * ((lane >> 3) & 1);

    float acc[MT][4][4];
#pragma unroll
    for (int mt = 0; mt < MT; mt++)
#pragma unroll
        for (int nt = 0; nt < 4; nt++)
#pragma unroll
            for (int c = 0; c < 4; c++) acc[mt][nt][c] = 0.f;

    auto prefetch = [&](int s, int k0) {
        unsigned sA = sbase + s * STG * 2;
        unsigned sB = sA + AST * 2;
#pragma unroll
        for (int i = 0; i < 4; i++) {
            int lin = i * 256 + tid;
            int m = lin >> 3, f8 = lin & 7;
            cp16(sA + (m * APH + f8 * 8) * 2,
                 A + (size_t)(row0 + m) * lda + k0 + f8 * 8, 16);
        }
#pragma unroll
        for (int i = 0; i < BN / 32; i++) {
            int lin = i * 256 + tid;
            int n = lin >> 3, f8 = lin & 7;
            int gn = col0 + n;
            cp16(sB + (n * APH + f8 * 8) * 2,
                 B + (size_t)gn * ldb + k0 + f8 * 8, (gn < N) ? 16 : 0);
        }
        cp_commit();
    };

    prefetch(0, 0);

    for (int ks = 0; ks < nk; ks++) {
        int cur = ks & 1, nxt = cur ^ 1;
        bool more = (ks + 1) < nk;
        if (more) prefetch(nxt, (ks + 1) * BKT2);

        if (more) cp_wait<1>(); else cp_wait<0>();
        __syncthreads();

        unsigned uA = sbase + cur * STG * 2;
        unsigned uB = uA + AST * 2;

#pragma unroll
        for (int kb = 0; kb < BKT2; kb += 16) {
            unsigned af[MT][4];
#pragma unroll
            for (int mt = 0; mt < MT; mt++) {
                unsigned addr = uA + (((mbase + mt * 16 + a_lrow) * APH) + kb + a_lcol) * 2;
                ldsm_x4(af[mt][0], af[mt][1], af[mt][2], af[mt][3], addr);
            }
            unsigned bf[4][2];
#pragma unroll
            for (int np = 0; np < 2; np++) {
                unsigned addr = uB + (((nbase + np * 16 + b_lrow) * APH) + kb + b_lcol) * 2;
                ldsm_x4(bf[np * 2][0], bf[np * 2][1], bf[np * 2 + 1][0], bf[np * 2 + 1][1], addr);
            }
#pragma unroll
            for (int mt = 0; mt < MT; mt++)
#pragma unroll
                for (int nt = 0; nt < 4; nt++)
                    mma_f16(acc[mt][nt], af[mt][0], af[mt][1], af[mt][2], af[mt][3],
                            bf[nt][0], bf[nt][1]);
        }
        __syncthreads();
    }

#pragma unroll
    for (int mt = 0; mt < MT; mt++) {
#pragma unroll
        for (int nt = 0; nt < 4; nt++) {
#pragma unroll
            for (int c = 0; c < 4; c++) {
                int gr = row0 + mbase + mt * 16 + l28 + ((c >= 2) ? 8 : 0);
                int gc = col0 + nbase + nt * 8 + l4 * 2 + (c & 1);
                if (gc >= N) continue;
                float v = alpha * acc[mt][nt][c];
                if (bias) v += bias[gc];
                if (res) v += res[(size_t)gr * ldc + gc];
                if (do_gelu) v = 0.5f * v * (1.f + erff(v * 0.70710678118654752f));
                size_t idx = (size_t)gr * ldc + gc;
                if (out_mode == 2)      ((__half*)C)[idx] = __float2half(v);
                else if (out_mode == 1) ((float*)C)[idx] = tf32f(v);
                else                    ((float*)C)[idx] = v;
            }
        }
    }
}

static inline HPtr3 oneh(const __half* b, void* c) {
    HPtr3 p; p.b0 = b; p.b1 = nullptr; p.b2 = nullptr;
    p.c0 = c; p.c1 = nullptr; p.c2 = nullptr; return p;
}

#define SM128 (2 * (128 + 128) * APH * 2)
#define SM64  (2 * (128 + 64)  * APH * 2)

// ================= fp16 fused causal flash attention (R14, proven) =========
#define KPH 72
#define FA_SMEM (2 * 2 * 128 * KPH * 2)

__global__ void __launch_bounds__(256, 2)
flash_kernel(const __half* __restrict__ q, const __half* __restrict__ k,
             const __half* __restrict__ v, __half* __restrict__ o) {
    extern __shared__ __align__(16) __half hsm[];
    __half* Ksm[2] = { hsm, hsm + 128 * KPH };
    unsigned uK[2], uV[2];
    uK[0] = (unsigned)__cvta_generic_to_shared(Ksm[0]);
    uK[1] = (unsigned)__cvta_generic_to_shared(Ksm[1]);
    uV[0] = (unsigned)__cvta_generic_to_shared(hsm + 2 * 128 * KPH);
    uV[1] = (unsigned)__cvta_generic_to_shared(hsm + 3 * 128 * KPH);

    int rb = 15 - blockIdx.x;
    int hb = blockIdx.y * HDIM;
    int row0 = rb * 128;

    int tid = threadIdx.x, lane = tid & 31, w = tid >> 5;
    int l4 = lane & 3, l28 = lane >> 2;
    int rl0 = w * 16 + l28;
    int rl1 = rl0 + 8;
    int grow0 = row0 + rl0, grow1 = row0 + rl1;

    const __half2 sc8 = __float2half2_rn(0.125f);
    unsigned qa[4][4];
#pragma unroll
    for (int c = 0; c < 4; c++) {
        __half2 t0 = __hmul2(*(const __half2*)&q[(size_t)grow0 * DD + hb + 16 * c + 2 * l4], sc8);
        __half2 t1 = __hmul2(*(const __half2*)&q[(size_t)grow1 * DD + hb + 16 * c + 2 * l4], sc8);
        __half2 t2 = __hmul2(*(const __half2*)&q[(size_t)grow0 * DD + hb + 16 * c + 2 * l4 + 8], sc8);
        __half2 t3 = __hmul2(*(const __half2*)&q[(size_t)grow1 * DD + hb + 16 * c + 2 * l4 + 8], sc8);
        qa[c][0] = *(unsigned*)&t0; qa[c][1] = *(unsigned*)&t1;
        qa[c][2] = *(unsigned*)&t2; qa[c][3] = *(unsigned*)&t3;
    }

    float oacc[8][4];
#pragma unroll
    for (int n2 = 0; n2 < 8; n2++)
#pragma unroll
        for (int c = 0; c < 4; c++) oacc[n2][c] = 0.f;
    float mA = -1e30f, mB = -1e30f, lA = 0.f, lB = 0.f;

    auto prefetch = [&](int j, int s) {
#pragma unroll
        for (int i = 0; i < 4; i++) {
            int lin = i * 256 + tid;
            int r = lin >> 3, f = lin & 7;
            cp16(uK[s] + (r * KPH + f * 8) * 2,
                 k + (size_t)(j * 128 + r) * DD + hb + f * 8, 16);
            cp16(uV[s] + (r * KPH + f * 8) * 2,
                 v + (size_t)(j * 128 + r) * DD + hb + f * 8, 16);
        }
        cp_commit();
    };

    prefetch(0, 0);

    for (int j = 0; j <= rb; j++) {
        int s = j & 1;
        bool more = j < rb;
        if (more) prefetch(j + 1, s ^ 1);
        if (more) cp_wait<1>(); else cp_wait<0>();
        __syncthreads();

        float sacc[16][4];
#pragma unroll
        for (int t = 0; t < 16; t++)
#pragma unroll
            for (int c = 0; c < 4; c++) sacc[t][c] = 0.f;
#pragma unroll
        for (int c = 0; c < 4; c++) {
#pragma unroll
            for (int t = 0; t < 16; t++) {
                unsigned b0 = *(const unsigned*)&Ksm[s][(t * 8 + l28) * KPH + 16 * c + 2 * l4];
                unsigned b1 = *(const unsigned*)&Ksm[s][(t * 8 + l28) * KPH + 16 * c + 2 * l4 + 8];
                mma_f16(sacc[t], qa[c][0], qa[c][1], qa[c][2], qa[c][3], b0, b1);
            }
        }

        if (j == rb) {
#pragma unroll
            for (int t = 0; t < 16; t++) {
                int cb = 8 * t + 2 * l4;
                if (cb     > rl0) sacc[t][0] = -1e30f;
                if (cb + 1 > rl0) sacc[t][1] = -1e30f;
                if (cb     > rl1) sacc[t][2] = -1e30f;
                if (cb + 1 > rl1) sacc[t][3] = -1e30f;
            }
        }

        float tmA = -1e30f, tmB = -1e30f;
#pragma unroll
        for (int t = 0; t < 16; t++) {
            tmA = fmaxf(tmA, fmaxf(sacc[t][0], sacc[t][1]));
            tmB = fmaxf(tmB, fmaxf(sacc[t][2], sacc[t][3]));
        }
        tmA = fmaxf(tmA, __shfl_xor_sync(0xffffffffu, tmA, 1));
        tmA = fmaxf(tmA, __shfl_xor_sync(0xffffffffu, tmA, 2));
        tmB = fmaxf(tmB, __shfl_xor_sync(0xffffffffu, tmB, 1));
        tmB = fmaxf(tmB, __shfl_xor_sync(0xffffffffu, tmB, 2));

        float mnA = fmaxf(mA, tmA), mnB = fmaxf(mB, tmB);
        float cA = __expf(mA - mnA), cB = __expf(mB - mnB);
        mA = mnA; mB = mnB;

        float tsA = 0.f, tsB = 0.f;
#pragma unroll
        for (int t = 0; t < 16; t++) {
            sacc[t][0] = __expf(sacc[t][0] - mA);
            sacc[t][1] = __expf(sacc[t][1] - mA);
            sacc[t][2] = __expf(sacc[t][2] - mB);
            sacc[t][3] = __expf(sacc[t][3] - mB);
            tsA += sacc[t][0] + sacc[t][1];
            tsB += sacc[t][2] + sacc[t][3];
        }
        tsA += __shfl_xor_sync(0xffffffffu, tsA, 1);
        tsA += __shfl_xor_sync(0xffffffffu, tsA, 2);
        tsB += __shfl_xor_sync(0xffffffffu, tsB, 1);
        tsB += __shfl_xor_sync(0xffffffffu, tsB, 2);
        lA = lA * cA + tsA;
        lB = lB * cB + tsB;

#pragma unroll
        for (int n2 = 0; n2 < 8; n2++) {
            oacc[n2][0] *= cA; oacc[n2][1] *= cA;
            oacc[n2][2] *= cB; oacc[n2][3] *= cB;
        }

#pragma unroll
        for (int kc = 0; kc < 8; kc++) {
            unsigned a0 = packh(sacc[2 * kc][0],     sacc[2 * kc][1]);
            unsigned a1 = packh(sacc[2 * kc][2],     sacc[2 * kc][3]);
            unsigned a2 = packh(sacc[2 * kc + 1][0], sacc[2 * kc + 1][1]);
            unsigned a3 = packh(sacc[2 * kc + 1][2], sacc[2 * kc + 1][3]);
            unsigned vrow = (unsigned)(16 * kc + (lane & 7) + 8 * ((lane >> 3) & 1));
#pragma unroll
            for (int pq = 0; pq < 4; pq++) {
                unsigned b0, b1, b2, b3;
                unsigned addr = uV[s] + (vrow * KPH + pq * 16 + 8 * (lane >> 4)) * 2;
                ldsm_x4_trans(b0, b1, b2, b3, addr);
                mma_f16(oacc[2 * pq],     a0, a1, a2, a3, b0, b1);
                mma_f16(oacc[2 * pq + 1], a0, a1, a2, a3, b2, b3);
            }
        }
        __syncthreads();
    }

    float iA = 1.f / lA, iB = 1.f / lB;
#pragma unroll
    for (int n2 = 0; n2 < 8; n2++) {
        *(__half2*)&o[(size_t)grow0 * DD + hb + n2 * 8 + 2 * l4] =
            __floats2half2_rn(oacc[n2][0] * iA, oacc[n2][1] * iA);
        *(__half2*)&o[(size_t)grow1 * DD + hb + n2 * 8 + 2 * l4] =
            __floats2half2_rn(oacc[n2][2] * iB, oacc[n2][3] * iB);
    }
}

// ---------------- host orchestration (converters forked to side stream) ----
extern "C" void kernel_launch(void* const* d_in, const int* in_sizes, int n_in,
                              void* d_out, int out_size) {
    const int*   ids  = (const int*)d_in[0];
    const float* emb  = (const float*)d_in[1];
    const float* Wq   = (const float*)d_in[2];
    const float* Wk   = (const float*)d_in[3];
    const float* Wv   = (const float*)d_in[4];
    const float* Wo   = (const float*)d_in[5];
    const float* ln1g = (const float*)d_in[6];
    const float* ln1b = (const float*)d_in[7];
    const float* ln2g = (const float*)d_in[8];
    const float* ln2b = (const float*)d_in[9];
    const float* W1   = (const float*)d_in[10];
    const float* b1   = (const float*)d_in[11];
    const float* W2   = (const float*)d_in[12];
    const float* b2   = (const float*)d_in[13];
    const float* lnfg = (const float*)d_in[14];
    const float* lnfb = (const float*)d_in[15];
    float* out = (float*)d_out;

    float *x;
    __half *h, *q, *k, *v, *mlp, *wqh, *wkh, *wvh, *woh, *w1h, *w2h, *embh;
    cudaGetSymbolAddress((void**)&x,    g_x);
    cudaGetSymbolAddress((void**)&h,    g_h);
    cudaGetSymbolAddress((void**)&q,    g_q);
    cudaGetSymbolAddress((void**)&k,    g_k);
    cudaGetSymbolAddress((void**)&v,    g_v);
    cudaGetSymbolAddress((void**)&mlp,  g_mlp);
    cudaGetSymbolAddress((void**)&wqh,  g_wqh);
    cudaGetSymbolAddress((void**)&wkh,  g_wkh);
    cudaGetSymbolAddress((void**)&wvh,  g_wvh);
    cudaGetSymbolAddress((void**)&woh,  g_woh);
    cudaGetSymbolAddress((void**)&w1h,  g_w1h);
    cudaGetSymbolAddress((void**)&w2h,  g_w2h);
    cudaGetSymbolAddress((void**)&embh, g_embh);

    cudaFuncSetAttribute(flash_kernel,
                         cudaFuncAttributeMaxDynamicSharedMemorySize, FA_SMEM);
    cudaFuncSetAttribute(hgemm_kernel<128>,
                         cudaFuncAttributeMaxDynamicSharedMemorySize, SM128);
    cudaFuncSetAttribute(hgemm_kernel<64>,
                         cudaFuncAttributeMaxDynamicSharedMemorySize, SM64);

    // --- fork a side stream inside the capture for the converter chain ---
    // kernel_launch runs only for correctness + capture (graph replays don't
    // re-enter), so per-call stream/event creation does not grow unbounded.
    cudaStream_t side;
    cudaStreamCreateWithFlags(&side, cudaStreamNonBlocking);
    cudaEvent_t eFork, eQKV, eWo, eW1, eW2, eEmb;
    cudaEventCreateWithFlags(&eFork, cudaEventDisableTiming);
    cudaEventCreateWithFlags(&eQKV,  cudaEventDisableTiming);
    cudaEventCreateWithFlags(&eWo,   cudaEventDisableTiming);
    cudaEventCreateWithFlags(&eW1,   cudaEventDisableTiming);
    cudaEventCreateWithFlags(&eW2,   cudaEventDisableTiming);
    cudaEventCreateWithFlags(&eEmb,  cudaEventDisableTiming);

    cudaEventRecord(eFork, 0);
    cudaStreamWaitEvent(side, eFork, 0);

    // side stream: converters ordered by first-use time on the main stream
    transph_kernel<<<dim3(32, 32, NL), 256, 0, side>>>(
        Wq, wqh, DD, DD, (long long)DD * DD, (long long)DD * DD);
    transph_kernel<<<dim3(32, 32, NL), 256, 0, side>>>(
        Wk, wkh, DD, DD, (long long)DD * DD, (long long)DD * DD);
    transph_kernel<<<dim3(32, 32, NL), 256, 0, side>>>(
        Wv, wvh, DD, DD, (long long)DD * DD, (long long)DD * DD);
    cudaEventRecord(eQKV, side);
    transph_kernel<<<dim3(32, 32, NL), 256, 0, side>>>(
        Wo, woh, DD, DD, (long long)DD * DD, (long long)DD * DD);
    cudaEventRecord(eWo, side);
    transph_kernel<<<dim3(DMLP / 32, 32, NL), 256, 0, side>>>(
        W1, w1h, DD, DMLP, (long long)DD * DMLP, (long long)DD * DMLP);
    cudaEventRecord(eW1, side);
    transph_kernel<<<dim3(32, DMLP / 32, NL), 256, 0, side>>>(
        W2, w2h, DMLP, DD, (long long)DMLP * DD, (long long)DMLP * DD);
    cudaEventRecord(eW2, side);
    convh_kernel<<<4096, 256, 0, side>>>((const float4*)emb, (uint2*)embh,
                                         (long long)NV * DD / 4);
    cudaEventRecord(eEmb, side);

    // main stream
    embed_kernel<<<SS, 256>>>(ids, emb, x);

    for (int l = 0; l < NL; l++) {
        const size_t wofs = (size_t)l * DD * DD;
        layernorm_kernel<<<SS, 256>>>(x, ln1g + l * DD, ln1b + l * DD, h);

        if (l == 0) cudaStreamWaitEvent(0, eQKV, 0);
        {
            HPtr3 p;
            p.b0 = wqh + wofs; p.b1 = wkh + wofs; p.b2 = wvh + wofs;
            p.c0 = q; p.c1 = k; p.c2 = v;
            hgemm_kernel<128><<<dim3(SS / 128, DD / 128, 3), 256, SM128>>>(
                h, DD, 0, p, DD, DD, 0,
                SS, DD, DD, 1.f, nullptr, nullptr, 0, 1, 2);
        }

        rope_kernel<<<(SS * NH * 32 + 255) / 256, 256>>>(q, k);

        flash_kernel<<<dim3(SS / 128, NH), 256, FA_SMEM>>>(q, k, v, h);

        if (l == 0) cudaStreamWaitEvent(0, eWo, 0);
        hgemm_kernel<64><<<dim3(SS / 128, DD / 64, 1), 256, SM64>>>(
            h, DD, 0, oneh(woh + wofs, x), DD, DD, 0,
            SS, DD, DD, 1.f, nullptr, x, 0, 0, 0);

        layernorm_kernel<<<SS, 256>>>(x, ln2g + l * DD, ln2b + l * DD, h);

        if (l == 0) cudaStreamWaitEvent(0, eW1, 0);
        hgemm_kernel<128><<<dim3(SS / 128, DMLP / 128, 1), 256, SM128>>>(
            h, DD, 0, oneh(w1h + (size_t)l * DD * DMLP, mlp), DD, DMLP, 0,
            SS, DMLP, DD, 1.f, b1 + (size_t)l * DMLP, nullptr, 1, 0, 2);

        if (l == 0) cudaStreamWaitEvent(0, eW2, 0);
        hgemm_kernel<64><<<dim3(SS / 128, DD / 64, 1), 256, SM64>>>(
            mlp, DMLP, 0, oneh(w2h + (size_t)l * DD * DMLP, x), DMLP, DD, 0,
            SS, DD, DMLP, 1.f, b2 + (size_t)l * DD, x, 0, 0, 0);
    }

    layernorm_kernel<<<SS, 256>>>(x, lnfg, lnfb, h);

    cudaStreamWaitEvent(0, eEmb, 0);
    hgemm_kernel<128><<<dim3(SS / 128, (NV + 127) / 128, 1), 256, SM128>>>(
        h, DD, 0, oneh(embh, out), DD, NV, 0,
        SS, NV, DD, 1.f, nullptr, nullptr, 0, 0, 0);
}